// round 3
// baseline (speedup 1.0000x reference)
#include <cuda_runtime.h>
#include <math.h>

#define TT 256
#define BB 16
#define DD 512
#define NN 4096
#define HRR 256
#define BN_EPS 1e-5f

// ---------------- device scratch ----------------
__device__ float g_gi_r [NN * 768];
__device__ float g_gi_e1[NN * 384];
__device__ float g_gi_e2[NN * 768];
__device__ float g_gi_e3[NN * 1536];
__device__ float g_Hr[NN * HRR];
__device__ float g_H1[NN * 128];
__device__ float g_H2[NN * 256];
__device__ float g_H3[NN * 512];
__device__ unsigned g_flag1[NN];
__device__ unsigned g_flag2[NN];
__device__ unsigned g_flag3[NN];
__device__ float g_gates[NN * 4];
__device__ float g_bnA[3][512];
__device__ float g_bnB[3][512];
__device__ float g_tsum[4];
__device__ unsigned g_tcnt[4];

__device__ __forceinline__ float sigf(float x) { return 1.f / (1.f + __expf(-x)); }

// ---------------- zero flags / accumulators ----------------
__global__ void k_zero() {
    int i = blockIdx.x * 256 + threadIdx.x;
    if (i < NN) { g_flag1[i] = 0u; g_flag2[i] = 0u; g_flag3[i] = 0u; }
    if (i < 4) { g_tsum[i] = 0.f; g_tcnt[i] = 0u; }
}

// ---------------- gi GEMM: C[4096 x Nn] = A[4096 x 512] @ W[Nn x 512]^T + bias ----------------
__global__ __launch_bounds__(256) void k_gemm_bias(
    const float* __restrict__ A, const float* __restrict__ W,
    const float* __restrict__ bias, int which, int Nn)
{
    float* C = (which == 0) ? g_gi_r : (which == 1) ? g_gi_e1 : (which == 2) ? g_gi_e2 : g_gi_e3;
    __shared__ float As[64][17];
    __shared__ float Ws[64][17];
    const int tid = threadIdx.x;
    const int tx = tid & 15, ty = tid >> 4;
    const int m0 = blockIdx.y * 64, n0 = blockIdx.x * 64;
    const int lr = tid >> 2, lc = (tid & 3) * 4;

    float acc[4][4];
#pragma unroll
    for (int i = 0; i < 4; i++)
#pragma unroll
        for (int j = 0; j < 4; j++) acc[i][j] = 0.f;

    for (int kb = 0; kb < 512; kb += 16) {
        float4 av = *reinterpret_cast<const float4*>(&A[(size_t)(m0 + lr) * 512 + kb + lc]);
        float4 wv = *reinterpret_cast<const float4*>(&W[(size_t)(n0 + lr) * 512 + kb + lc]);
        As[lr][lc + 0] = av.x; As[lr][lc + 1] = av.y; As[lr][lc + 2] = av.z; As[lr][lc + 3] = av.w;
        Ws[lr][lc + 0] = wv.x; Ws[lr][lc + 1] = wv.y; Ws[lr][lc + 2] = wv.z; Ws[lr][lc + 3] = wv.w;
        __syncthreads();
#pragma unroll
        for (int k = 0; k < 16; k++) {
            float a[4], b[4];
#pragma unroll
            for (int i = 0; i < 4; i++) a[i] = As[ty * 4 + i][k];
#pragma unroll
            for (int j = 0; j < 4; j++) b[j] = Ws[tx * 4 + j][k];
#pragma unroll
            for (int i = 0; i < 4; i++)
#pragma unroll
                for (int j = 0; j < 4; j++) acc[i][j] += a[i] * b[j];
        }
        __syncthreads();
    }
#pragma unroll
    for (int i = 0; i < 4; i++)
#pragma unroll
        for (int j = 0; j < 4; j++)
            C[(size_t)(m0 + ty * 4 + i) * Nn + n0 + tx * 4 + j] =
                acc[i][j] + __ldg(&bias[n0 + tx * 4 + j]);
}

// ---------------- expert recurrence: NC CTAs cooperate, weights in registers ----------------
template <int H, int NC>
__device__ void expert_recur(int cta,
                             const float* __restrict__ Whh, const float* __restrict__ bhh,
                             const float* __restrict__ gi, float* __restrict__ Hbuf,
                             unsigned* __restrict__ flag, float* hs0, float* hs1)
{
    constexpr int JPC = H / NC;    // outputs (j) per CTA
    constexpr int JW  = JPC / 16;  // j per warp (16 warps)
    constexpr int KL  = H / 32;    // k elems per lane
    const int tid = threadIdx.x, w = tid >> 5, lane = tid & 31;
    const int jbase = cta * JPC + w * JW;
    const int own_lo = cta * JPC, own_hi = own_lo + JPC;

    float wreg[3][JW][KL];
    float bh[3][JW];
#pragma unroll
    for (int g = 0; g < 3; g++)
#pragma unroll
        for (int jj = 0; jj < JW; jj++) {
            int row = g * H + jbase + jj;
            bh[g][jj] = bhh[row];
#pragma unroll
            for (int kk = 0; kk < KL; kk++)
                wreg[g][jj][kk] = Whh[(size_t)row * H + kk * 32 + lane];
        }

    if (tid < H) { hs0[tid] = 0.f; hs1[tid] = 0.f; }
    __syncthreads();

    float* cur = hs0;
    float* nxt = hs1;
    volatile unsigned* vflag = (volatile unsigned*)flag;

    for (int t = 0; t < NN; t++) {
        const float* git = gi + (size_t)t * 3 * H;
        float gr[3][JW];
        if (lane == 0) {
#pragma unroll
            for (int g = 0; g < 3; g++)
#pragma unroll
                for (int jj = 0; jj < JW; jj++) gr[g][jj] = __ldg(&git[g * H + jbase + jj]);
        }

        float acc[3][JW];
#pragma unroll
        for (int g = 0; g < 3; g++)
#pragma unroll
            for (int jj = 0; jj < JW; jj++) acc[g][jj] = 0.f;

#pragma unroll
        for (int kk = 0; kk < KL; kk++) {
            float hv = cur[kk * 32 + lane];
#pragma unroll
            for (int g = 0; g < 3; g++)
#pragma unroll
                for (int jj = 0; jj < JW; jj++) acc[g][jj] += wreg[g][jj][kk] * hv;
        }
#pragma unroll
        for (int g = 0; g < 3; g++)
#pragma unroll
            for (int jj = 0; jj < JW; jj++)
#pragma unroll
                for (int off = 16; off > 0; off >>= 1)
                    acc[g][jj] += __shfl_xor_sync(0xffffffffu, acc[g][jj], off);

        if (lane == 0) {
#pragma unroll
            for (int jj = 0; jj < JW; jj++) {
                int j = jbase + jj;
                float r = sigf(gr[0][jj] + acc[0][jj] + bh[0][jj]);
                float z = sigf(gr[1][jj] + acc[1][jj] + bh[1][jj]);
                float n = tanhf(gr[2][jj] + r * (acc[2][jj] + bh[2][jj]));
                float hn = (1.f - z) * n + z * cur[j];
                nxt[j] = hn;
                Hbuf[(size_t)t * H + j] = hn;
            }
        }
        __syncthreads();                       // own slice written (smem + gmem)
        if (tid == 0) {
            __threadfence();
            atomicAdd(&flag[t], 1u);
        }
        while (vflag[t] < (unsigned)NC) {}     // all warps spin (broadcast load)
        __threadfence();
        if (tid < H && (tid < own_lo || tid >= own_hi))
            nxt[tid] = __ldcg(&Hbuf[(size_t)t * H + tid]);
        __syncthreads();
        float* tmp = cur; cur = nxt; nxt = tmp;
    }
}

// ---------------- router recurrence: one CTA per batch item, L2-streamed weights ----------------
__device__ void router_recur(int b, const float* __restrict__ Whh, const float* __restrict__ bhh,
                             float* cur, float* nxt)
{
    const int tid = threadIdx.x, w = tid >> 5, lane = tid & 31;
    const int j0 = w * 16;
    if (tid < HRR) { cur[tid] = 0.f; }
    __syncthreads();

    for (int t = 0; t < TT; t++) {
        const int n = t * BB + b;
        const float* git = g_gi_r + (size_t)n * 768;
        float4 h1 = *reinterpret_cast<const float4*>(cur + lane * 4);
        float4 h2 = *reinterpret_cast<const float4*>(cur + 128 + lane * 4);
#pragma unroll 2
        for (int jj = 0; jj < 16; jj++) {
            int j = j0 + jj;
            const float4* r0 = reinterpret_cast<const float4*>(Whh + (size_t)j * HRR);
            const float4* r1 = reinterpret_cast<const float4*>(Whh + (size_t)(j + 256) * HRR);
            const float4* r2 = reinterpret_cast<const float4*>(Whh + (size_t)(j + 512) * HRR);
            float4 a = __ldg(r0 + lane), c = __ldg(r0 + 32 + lane);
            float s0 = a.x * h1.x + a.y * h1.y + a.z * h1.z + a.w * h1.w
                     + c.x * h2.x + c.y * h2.y + c.z * h2.z + c.w * h2.w;
            a = __ldg(r1 + lane); c = __ldg(r1 + 32 + lane);
            float s1 = a.x * h1.x + a.y * h1.y + a.z * h1.z + a.w * h1.w
                     + c.x * h2.x + c.y * h2.y + c.z * h2.z + c.w * h2.w;
            a = __ldg(r2 + lane); c = __ldg(r2 + 32 + lane);
            float s2 = a.x * h1.x + a.y * h1.y + a.z * h1.z + a.w * h1.w
                     + c.x * h2.x + c.y * h2.y + c.z * h2.z + c.w * h2.w;
#pragma unroll
            for (int off = 16; off > 0; off >>= 1) {
                s0 += __shfl_xor_sync(0xffffffffu, s0, off);
                s1 += __shfl_xor_sync(0xffffffffu, s1, off);
                s2 += __shfl_xor_sync(0xffffffffu, s2, off);
            }
            if (lane == 0) {
                float r = sigf(__ldg(&git[j]) + s0 + __ldg(&bhh[j]));
                float z = sigf(__ldg(&git[256 + j]) + s1 + __ldg(&bhh[256 + j]));
                float nn2 = tanhf(__ldg(&git[512 + j]) + r * (s2 + __ldg(&bhh[512 + j])));
                float hn = (1.f - z) * nn2 + z * cur[j];
                nxt[j] = hn;
                g_Hr[(size_t)n * HRR + j] = hn;
            }
        }
        __syncthreads();
        float* tmp = cur; cur = nxt; nxt = tmp;
    }
}

// ---------------- fused recurrence kernel: 58 co-resident CTAs ----------------
__global__ __launch_bounds__(512) void k_recur(
    const float* r_whh, const float* r_bhh,
    const float* e1_whh, const float* e1_bhh,
    const float* e2_whh, const float* e2_bhh,
    const float* e3_whh, const float* e3_bhh)
{
    __shared__ float hsm[1152];
    int c = blockIdx.x;
    if (c < 32)      expert_recur<512, 32>(c,      e3_whh, e3_bhh, g_gi_e3, g_H3, g_flag3, hsm, hsm + 576);
    else if (c < 40) expert_recur<256, 8>(c - 32,  e2_whh, e2_bhh, g_gi_e2, g_H2, g_flag2, hsm, hsm + 576);
    else if (c < 42) expert_recur<128, 2>(c - 40,  e1_whh, e1_bhh, g_gi_e1, g_H1, g_flag1, hsm, hsm + 576);
    else             router_recur(c - 42, r_whh, r_bhh, hsm, hsm + 576);
}

// ---------------- gates: logits -> softmax -> raw, eul, task sums ----------------
__global__ void k_gates(const float* __restrict__ rw, const float* __restrict__ rb,
                        const int* __restrict__ task, float* __restrict__ out_raw)
{
    int warp = (blockIdx.x * blockDim.x + threadIdx.x) >> 5;
    int lane = threadIdx.x & 31;
    if (warp >= NN) return;
    const float* h = g_Hr + (size_t)warp * HRR;
    float hr[8];
#pragma unroll
    for (int i = 0; i < 8; i++) hr[i] = fmaxf(h[i * 32 + lane], 0.f);
    float lg[4];
#pragma unroll
    for (int e = 0; e < 4; e++) {
        float s = 0.f;
#pragma unroll
        for (int i = 0; i < 8; i++) s += __ldg(&rw[e * HRR + i * 32 + lane]) * hr[i];
#pragma unroll
        for (int off = 16; off > 0; off >>= 1) s += __shfl_xor_sync(0xffffffffu, s, off);
        lg[e] = s;
    }
    if (lane == 0) {
#pragma unroll
        for (int e = 0; e < 4; e++) lg[e] += __ldg(&rb[e]);
        float mx = fmaxf(fmaxf(lg[0], lg[1]), fmaxf(lg[2], lg[3]));
        float ex[4], se = 0.f;
#pragma unroll
        for (int e = 0; e < 4; e++) { ex[e] = __expf(lg[e] - mx); se += ex[e]; }
        float inv = 1.f / se;
        float gg[4];
#pragma unroll
        for (int e = 0; e < 4; e++) {
            gg[e] = ex[e] * inv;
            out_raw[warp * 4 + e] = gg[e];
            g_gates[warp * 4 + e] = gg[e];
        }
        float eul = gg[1] * 128.f + gg[2] * 256.f + gg[3] * 512.f;
        int tk = task[warp];
        atomicAdd(&g_tsum[tk], eul);
        atomicAdd(&g_tcnt[tk], 1u);
    }
}

// ---------------- BN stats: per-column mean/var -> affine A,B ----------------
__global__ void k_bn(const float* g1, const float* b1, const float* g2, const float* b2,
                     const float* g3, const float* b3)
{
    int bid = blockIdx.x, tid = threadIdx.x;
    const float* Hb; int H, ei, c;
    if (bid == 0)      { Hb = g_H1; H = 128; ei = 0; c = tid; }
    else if (bid < 3)  { Hb = g_H2; H = 256; ei = 1; c = (bid - 1) * 128 + tid; }
    else               { Hb = g_H3; H = 512; ei = 2; c = (bid - 3) * 128 + tid; }
    float s = 0.f, s2 = 0.f;
#pragma unroll 8
    for (int n = 0; n < NN; n++) {
        float v = __ldg(&Hb[(size_t)n * H + c]);
        s += v; s2 += v * v;
    }
    float mu = s * (1.f / NN);
    float var = s2 * (1.f / NN) - mu * mu;
    const float* gg = (ei == 0) ? g1 : (ei == 1) ? g2 : g3;
    const float* bb = (ei == 0) ? b1 : (ei == 1) ? b2 : b3;
    float A = gg[c] * rsqrtf(var + BN_EPS);
    g_bnA[ei][c] = A;
    g_bnB[ei][c] = bb[c] - mu * A;
}

// ---------------- epilogue: out (+)= gate_i * (relu(bn(H_i)) @ ow^T + ob) ----------------
__global__ __launch_bounds__(256) void k_epi(
    const float* __restrict__ ow, const float* __restrict__ ob,
    const float* __restrict__ x, float* __restrict__ out, int ei, int H)
{
    const float* Hb = (ei == 1) ? g_H1 : (ei == 2) ? g_H2 : g_H3;
    const float* bA = g_bnA[ei - 1];
    const float* bBv = g_bnB[ei - 1];
    __shared__ float As[64][17];
    __shared__ float Ws[64][17];
    const int tid = threadIdx.x;
    const int tx = tid & 15, ty = tid >> 4;
    const int m0 = blockIdx.y * 64, n0 = blockIdx.x * 64;
    const int lr = tid >> 2, lc = (tid & 3) * 4;

    float acc[4][4];
#pragma unroll
    for (int i = 0; i < 4; i++)
#pragma unroll
        for (int j = 0; j < 4; j++) acc[i][j] = 0.f;

    for (int kb = 0; kb < H; kb += 16) {
        float4 av = *reinterpret_cast<const float4*>(&Hb[(size_t)(m0 + lr) * H + kb + lc]);
        float4 wv = *reinterpret_cast<const float4*>(&ow[(size_t)(n0 + lr) * H + kb + lc]);
        As[lr][lc + 0] = fmaxf(av.x * __ldg(&bA[kb + lc + 0]) + __ldg(&bBv[kb + lc + 0]), 0.f);
        As[lr][lc + 1] = fmaxf(av.y * __ldg(&bA[kb + lc + 1]) + __ldg(&bBv[kb + lc + 1]), 0.f);
        As[lr][lc + 2] = fmaxf(av.z * __ldg(&bA[kb + lc + 2]) + __ldg(&bBv[kb + lc + 2]), 0.f);
        As[lr][lc + 3] = fmaxf(av.w * __ldg(&bA[kb + lc + 3]) + __ldg(&bBv[kb + lc + 3]), 0.f);
        Ws[lr][lc + 0] = wv.x; Ws[lr][lc + 1] = wv.y; Ws[lr][lc + 2] = wv.z; Ws[lr][lc + 3] = wv.w;
        __syncthreads();
#pragma unroll
        for (int k = 0; k < 16; k++) {
            float a[4], b[4];
#pragma unroll
            for (int i = 0; i < 4; i++) a[i] = As[ty * 4 + i][k];
#pragma unroll
            for (int j = 0; j < 4; j++) b[j] = Ws[tx * 4 + j][k];
#pragma unroll
            for (int i = 0; i < 4; i++)
#pragma unroll
                for (int j = 0; j < 4; j++) acc[i][j] += a[i] * b[j];
        }
        __syncthreads();
    }
#pragma unroll
    for (int i = 0; i < 4; i++) {
        int m = m0 + ty * 4 + i;
        float gate = g_gates[m * 4 + ei];
        float g0 = g_gates[m * 4];
#pragma unroll
        for (int j = 0; j < 4; j++) {
            int n = n0 + tx * 4 + j;
            float v = (acc[i][j] + __ldg(&ob[n])) * gate;
            if (ei == 1) v += g0 * __ldg(&x[(size_t)m * DD + n]);
            else         v += out[(size_t)m * DD + n];
            out[(size_t)m * DD + n] = v;
        }
    }
}

// ---------------- task losses ----------------
__global__ void k_tl(float* o) {
    int i = threadIdx.x;
    if (i < 4) o[i] = g_tsum[i] / (float)g_tcnt[i];
}

// ---------------- launch ----------------
extern "C" void kernel_launch(void* const* d_in, const int* in_sizes, int n_in,
                              void* d_out, int out_size)
{
    const float* x      = (const float*)d_in[0];
    const int*   task   = (const int*)d_in[1];
    const float* r_wih  = (const float*)d_in[2];
    const float* r_whh  = (const float*)d_in[3];
    const float* r_bih  = (const float*)d_in[4];
    const float* r_bhh  = (const float*)d_in[5];
    const float* r_ow   = (const float*)d_in[6];
    const float* r_ob   = (const float*)d_in[7];
    const float* e1_wih = (const float*)d_in[8];
    const float* e1_whh = (const float*)d_in[9];
    const float* e1_bih = (const float*)d_in[10];
    const float* e1_bhh = (const float*)d_in[11];
    const float* e1_bng = (const float*)d_in[12];
    const float* e1_bnb = (const float*)d_in[13];
    const float* e1_ow  = (const float*)d_in[14];
    const float* e1_ob  = (const float*)d_in[15];
    const float* e2_wih = (const float*)d_in[16];
    const float* e2_whh = (const float*)d_in[17];
    const float* e2_bih = (const float*)d_in[18];
    const float* e2_bhh = (const float*)d_in[19];
    const float* e2_bng = (const float*)d_in[20];
    const float* e2_bnb = (const float*)d_in[21];
    const float* e2_ow  = (const float*)d_in[22];
    const float* e2_ob  = (const float*)d_in[23];
    const float* e3_wih = (const float*)d_in[24];
    const float* e3_whh = (const float*)d_in[25];
    const float* e3_bih = (const float*)d_in[26];
    const float* e3_bhh = (const float*)d_in[27];
    const float* e3_bng = (const float*)d_in[28];
    const float* e3_bnb = (const float*)d_in[29];
    const float* e3_ow  = (const float*)d_in[30];
    const float* e3_ob  = (const float*)d_in[31];

    float* out = (float*)d_out;
    float* raw = out + (size_t)NN * DD;
    float* tl  = raw + (size_t)NN * 4;

    k_zero<<<16, 256>>>();
    k_gemm_bias<<<dim3(12, 64), 256>>>(x, r_wih,  r_bih,  0, 768);
    k_gemm_bias<<<dim3(6, 64),  256>>>(x, e1_wih, e1_bih, 1, 384);
    k_gemm_bias<<<dim3(12, 64), 256>>>(x, e2_wih, e2_bih, 2, 768);
    k_gemm_bias<<<dim3(24, 64), 256>>>(x, e3_wih, e3_bih, 3, 1536);
    k_recur<<<58, 512>>>(r_whh, r_bhh, e1_whh, e1_bhh, e2_whh, e2_bhh, e3_whh, e3_bhh);
    k_gates<<<512, 256>>>(r_ow, r_ob, task, raw);
    k_bn<<<7, 128>>>(e1_bng, e1_bnb, e2_bng, e2_bnb, e3_bng, e3_bnb);
    k_epi<<<dim3(8, 64), 256>>>(e1_ow, e1_ob, x, out, 1, 128);
    k_epi<<<dim3(8, 64), 256>>>(e2_ow, e2_ob, x, out, 2, 256);
    k_epi<<<dim3(8, 64), 256>>>(e3_ow, e3_ob, x, out, 3, 512);
    k_tl<<<1, 32>>>(tl);
}

// round 4
// speedup vs baseline: 1.0637x; 1.0637x over previous
#include <cuda_runtime.h>
#include <math.h>

#define TT 256
#define BB 16
#define DD 512
#define NN 4096
#define HRR 256
#define BN_EPS 1e-5f

// ---------------- device scratch ----------------
__device__ float g_gi_r [NN * 768];
__device__ float g_gi_e1[NN * 384];
__device__ float g_gi_e2[NN * 768];
__device__ float g_gi_e3[NN * 1536];
__device__ float g_Hr[NN * HRR];
__device__ float g_H1[NN * 128];
__device__ float g_H2[NN * 256];
__device__ float g_H3[NN * 512];
__device__ unsigned g_flag1[NN];
__device__ unsigned g_flag2[NN];
__device__ unsigned g_flag3[NN];
__device__ float g_gates[NN * 4];
__device__ float g_bnA[3][512];
__device__ float g_bnB[3][512];
__device__ float g_tsum[4];
__device__ unsigned g_tcnt[4];

__device__ __forceinline__ float sigf(float x) { return 1.f / (1.f + __expf(-x)); }

// release/acquire barrier primitives (no full membar on the critical path)
__device__ __forceinline__ void red_release_add(unsigned* p) {
    asm volatile("red.release.gpu.global.add.u32 [%0], 1;" :: "l"(p) : "memory");
}
__device__ __forceinline__ unsigned ld_acquire(const unsigned* p) {
    unsigned v;
    asm volatile("ld.acquire.gpu.global.u32 %0, [%1];" : "=r"(v) : "l"(p) : "memory");
    return v;
}

// ---------------- zero flags / accumulators ----------------
__global__ void k_zero() {
    int i = blockIdx.x * 256 + threadIdx.x;
    if (i < NN) { g_flag1[i] = 0u; g_flag2[i] = 0u; g_flag3[i] = 0u; }
    if (i < 4) { g_tsum[i] = 0.f; g_tcnt[i] = 0u; }
}

// ---------------- gi GEMM: C[4096 x Nn] = A[4096 x 512] @ W[Nn x 512]^T + bias ----------------
__global__ __launch_bounds__(256) void k_gemm_bias(
    const float* __restrict__ A, const float* __restrict__ W,
    const float* __restrict__ bias, int which, int Nn)
{
    float* C = (which == 0) ? g_gi_r : (which == 1) ? g_gi_e1 : (which == 2) ? g_gi_e2 : g_gi_e3;
    __shared__ float As[64][17];
    __shared__ float Ws[64][17];
    const int tid = threadIdx.x;
    const int tx = tid & 15, ty = tid >> 4;
    const int m0 = blockIdx.y * 64, n0 = blockIdx.x * 64;
    const int lr = tid >> 2, lc = (tid & 3) * 4;

    float acc[4][4];
#pragma unroll
    for (int i = 0; i < 4; i++)
#pragma unroll
        for (int j = 0; j < 4; j++) acc[i][j] = 0.f;

    for (int kb = 0; kb < 512; kb += 16) {
        float4 av = *reinterpret_cast<const float4*>(&A[(size_t)(m0 + lr) * 512 + kb + lc]);
        float4 wv = *reinterpret_cast<const float4*>(&W[(size_t)(n0 + lr) * 512 + kb + lc]);
        As[lr][lc + 0] = av.x; As[lr][lc + 1] = av.y; As[lr][lc + 2] = av.z; As[lr][lc + 3] = av.w;
        Ws[lr][lc + 0] = wv.x; Ws[lr][lc + 1] = wv.y; Ws[lr][lc + 2] = wv.z; Ws[lr][lc + 3] = wv.w;
        __syncthreads();
#pragma unroll
        for (int k = 0; k < 16; k++) {
            float a[4], b[4];
#pragma unroll
            for (int i = 0; i < 4; i++) a[i] = As[ty * 4 + i][k];
#pragma unroll
            for (int j = 0; j < 4; j++) b[j] = Ws[tx * 4 + j][k];
#pragma unroll
            for (int i = 0; i < 4; i++)
#pragma unroll
                for (int j = 0; j < 4; j++) acc[i][j] += a[i] * b[j];
        }
        __syncthreads();
    }
#pragma unroll
    for (int i = 0; i < 4; i++)
#pragma unroll
        for (int j = 0; j < 4; j++)
            C[(size_t)(m0 + ty * 4 + i) * Nn + n0 + tx * 4 + j] =
                acc[i][j] + __ldg(&bias[n0 + tx * 4 + j]);
}

// ---------------- expert recurrence: NC CTAs cooperate, weights in registers ----------------
template <int H, int NC>
__device__ void expert_recur(int cta,
                             const float* __restrict__ Whh, const float* __restrict__ bhh,
                             const float* __restrict__ gi, float* __restrict__ Hbuf,
                             unsigned* __restrict__ flag, float* hs0, float* hs1)
{
    constexpr int JPC = H / NC;    // outputs (j) per CTA
    constexpr int JW  = JPC / 16;  // j per warp (16 warps)
    constexpr int KL  = H / 32;    // k elems per lane
    const int tid = threadIdx.x, w = tid >> 5, lane = tid & 31;
    const int jbase = cta * JPC + w * JW;
    const int own_lo = cta * JPC, own_hi = own_lo + JPC;

    float wreg[3][JW][KL];
    float bh[3][JW];
#pragma unroll
    for (int g = 0; g < 3; g++)
#pragma unroll
        for (int jj = 0; jj < JW; jj++) {
            int row = g * H + jbase + jj;
            bh[g][jj] = bhh[row];
#pragma unroll
            for (int kk = 0; kk < KL; kk++)
                wreg[g][jj][kk] = Whh[(size_t)row * H + kk * 32 + lane];
        }

    if (tid < H) { hs0[tid] = 0.f; hs1[tid] = 0.f; }
    __syncthreads();

    float* cur = hs0;
    float* nxt = hs1;

    for (int t = 0; t < NN; t++) {
        const float* git = gi + (size_t)t * 3 * H;
        float gr[3][JW];
        if (lane == 0) {
#pragma unroll
            for (int g = 0; g < 3; g++)
#pragma unroll
                for (int jj = 0; jj < JW; jj++) gr[g][jj] = __ldg(&git[g * H + jbase + jj]);
        }

        float acc[3][JW];
#pragma unroll
        for (int g = 0; g < 3; g++)
#pragma unroll
            for (int jj = 0; jj < JW; jj++) acc[g][jj] = 0.f;

#pragma unroll
        for (int kk = 0; kk < KL; kk++) {
            float hv = cur[kk * 32 + lane];
#pragma unroll
            for (int g = 0; g < 3; g++)
#pragma unroll
                for (int jj = 0; jj < JW; jj++) acc[g][jj] += wreg[g][jj][kk] * hv;
        }
#pragma unroll
        for (int g = 0; g < 3; g++)
#pragma unroll
            for (int jj = 0; jj < JW; jj++)
#pragma unroll
                for (int off = 16; off > 0; off >>= 1)
                    acc[g][jj] += __shfl_xor_sync(0xffffffffu, acc[g][jj], off);

        if (lane == 0) {
#pragma unroll
            for (int jj = 0; jj < JW; jj++) {
                int j = jbase + jj;
                float r = sigf(gr[0][jj] + acc[0][jj] + bh[0][jj]);
                float z = sigf(gr[1][jj] + acc[1][jj] + bh[1][jj]);
                float n = tanhf(gr[2][jj] + r * (acc[2][jj] + bh[2][jj]));
                float hn = (1.f - z) * n + z * cur[j];
                nxt[j] = hn;
                Hbuf[(size_t)t * H + j] = hn;
            }
        }
        // ---- release/acquire inter-CTA barrier (no full membar) ----
        __syncthreads();                         // CTA-scope: all lane0 STG ordered
        if (tid == 0) red_release_add(&flag[t]); // cumulative release arrive
        if (w == 0) {                            // only warp 0 polls
            while (ld_acquire(&flag[t]) < (unsigned)NC) {}
        }
        __syncthreads();                         // release CTA, acquire is cumulative
        if (tid < H && (tid < own_lo || tid >= own_hi))
            nxt[tid] = __ldcg(&Hbuf[(size_t)t * H + tid]);
        __syncthreads();
        float* tmp = cur; cur = nxt; nxt = tmp;
    }
}

// ---------------- router recurrence: one CTA per batch item, L2-streamed weights ----------------
__device__ void router_recur(int b, const float* __restrict__ Whh, const float* __restrict__ bhh,
                             float* cur, float* nxt)
{
    const int tid = threadIdx.x, w = tid >> 5, lane = tid & 31;
    const int j0 = w * 16;
    if (tid < HRR) { cur[tid] = 0.f; }
    __syncthreads();

    for (int t = 0; t < TT; t++) {
        const int n = t * BB + b;
        const float* git = g_gi_r + (size_t)n * 768;
        float4 h1 = *reinterpret_cast<const float4*>(cur + lane * 4);
        float4 h2 = *reinterpret_cast<const float4*>(cur + 128 + lane * 4);
#pragma unroll 2
        for (int jj = 0; jj < 16; jj++) {
            int j = j0 + jj;
            const float4* r0 = reinterpret_cast<const float4*>(Whh + (size_t)j * HRR);
            const float4* r1 = reinterpret_cast<const float4*>(Whh + (size_t)(j + 256) * HRR);
            const float4* r2 = reinterpret_cast<const float4*>(Whh + (size_t)(j + 512) * HRR);
            float4 a = __ldg(r0 + lane), c = __ldg(r0 + 32 + lane);
            float s0 = a.x * h1.x + a.y * h1.y + a.z * h1.z + a.w * h1.w
                     + c.x * h2.x + c.y * h2.y + c.z * h2.z + c.w * h2.w;
            a = __ldg(r1 + lane); c = __ldg(r1 + 32 + lane);
            float s1 = a.x * h1.x + a.y * h1.y + a.z * h1.z + a.w * h1.w
                     + c.x * h2.x + c.y * h2.y + c.z * h2.z + c.w * h2.w;
            a = __ldg(r2 + lane); c = __ldg(r2 + 32 + lane);
            float s2 = a.x * h1.x + a.y * h1.y + a.z * h1.z + a.w * h1.w
                     + c.x * h2.x + c.y * h2.y + c.z * h2.z + c.w * h2.w;
#pragma unroll
            for (int off = 16; off > 0; off >>= 1) {
                s0 += __shfl_xor_sync(0xffffffffu, s0, off);
                s1 += __shfl_xor_sync(0xffffffffu, s1, off);
                s2 += __shfl_xor_sync(0xffffffffu, s2, off);
            }
            if (lane == 0) {
                float r = sigf(__ldg(&git[j]) + s0 + __ldg(&bhh[j]));
                float z = sigf(__ldg(&git[256 + j]) + s1 + __ldg(&bhh[256 + j]));
                float nn2 = tanhf(__ldg(&git[512 + j]) + r * (s2 + __ldg(&bhh[512 + j])));
                float hn = (1.f - z) * nn2 + z * cur[j];
                nxt[j] = hn;
                g_Hr[(size_t)n * HRR + j] = hn;
            }
        }
        __syncthreads();
        float* tmp = cur; cur = nxt; nxt = tmp;
    }
}

// ---------------- fused recurrence kernel: 58 co-resident CTAs ----------------
__global__ __launch_bounds__(512) void k_recur(
    const float* r_whh, const float* r_bhh,
    const float* e1_whh, const float* e1_bhh,
    const float* e2_whh, const float* e2_bhh,
    const float* e3_whh, const float* e3_bhh)
{
    __shared__ float hsm[1152];
    int c = blockIdx.x;
    if (c < 32)      expert_recur<512, 32>(c,      e3_whh, e3_bhh, g_gi_e3, g_H3, g_flag3, hsm, hsm + 576);
    else if (c < 40) expert_recur<256, 8>(c - 32,  e2_whh, e2_bhh, g_gi_e2, g_H2, g_flag2, hsm, hsm + 576);
    else if (c < 42) expert_recur<128, 2>(c - 40,  e1_whh, e1_bhh, g_gi_e1, g_H1, g_flag1, hsm, hsm + 576);
    else             router_recur(c - 42, r_whh, r_bhh, hsm, hsm + 576);
}

// ---------------- gates: logits -> softmax -> raw, eul, task sums ----------------
__global__ void k_gates(const float* __restrict__ rw, const float* __restrict__ rb,
                        const int* __restrict__ task, float* __restrict__ out_raw)
{
    int warp = (blockIdx.x * blockDim.x + threadIdx.x) >> 5;
    int lane = threadIdx.x & 31;
    if (warp >= NN) return;
    const float* h = g_Hr + (size_t)warp * HRR;
    float hr[8];
#pragma unroll
    for (int i = 0; i < 8; i++) hr[i] = fmaxf(h[i * 32 + lane], 0.f);
    float lg[4];
#pragma unroll
    for (int e = 0; e < 4; e++) {
        float s = 0.f;
#pragma unroll
        for (int i = 0; i < 8; i++) s += __ldg(&rw[e * HRR + i * 32 + lane]) * hr[i];
#pragma unroll
        for (int off = 16; off > 0; off >>= 1) s += __shfl_xor_sync(0xffffffffu, s, off);
        lg[e] = s;
    }
    if (lane == 0) {
#pragma unroll
        for (int e = 0; e < 4; e++) lg[e] += __ldg(&rb[e]);
        float mx = fmaxf(fmaxf(lg[0], lg[1]), fmaxf(lg[2], lg[3]));
        float ex[4], se = 0.f;
#pragma unroll
        for (int e = 0; e < 4; e++) { ex[e] = __expf(lg[e] - mx); se += ex[e]; }
        float inv = 1.f / se;
        float gg[4];
#pragma unroll
        for (int e = 0; e < 4; e++) {
            gg[e] = ex[e] * inv;
            out_raw[warp * 4 + e] = gg[e];
            g_gates[warp * 4 + e] = gg[e];
        }
        float eul = gg[1] * 128.f + gg[2] * 256.f + gg[3] * 512.f;
        int tk = task[warp];
        atomicAdd(&g_tsum[tk], eul);
        atomicAdd(&g_tcnt[tk], 1u);
    }
}

// ---------------- BN stats: per-column mean/var -> affine A,B ----------------
__global__ void k_bn(const float* g1, const float* b1, const float* g2, const float* b2,
                     const float* g3, const float* b3)
{
    int bid = blockIdx.x, tid = threadIdx.x;
    const float* Hb; int H, ei, c;
    if (bid == 0)      { Hb = g_H1; H = 128; ei = 0; c = tid; }
    else if (bid < 3)  { Hb = g_H2; H = 256; ei = 1; c = (bid - 1) * 128 + tid; }
    else               { Hb = g_H3; H = 512; ei = 2; c = (bid - 3) * 128 + tid; }
    float s = 0.f, s2 = 0.f;
#pragma unroll 8
    for (int n = 0; n < NN; n++) {
        float v = __ldg(&Hb[(size_t)n * H + c]);
        s += v; s2 += v * v;
    }
    float mu = s * (1.f / NN);
    float var = s2 * (1.f / NN) - mu * mu;
    const float* gg = (ei == 0) ? g1 : (ei == 1) ? g2 : g3;
    const float* bb = (ei == 0) ? b1 : (ei == 1) ? b2 : b3;
    float A = gg[c] * rsqrtf(var + BN_EPS);
    g_bnA[ei][c] = A;
    g_bnB[ei][c] = bb[c] - mu * A;
}

// ---------------- epilogue: out (+)= gate_i * (relu(bn(H_i)) @ ow^T + ob) ----------------
__global__ __launch_bounds__(256) void k_epi(
    const float* __restrict__ ow, const float* __restrict__ ob,
    const float* __restrict__ x, float* __restrict__ out, int ei, int H)
{
    const float* Hb = (ei == 1) ? g_H1 : (ei == 2) ? g_H2 : g_H3;
    const float* bA = g_bnA[ei - 1];
    const float* bBv = g_bnB[ei - 1];
    __shared__ float As[64][17];
    __shared__ float Ws[64][17];
    const int tid = threadIdx.x;
    const int tx = tid & 15, ty = tid >> 4;
    const int m0 = blockIdx.y * 64, n0 = blockIdx.x * 64;
    const int lr = tid >> 2, lc = (tid & 3) * 4;

    float acc[4][4];
#pragma unroll
    for (int i = 0; i < 4; i++)
#pragma unroll
        for (int j = 0; j < 4; j++) acc[i][j] = 0.f;

    for (int kb = 0; kb < H; kb += 16) {
        float4 av = *reinterpret_cast<const float4*>(&Hb[(size_t)(m0 + lr) * H + kb + lc]);
        float4 wv = *reinterpret_cast<const float4*>(&ow[(size_t)(n0 + lr) * H + kb + lc]);
        As[lr][lc + 0] = fmaxf(av.x * __ldg(&bA[kb + lc + 0]) + __ldg(&bBv[kb + lc + 0]), 0.f);
        As[lr][lc + 1] = fmaxf(av.y * __ldg(&bA[kb + lc + 1]) + __ldg(&bBv[kb + lc + 1]), 0.f);
        As[lr][lc + 2] = fmaxf(av.z * __ldg(&bA[kb + lc + 2]) + __ldg(&bBv[kb + lc + 2]), 0.f);
        As[lr][lc + 3] = fmaxf(av.w * __ldg(&bA[kb + lc + 3]) + __ldg(&bBv[kb + lc + 3]), 0.f);
        Ws[lr][lc + 0] = wv.x; Ws[lr][lc + 1] = wv.y; Ws[lr][lc + 2] = wv.z; Ws[lr][lc + 3] = wv.w;
        __syncthreads();
#pragma unroll
        for (int k = 0; k < 16; k++) {
            float a[4], b[4];
#pragma unroll
            for (int i = 0; i < 4; i++) a[i] = As[ty * 4 + i][k];
#pragma unroll
            for (int j = 0; j < 4; j++) b[j] = Ws[tx * 4 + j][k];
#pragma unroll
            for (int i = 0; i < 4; i++)
#pragma unroll
                for (int j = 0; j < 4; j++) acc[i][j] += a[i] * b[j];
        }
        __syncthreads();
    }
#pragma unroll
    for (int i = 0; i < 4; i++) {
        int m = m0 + ty * 4 + i;
        float gate = g_gates[m * 4 + ei];
        float g0 = g_gates[m * 4];
#pragma unroll
        for (int j = 0; j < 4; j++) {
            int n = n0 + tx * 4 + j;
            float v = (acc[i][j] + __ldg(&ob[n])) * gate;
            if (ei == 1) v += g0 * __ldg(&x[(size_t)m * DD + n]);
            else         v += out[(size_t)m * DD + n];
            out[(size_t)m * DD + n] = v;
        }
    }
}

// ---------------- task losses ----------------
__global__ void k_tl(float* o) {
    int i = threadIdx.x;
    if (i < 4) o[i] = g_tsum[i] / (float)g_tcnt[i];
}

// ---------------- launch ----------------
extern "C" void kernel_launch(void* const* d_in, const int* in_sizes, int n_in,
                              void* d_out, int out_size)
{
    const float* x      = (const float*)d_in[0];
    const int*   task   = (const int*)d_in[1];
    const float* r_wih  = (const float*)d_in[2];
    const float* r_whh  = (const float*)d_in[3];
    const float* r_bih  = (const float*)d_in[4];
    const float* r_bhh  = (const float*)d_in[5];
    const float* r_ow   = (const float*)d_in[6];
    const float* r_ob   = (const float*)d_in[7];
    const float* e1_wih = (const float*)d_in[8];
    const float* e1_whh = (const float*)d_in[9];
    const float* e1_bih = (const float*)d_in[10];
    const float* e1_bhh = (const float*)d_in[11];
    const float* e1_bng = (const float*)d_in[12];
    const float* e1_bnb = (const float*)d_in[13];
    const float* e1_ow  = (const float*)d_in[14];
    const float* e1_ob  = (const float*)d_in[15];
    const float* e2_wih = (const float*)d_in[16];
    const float* e2_whh = (const float*)d_in[17];
    const float* e2_bih = (const float*)d_in[18];
    const float* e2_bhh = (const float*)d_in[19];
    const float* e2_bng = (const float*)d_in[20];
    const float* e2_bnb = (const float*)d_in[21];
    const float* e2_ow  = (const float*)d_in[22];
    const float* e2_ob  = (const float*)d_in[23];
    const float* e3_wih = (const float*)d_in[24];
    const float* e3_whh = (const float*)d_in[25];
    const float* e3_bih = (const float*)d_in[26];
    const float* e3_bhh = (const float*)d_in[27];
    const float* e3_bng = (const float*)d_in[28];
    const float* e3_bnb = (const float*)d_in[29];
    const float* e3_ow  = (const float*)d_in[30];
    const float* e3_ob  = (const float*)d_in[31];

    float* out = (float*)d_out;
    float* raw = out + (size_t)NN * DD;
    float* tl  = raw + (size_t)NN * 4;

    k_zero<<<16, 256>>>();
    k_gemm_bias<<<dim3(12, 64), 256>>>(x, r_wih,  r_bih,  0, 768);
    k_gemm_bias<<<dim3(6, 64),  256>>>(x, e1_wih, e1_bih, 1, 384);
    k_gemm_bias<<<dim3(12, 64), 256>>>(x, e2_wih, e2_bih, 2, 768);
    k_gemm_bias<<<dim3(24, 64), 256>>>(x, e3_wih, e3_bih, 3, 1536);
    k_recur<<<58, 512>>>(r_whh, r_bhh, e1_whh, e1_bhh, e2_whh, e2_bhh, e3_whh, e3_bhh);
    k_gates<<<512, 256>>>(r_ow, r_ob, task, raw);
    k_bn<<<7, 128>>>(e1_bng, e1_bnb, e2_bng, e2_bnb, e3_bng, e3_bnb);
    k_epi<<<dim3(8, 64), 256>>>(e1_ow, e1_ob, x, out, 1, 128);
    k_epi<<<dim3(8, 64), 256>>>(e2_ow, e2_ob, x, out, 2, 256);
    k_epi<<<dim3(8, 64), 256>>>(e3_ow, e3_ob, x, out, 3, 512);
    k_tl<<<1, 32>>>(tl);
}

// round 6
// speedup vs baseline: 1.1620x; 1.0923x over previous
#include <cuda_runtime.h>
#include <math.h>

#define TT 256
#define BB 16
#define DD 512
#define NN 4096
#define HRR 256
#define BN_EPS 1e-5f

// ---------------- device scratch ----------------
__device__ float g_gi_r [NN * 768];
__device__ float g_gi_e1[NN * 384];
__device__ float g_gi_e2[NN * 768];
__device__ float g_gi_e3[NN * 1536];
__device__ float g_Hr[NN * HRR];
__device__ float g_H1[NN * 128];
__device__ float g_H2[NN * 256];
__device__ float g_H3[NN * 512];
// per-CTA arrival flags: one 128B line (32 words) per step
__device__ unsigned g_f1[NN * 32];
__device__ unsigned g_f2[NN * 32];
__device__ unsigned g_f3[NN * 32];
__device__ float g_gates[NN * 4];
__device__ float g_bnA[3][512];
__device__ float g_bnB[3][512];
__device__ float g_tsum[4];
__device__ unsigned g_tcnt[4];

__device__ __forceinline__ float sigf(float x) { return 1.f / (1.f + __expf(-x)); }

__device__ __forceinline__ void st_release(unsigned* p, unsigned v) {
    asm volatile("st.release.gpu.global.u32 [%0], %1;" :: "l"(p), "r"(v) : "memory");
}
__device__ __forceinline__ unsigned ld_acquire(const unsigned* p) {
    unsigned v;
    asm volatile("ld.acquire.gpu.global.u32 %0, [%1];" : "=r"(v) : "l"(p) : "memory");
    return v;
}

// ---------------- zero flags / accumulators ----------------
__global__ void k_zero() {
    int i = blockIdx.x * 256 + threadIdx.x;
    if (i < NN * 32) { g_f1[i] = 0u; g_f2[i] = 0u; g_f3[i] = 0u; }
    if (i < 4) { g_tsum[i] = 0.f; g_tcnt[i] = 0u; }
}

// ---------------- gi GEMM: C[4096 x Nn] = A[4096 x 512] @ W[Nn x 512]^T + bias ----------------
__global__ __launch_bounds__(256) void k_gemm_bias(
    const float* __restrict__ A, const float* __restrict__ W,
    const float* __restrict__ bias, int which, int Nn)
{
    float* C = (which == 0) ? g_gi_r : (which == 1) ? g_gi_e1 : (which == 2) ? g_gi_e2 : g_gi_e3;
    __shared__ float As[64][17];
    __shared__ float Ws[64][17];
    const int tid = threadIdx.x;
    const int tx = tid & 15, ty = tid >> 4;
    const int m0 = blockIdx.y * 64, n0 = blockIdx.x * 64;
    const int lr = tid >> 2, lc = (tid & 3) * 4;

    float acc[4][4];
#pragma unroll
    for (int i = 0; i < 4; i++)
#pragma unroll
        for (int j = 0; j < 4; j++) acc[i][j] = 0.f;

    for (int kb = 0; kb < 512; kb += 16) {
        float4 av = *reinterpret_cast<const float4*>(&A[(size_t)(m0 + lr) * 512 + kb + lc]);
        float4 wv = *reinterpret_cast<const float4*>(&W[(size_t)(n0 + lr) * 512 + kb + lc]);
        As[lr][lc + 0] = av.x; As[lr][lc + 1] = av.y; As[lr][lc + 2] = av.z; As[lr][lc + 3] = av.w;
        Ws[lr][lc + 0] = wv.x; Ws[lr][lc + 1] = wv.y; Ws[lr][lc + 2] = wv.z; Ws[lr][lc + 3] = wv.w;
        __syncthreads();
#pragma unroll
        for (int k = 0; k < 16; k++) {
            float a[4], b[4];
#pragma unroll
            for (int i = 0; i < 4; i++) a[i] = As[ty * 4 + i][k];
#pragma unroll
            for (int j = 0; j < 4; j++) b[j] = Ws[tx * 4 + j][k];
#pragma unroll
            for (int i = 0; i < 4; i++)
#pragma unroll
                for (int j = 0; j < 4; j++) acc[i][j] += a[i] * b[j];
        }
        __syncthreads();
    }
#pragma unroll
    for (int i = 0; i < 4; i++)
#pragma unroll
        for (int j = 0; j < 4; j++)
            C[(size_t)(m0 + ty * 4 + i) * Nn + n0 + tx * 4 + j] =
                acc[i][j] + __ldg(&bias[n0 + tx * 4 + j]);
}

// ---------------- expert recurrence: NC CTAs cooperate, weights in registers ----------------
template <int H, int NC>
__device__ void expert_recur(int cta,
                             const float* __restrict__ Whh, const float* __restrict__ bhh,
                             const float* __restrict__ gi, float* __restrict__ Hbuf,
                             unsigned* __restrict__ flag, float* hs0, float* hs1)
{
    constexpr int JPC = H / NC;    // outputs (j) per CTA
    constexpr int JW  = JPC / 16;  // j per warp (16 warps)
    constexpr int KL  = H / 32;    // k elems per lane
    const int tid = threadIdx.x, w = tid >> 5, lane = tid & 31;
    const int jbase = cta * JPC + w * JW;
    const int own_lo = cta * JPC, own_hi = own_lo + JPC;

    float wreg[3][JW][KL];
    float bh[3][JW];
#pragma unroll
    for (int g = 0; g < 3; g++)
#pragma unroll
        for (int jj = 0; jj < JW; jj++) {
            int row = g * H + jbase + jj;
            bh[g][jj] = bhh[row];
#pragma unroll
            for (int kk = 0; kk < KL; kk++)
                wreg[g][jj][kk] = Whh[(size_t)row * H + kk * 32 + lane];
        }

    if (tid < H) { hs0[tid] = 0.f; hs1[tid] = 0.f; }
    __syncthreads();

    float* cur = hs0;
    float* nxt = hs1;

    // preload gi for t=0 (lane0 only; lane-local registers)
    float gr[3][JW];
    if (lane == 0) {
#pragma unroll
        for (int g = 0; g < 3; g++)
#pragma unroll
            for (int jj = 0; jj < JW; jj++) gr[g][jj] = __ldg(&gi[g * H + jbase + jj]);
    }

    for (int t = 0; t < NN; t++) {
        float acc[3][JW];
#pragma unroll
        for (int g = 0; g < 3; g++)
#pragma unroll
            for (int jj = 0; jj < JW; jj++) acc[g][jj] = 0.f;

#pragma unroll
        for (int kk = 0; kk < KL; kk++) {
            float hv = cur[kk * 32 + lane];
#pragma unroll
            for (int g = 0; g < 3; g++)
#pragma unroll
                for (int jj = 0; jj < JW; jj++) acc[g][jj] += wreg[g][jj][kk] * hv;
        }
#pragma unroll
        for (int g = 0; g < 3; g++)
#pragma unroll
            for (int jj = 0; jj < JW; jj++)
#pragma unroll
                for (int off = 16; off > 0; off >>= 1)
                    acc[g][jj] += __shfl_xor_sync(0xffffffffu, acc[g][jj], off);

        if (lane == 0) {
#pragma unroll
            for (int jj = 0; jj < JW; jj++) {
                int j = jbase + jj;
                float r = sigf(gr[0][jj] + acc[0][jj] + bh[0][jj]);
                float z = sigf(gr[1][jj] + acc[1][jj] + bh[1][jj]);
                float n = tanhf(gr[2][jj] + r * (acc[2][jj] + bh[2][jj]));
                float hn = (1.f - z) * n + z * cur[j];
                nxt[j] = hn;
                Hbuf[(size_t)t * H + j] = hn;
            }
            // prefetch gi for t+1 (hidden under the barrier wait)
            int tn = (t + 1 < NN) ? t + 1 : t;
            const float* gin = gi + (size_t)tn * 3 * H;
#pragma unroll
            for (int g = 0; g < 3; g++)
#pragma unroll
                for (int jj = 0; jj < JW; jj++) gr[g][jj] = __ldg(&gin[g * H + jbase + jj]);
        }
        // ---- inter-CTA barrier: per-CTA release flags, no atomics ----
        unsigned* ft = flag + (size_t)t * 32;
        __syncthreads();                          // all warps' h stores done (CTA h-b)
        if (tid == 0) st_release(&ft[cta], 1u);   // cumulative release of CTA's stores
        if (w == 0) {
            unsigned got;
            do {
                got = (lane < NC) ? ld_acquire(&ft[lane]) : 1u;
            } while (__any_sync(0xffffffffu, got == 0u));
        }
        __syncthreads();                          // acquire propagates to whole CTA
        if (tid < H && (tid < own_lo || tid >= own_hi))
            nxt[tid] = __ldcg(&Hbuf[(size_t)t * H + tid]);
        __syncthreads();
        float* tmp = cur; cur = nxt; nxt = tmp;
    }
}

// ---------------- router recurrence: one CTA per batch item, L2-streamed weights ----------------
__device__ void router_recur(int b, const float* __restrict__ Whh, const float* __restrict__ bhh,
                             float* cur, float* nxt)
{
    const int tid = threadIdx.x, w = tid >> 5, lane = tid & 31;
    const int j0 = w * 16;
    if (tid < HRR) { cur[tid] = 0.f; }
    __syncthreads();

    for (int t = 0; t < TT; t++) {
        const int n = t * BB + b;
        const float* git = g_gi_r + (size_t)n * 768;
        float4 h1 = *reinterpret_cast<const float4*>(cur + lane * 4);
        float4 h2 = *reinterpret_cast<const float4*>(cur + 128 + lane * 4);
#pragma unroll 2
        for (int jj = 0; jj < 16; jj++) {
            int j = j0 + jj;
            const float4* r0 = reinterpret_cast<const float4*>(Whh + (size_t)j * HRR);
            const float4* r1 = reinterpret_cast<const float4*>(Whh + (size_t)(j + 256) * HRR);
            const float4* r2 = reinterpret_cast<const float4*>(Whh + (size_t)(j + 512) * HRR);
            float4 a = __ldg(r0 + lane), c = __ldg(r0 + 32 + lane);
            float s0 = a.x * h1.x + a.y * h1.y + a.z * h1.z + a.w * h1.w
                     + c.x * h2.x + c.y * h2.y + c.z * h2.z + c.w * h2.w;
            a = __ldg(r1 + lane); c = __ldg(r1 + 32 + lane);
            float s1 = a.x * h1.x + a.y * h1.y + a.z * h1.z + a.w * h1.w
                     + c.x * h2.x + c.y * h2.y + c.z * h2.z + c.w * h2.w;
            a = __ldg(r2 + lane); c = __ldg(r2 + 32 + lane);
            float s2 = a.x * h1.x + a.y * h1.y + a.z * h1.z + a.w * h1.w
                     + c.x * h2.x + c.y * h2.y + c.z * h2.z + c.w * h2.w;
#pragma unroll
            for (int off = 16; off > 0; off >>= 1) {
                s0 += __shfl_xor_sync(0xffffffffu, s0, off);
                s1 += __shfl_xor_sync(0xffffffffu, s1, off);
                s2 += __shfl_xor_sync(0xffffffffu, s2, off);
            }
            if (lane == 0) {
                float r = sigf(__ldg(&git[j]) + s0 + __ldg(&bhh[j]));
                float z = sigf(__ldg(&git[256 + j]) + s1 + __ldg(&bhh[256 + j]));
                float nn2 = tanhf(__ldg(&git[512 + j]) + r * (s2 + __ldg(&bhh[512 + j])));
                float hn = (1.f - z) * nn2 + z * cur[j];
                nxt[j] = hn;
                g_Hr[(size_t)n * HRR + j] = hn;
            }
        }
        __syncthreads();
        float* tmp = cur; cur = nxt; nxt = tmp;
    }
}

// ---------------- fused recurrence kernel: 58 co-resident CTAs ----------------
__global__ __launch_bounds__(512) void k_recur(
    const float* r_whh, const float* r_bhh,
    const float* e1_whh, const float* e1_bhh,
    const float* e2_whh, const float* e2_bhh,
    const float* e3_whh, const float* e3_bhh)
{
    __shared__ float hsm[1152];
    int c = blockIdx.x;
    if (c < 32)      expert_recur<512, 32>(c,     e3_whh, e3_bhh, g_gi_e3, g_H3, g_f3, hsm, hsm + 576);
    else if (c < 40) expert_recur<256, 8>(c - 32, e2_whh, e2_bhh, g_gi_e2, g_H2, g_f2, hsm, hsm + 576);
    else if (c < 42) expert_recur<128, 2>(c - 40, e1_whh, e1_bhh, g_gi_e1, g_H1, g_f1, hsm, hsm + 576);
    else             router_recur(c - 42, r_whh, r_bhh, hsm, hsm + 576);
}

// ---------------- gates: logits -> softmax -> raw, eul, task sums ----------------
__global__ void k_gates(const float* __restrict__ rw, const float* __restrict__ rb,
                        const int* __restrict__ task, float* __restrict__ out_raw)
{
    int warp = (blockIdx.x * blockDim.x + threadIdx.x) >> 5;
    int lane = threadIdx.x & 31;
    if (warp >= NN) return;
    const float* h = g_Hr + (size_t)warp * HRR;
    float hr[8];
#pragma unroll
    for (int i = 0; i < 8; i++) hr[i] = fmaxf(h[i * 32 + lane], 0.f);
    float lg[4];
#pragma unroll
    for (int e = 0; e < 4; e++) {
        float s = 0.f;
#pragma unroll
        for (int i = 0; i < 8; i++) s += __ldg(&rw[e * HRR + i * 32 + lane]) * hr[i];
#pragma unroll
        for (int off = 16; off > 0; off >>= 1) s += __shfl_xor_sync(0xffffffffu, s, off);
        lg[e] = s;
    }
    if (lane == 0) {
#pragma unroll
        for (int e = 0; e < 4; e++) lg[e] += __ldg(&rb[e]);
        float mx = fmaxf(fmaxf(lg[0], lg[1]), fmaxf(lg[2], lg[3]));
        float ex[4], se = 0.f;
#pragma unroll
        for (int e = 0; e < 4; e++) { ex[e] = __expf(lg[e] - mx); se += ex[e]; }
        float inv = 1.f / se;
        float gg[4];
#pragma unroll
        for (int e = 0; e < 4; e++) {
            gg[e] = ex[e] * inv;
            out_raw[warp * 4 + e] = gg[e];
            g_gates[warp * 4 + e] = gg[e];
        }
        float eul = gg[1] * 128.f + gg[2] * 256.f + gg[3] * 512.f;
        int tk = task[warp];
        atomicAdd(&g_tsum[tk], eul);
        atomicAdd(&g_tcnt[tk], 1u);
    }
}

// ---------------- BN stats: per-column mean/var -> affine A,B ----------------
__global__ void k_bn(const float* g1, const float* b1, const float* g2, const float* b2,
                     const float* g3, const float* b3)
{
    int bid = blockIdx.x, tid = threadIdx.x;
    const float* Hb; int H, ei, c;
    if (bid == 0)      { Hb = g_H1; H = 128; ei = 0; c = tid; }
    else if (bid < 3)  { Hb = g_H2; H = 256; ei = 1; c = (bid - 1) * 128 + tid; }
    else               { Hb = g_H3; H = 512; ei = 2; c = (bid - 3) * 128 + tid; }
    float s = 0.f, s2 = 0.f;
#pragma unroll 8
    for (int n = 0; n < NN; n++) {
        float v = __ldg(&Hb[(size_t)n * H + c]);
        s += v; s2 += v * v;
    }
    float mu = s * (1.f / NN);
    float var = s2 * (1.f / NN) - mu * mu;
    const float* gg = (ei == 0) ? g1 : (ei == 1) ? g2 : g3;
    const float* bb = (ei == 0) ? b1 : (ei == 1) ? b2 : b3;
    float A = gg[c] * rsqrtf(var + BN_EPS);
    g_bnA[ei][c] = A;
    g_bnB[ei][c] = bb[c] - mu * A;
}

// ---------------- epilogue: out (+)= gate_i * (relu(bn(H_i)) @ ow^T + ob) ----------------
__global__ __launch_bounds__(256) void k_epi(
    const float* __restrict__ ow, const float* __restrict__ ob,
    const float* __restrict__ x, float* __restrict__ out, int ei, int H)
{
    const float* Hb = (ei == 1) ? g_H1 : (ei == 2) ? g_H2 : g_H3;
    const float* bA = g_bnA[ei - 1];
    const float* bBv = g_bnB[ei - 1];
    __shared__ float As[64][17];
    __shared__ float Ws[64][17];
    const int tid = threadIdx.x;
    const int tx = tid & 15, ty = tid >> 4;
    const int m0 = blockIdx.y * 64, n0 = blockIdx.x * 64;
    const int lr = tid >> 2, lc = (tid & 3) * 4;

    float acc[4][4];
#pragma unroll
    for (int i = 0; i < 4; i++)
#pragma unroll
        for (int j = 0; j < 4; j++) acc[i][j] = 0.f;

    for (int kb = 0; kb < H; kb += 16) {
        float4 av = *reinterpret_cast<const float4*>(&Hb[(size_t)(m0 + lr) * H + kb + lc]);
        float4 wv = *reinterpret_cast<const float4*>(&ow[(size_t)(n0 + lr) * H + kb + lc]);
        As[lr][lc + 0] = fmaxf(av.x * __ldg(&bA[kb + lc + 0]) + __ldg(&bBv[kb + lc + 0]), 0.f);
        As[lr][lc + 1] = fmaxf(av.y * __ldg(&bA[kb + lc + 1]) + __ldg(&bBv[kb + lc + 1]), 0.f);
        As[lr][lc + 2] = fmaxf(av.z * __ldg(&bA[kb + lc + 2]) + __ldg(&bBv[kb + lc + 2]), 0.f);
        As[lr][lc + 3] = fmaxf(av.w * __ldg(&bA[kb + lc + 3]) + __ldg(&bBv[kb + lc + 3]), 0.f);
        Ws[lr][lc + 0] = wv.x; Ws[lr][lc + 1] = wv.y; Ws[lr][lc + 2] = wv.z; Ws[lr][lc + 3] = wv.w;
        __syncthreads();
#pragma unroll
        for (int k = 0; k < 16; k++) {
            float a[4], b[4];
#pragma unroll
            for (int i = 0; i < 4; i++) a[i] = As[ty * 4 + i][k];
#pragma unroll
            for (int j = 0; j < 4; j++) b[j] = Ws[tx * 4 + j][k];
#pragma unroll
            for (int i = 0; i < 4; i++)
#pragma unroll
                for (int j = 0; j < 4; j++) acc[i][j] += a[i] * b[j];
        }
        __syncthreads();
    }
#pragma unroll
    for (int i = 0; i < 4; i++) {
        int m = m0 + ty * 4 + i;
        float gate = g_gates[m * 4 + ei];
        float g0 = g_gates[m * 4];
#pragma unroll
        for (int j = 0; j < 4; j++) {
            int n = n0 + tx * 4 + j;
            float v = (acc[i][j] + __ldg(&ob[n])) * gate;
            if (ei == 1) v += g0 * __ldg(&x[(size_t)m * DD + n]);
            else         v += out[(size_t)m * DD + n];
            out[(size_t)m * DD + n] = v;
        }
    }
}

// ---------------- task losses ----------------
__global__ void k_tl(float* o) {
    int i = threadIdx.x;
    if (i < 4) o[i] = g_tsum[i] / (float)g_tcnt[i];
}

// ---------------- launch ----------------
extern "C" void kernel_launch(void* const* d_in, const int* in_sizes, int n_in,
                              void* d_out, int out_size)
{
    const float* x      = (const float*)d_in[0];
    const int*   task   = (const int*)d_in[1];
    const float* r_wih  = (const float*)d_in[2];
    const float* r_whh  = (const float*)d_in[3];
    const float* r_bih  = (const float*)d_in[4];
    const float* r_bhh  = (const float*)d_in[5];
    const float* r_ow   = (const float*)d_in[6];
    const float* r_ob   = (const float*)d_in[7];
    const float* e1_wih = (const float*)d_in[8];
    const float* e1_whh = (const float*)d_in[9];
    const float* e1_bih = (const float*)d_in[10];
    const float* e1_bhh = (const float*)d_in[11];
    const float* e1_bng = (const float*)d_in[12];
    const float* e1_bnb = (const float*)d_in[13];
    const float* e1_ow  = (const float*)d_in[14];
    const float* e1_ob  = (const float*)d_in[15];
    const float* e2_wih = (const float*)d_in[16];
    const float* e2_whh = (const float*)d_in[17];
    const float* e2_bih = (const float*)d_in[18];
    const float* e2_bhh = (const float*)d_in[19];
    const float* e2_bng = (const float*)d_in[20];
    const float* e2_bnb = (const float*)d_in[21];
    const float* e2_ow  = (const float*)d_in[22];
    const float* e2_ob  = (const float*)d_in[23];
    const float* e3_wih = (const float*)d_in[24];
    const float* e3_whh = (const float*)d_in[25];
    const float* e3_bih = (const float*)d_in[26];
    const float* e3_bhh = (const float*)d_in[27];
    const float* e3_bng = (const float*)d_in[28];
    const float* e3_bnb = (const float*)d_in[29];
    const float* e3_ow  = (const float*)d_in[30];
    const float* e3_ob  = (const float*)d_in[31];

    float* out = (float*)d_out;
    float* raw = out + (size_t)NN * DD;
    float* tl  = raw + (size_t)NN * 4;

    k_zero<<<512, 256>>>();
    k_gemm_bias<<<dim3(12, 64), 256>>>(x, r_wih,  r_bih,  0, 768);
    k_gemm_bias<<<dim3(6, 64),  256>>>(x, e1_wih, e1_bih, 1, 384);
    k_gemm_bias<<<dim3(12, 64), 256>>>(x, e2_wih, e2_bih, 2, 768);
    k_gemm_bias<<<dim3(24, 64), 256>>>(x, e3_wih, e3_bih, 3, 1536);
    k_recur<<<58, 512>>>(r_whh, r_bhh, e1_whh, e1_bhh, e2_whh, e2_bhh, e3_whh, e3_bhh);
    k_gates<<<512, 256>>>(r_ow, r_ob, task, raw);
    k_bn<<<7, 128>>>(e1_bng, e1_bnb, e2_bng, e2_bnb, e3_bng, e3_bnb);
    k_epi<<<dim3(8, 64), 256>>>(e1_ow, e1_ob, x, out, 1, 128);
    k_epi<<<dim3(8, 64), 256>>>(e2_ow, e2_ob, x, out, 2, 256);
    k_epi<<<dim3(8, 64), 256>>>(e3_ow, e3_ob, x, out, 3, 512);
    k_tl<<<1, 32>>>(tl);
}

// round 7
// speedup vs baseline: 1.4668x; 1.2623x over previous
#include <cuda_runtime.h>
#include <math.h>

#define TT 256
#define BB 16
#define DD 512
#define NN 4096
#define HRR 256
#define BN_EPS 1e-5f

// ---------------- device scratch ----------------
__device__ float g_gi_r [NN * 768];
__device__ float g_gi_e1[NN * 384];
__device__ float g_gi_e2[NN * 768];
__device__ float g_gi_e3[NN * 1536];
__device__ float g_Hr[NN * HRR];
__device__ float g_H1[NN * 128];
__device__ float g_H2[NN * 256];
__device__ float g_H3[NN * 512];
// tagged exchange pairs: [parity*H + j] = (tag<<32) | float_bits   (single 8B word)
__device__ unsigned long long g_p1[2 * 128];
__device__ unsigned long long g_p2[2 * 256];
__device__ unsigned long long g_p3[2 * 512];
__device__ float g_gates[NN * 4];
__device__ float g_bnA[3][512];
__device__ float g_bnB[3][512];
__device__ float g_tsum[4];
__device__ unsigned g_tcnt[4];

__device__ __forceinline__ float sigf(float x) { return 1.f / (1.f + __expf(-x)); }

__device__ __forceinline__ void st_pair(unsigned long long* p, float v, unsigned tag) {
    unsigned long long x = ((unsigned long long)tag << 32) | (unsigned long long)__float_as_uint(v);
    asm volatile("st.relaxed.gpu.global.b64 [%0], %1;" :: "l"(p), "l"(x) : "memory");
}
__device__ __forceinline__ unsigned long long ld_pair(const unsigned long long* p) {
    unsigned long long v;
    asm volatile("ld.relaxed.gpu.global.b64 %0, [%1];" : "=l"(v) : "l"(p) : "memory");
    return v;
}

// ---------------- zero pairs / accumulators ----------------
__global__ void k_zero() {
    int i = blockIdx.x * 256 + threadIdx.x;
    if (i < 1024) g_p3[i] = 0ull;
    if (i < 512)  g_p2[i] = 0ull;
    if (i < 256)  g_p1[i] = 0ull;
    if (i < 4) { g_tsum[i] = 0.f; g_tcnt[i] = 0u; }
}

// ---------------- gi GEMM: C[4096 x Nn] = A[4096 x 512] @ W[Nn x 512]^T + bias ----------------
__global__ __launch_bounds__(256) void k_gemm_bias(
    const float* __restrict__ A, const float* __restrict__ W,
    const float* __restrict__ bias, int which, int Nn)
{
    float* C = (which == 0) ? g_gi_r : (which == 1) ? g_gi_e1 : (which == 2) ? g_gi_e2 : g_gi_e3;
    __shared__ float As[64][17];
    __shared__ float Ws[64][17];
    const int tid = threadIdx.x;
    const int tx = tid & 15, ty = tid >> 4;
    const int m0 = blockIdx.y * 64, n0 = blockIdx.x * 64;
    const int lr = tid >> 2, lc = (tid & 3) * 4;

    float acc[4][4];
#pragma unroll
    for (int i = 0; i < 4; i++)
#pragma unroll
        for (int j = 0; j < 4; j++) acc[i][j] = 0.f;

    for (int kb = 0; kb < 512; kb += 16) {
        float4 av = *reinterpret_cast<const float4*>(&A[(size_t)(m0 + lr) * 512 + kb + lc]);
        float4 wv = *reinterpret_cast<const float4*>(&W[(size_t)(n0 + lr) * 512 + kb + lc]);
        As[lr][lc + 0] = av.x; As[lr][lc + 1] = av.y; As[lr][lc + 2] = av.z; As[lr][lc + 3] = av.w;
        Ws[lr][lc + 0] = wv.x; Ws[lr][lc + 1] = wv.y; Ws[lr][lc + 2] = wv.z; Ws[lr][lc + 3] = wv.w;
        __syncthreads();
#pragma unroll
        for (int k = 0; k < 16; k++) {
            float a[4], b[4];
#pragma unroll
            for (int i = 0; i < 4; i++) a[i] = As[ty * 4 + i][k];
#pragma unroll
            for (int j = 0; j < 4; j++) b[j] = Ws[tx * 4 + j][k];
#pragma unroll
            for (int i = 0; i < 4; i++)
#pragma unroll
                for (int j = 0; j < 4; j++) acc[i][j] += a[i] * b[j];
        }
        __syncthreads();
    }
#pragma unroll
    for (int i = 0; i < 4; i++)
#pragma unroll
        for (int j = 0; j < 4; j++)
            C[(size_t)(m0 + ty * 4 + i) * Nn + n0 + tx * 4 + j] =
                acc[i][j] + __ldg(&bias[n0 + tx * 4 + j]);
}

// ---------------- expert recurrence: tagged 8B exchange, 1 bar/step ----------------
template <int H, int NC>
__device__ void expert_recur(int cta,
                             const float* __restrict__ Whh, const float* __restrict__ bhh,
                             const float* __restrict__ gi, float* __restrict__ Hbuf,
                             unsigned long long* __restrict__ pbuf,  // [2*H]
                             float* hs0, float* hs1)
{
    constexpr int JPC = H / NC;    // outputs (j) per CTA
    constexpr int JW  = JPC / 16;  // j per warp (16 warps)
    constexpr int KL  = H / 32;    // k elems per lane
    const int tid = threadIdx.x, w = tid >> 5, lane = tid & 31;
    const int jbase = cta * JPC + w * JW;
    const int own_lo = cta * JPC, own_hi = own_lo + JPC;

    float wreg[3][JW][KL];
    float bh[3][JW];
#pragma unroll
    for (int g = 0; g < 3; g++)
#pragma unroll
        for (int jj = 0; jj < JW; jj++) {
            int row = g * H + jbase + jj;
            bh[g][jj] = bhh[row];
#pragma unroll
            for (int kk = 0; kk < KL; kk++)
                wreg[g][jj][kk] = Whh[(size_t)row * H + kk * 32 + lane];
        }

    if (tid < H) { hs0[tid] = 0.f; hs1[tid] = 0.f; }
    __syncthreads();

    float* cur = hs0;
    float* nxt = hs1;

    // preload gi for t=0 (lane0 only)
    float gr[3][JW];
    if (lane == 0) {
#pragma unroll
        for (int g = 0; g < 3; g++)
#pragma unroll
            for (int jj = 0; jj < JW; jj++) gr[g][jj] = __ldg(&gi[g * H + jbase + jj]);
    }

    for (int t = 0; t < NN; t++) {
        float acc[3][JW];
#pragma unroll
        for (int g = 0; g < 3; g++)
#pragma unroll
            for (int jj = 0; jj < JW; jj++) acc[g][jj] = 0.f;

#pragma unroll
        for (int kk = 0; kk < KL; kk++) {
            float hv = cur[kk * 32 + lane];
#pragma unroll
            for (int g = 0; g < 3; g++)
#pragma unroll
                for (int jj = 0; jj < JW; jj++) acc[g][jj] += wreg[g][jj][kk] * hv;
        }
#pragma unroll
        for (int g = 0; g < 3; g++)
#pragma unroll
            for (int jj = 0; jj < JW; jj++)
#pragma unroll
                for (int off = 16; off > 0; off >>= 1)
                    acc[g][jj] += __shfl_xor_sync(0xffffffffu, acc[g][jj], off);

        unsigned long long* pb = pbuf + (t & 1) * H;
        if (lane == 0) {
#pragma unroll
            for (int jj = 0; jj < JW; jj++) {
                int j = jbase + jj;
                float r = sigf(gr[0][jj] + acc[0][jj] + bh[0][jj]);
                float z = sigf(gr[1][jj] + acc[1][jj] + bh[1][jj]);
                float n = tanhf(gr[2][jj] + r * (acc[2][jj] + bh[2][jj]));
                float hn = (1.f - z) * n + z * cur[j];
                st_pair(&pb[j], hn, (unsigned)(t + 1));   // publish first (value+tag, one 8B word)
                nxt[j] = hn;                              // own slot locally
                Hbuf[(size_t)t * H + j] = hn;             // history (read only after kernel end)
            }
            // prefetch gi for t+1 (hidden under the wait)
            int tn = (t + 1 < NN) ? t + 1 : t;
            const float* gin = gi + (size_t)tn * 3 * H;
#pragma unroll
            for (int g = 0; g < 3; g++)
#pragma unroll
                for (int jj = 0; jj < JW; jj++) gr[g][jj] = __ldg(&gin[g * H + jj + jbase]);
        }
        // consumers: poll foreign slots — the confirming load IS the data
        if (tid < H && (tid < own_lo || tid >= own_hi)) {
            unsigned long long v;
            do { v = ld_pair(&pb[tid]); } while ((unsigned)(v >> 32) != (unsigned)(t + 1));
            nxt[tid] = __uint_as_float((unsigned)v);
        }
        __syncthreads();
        float* tmp = cur; cur = nxt; nxt = tmp;
    }
}

// ---------------- router recurrence: one CTA per batch item, L2-streamed weights ----------------
__device__ void router_recur(int b, const float* __restrict__ Whh, const float* __restrict__ bhh,
                             float* cur, float* nxt)
{
    const int tid = threadIdx.x, w = tid >> 5, lane = tid & 31;
    const int j0 = w * 16;
    if (tid < HRR) { cur[tid] = 0.f; }
    __syncthreads();

    for (int t = 0; t < TT; t++) {
        const int n = t * BB + b;
        const float* git = g_gi_r + (size_t)n * 768;
        float4 h1 = *reinterpret_cast<const float4*>(cur + lane * 4);
        float4 h2 = *reinterpret_cast<const float4*>(cur + 128 + lane * 4);
#pragma unroll 2
        for (int jj = 0; jj < 16; jj++) {
            int j = j0 + jj;
            const float4* r0 = reinterpret_cast<const float4*>(Whh + (size_t)j * HRR);
            const float4* r1 = reinterpret_cast<const float4*>(Whh + (size_t)(j + 256) * HRR);
            const float4* r2 = reinterpret_cast<const float4*>(Whh + (size_t)(j + 512) * HRR);
            float4 a = __ldg(r0 + lane), c = __ldg(r0 + 32 + lane);
            float s0 = a.x * h1.x + a.y * h1.y + a.z * h1.z + a.w * h1.w
                     + c.x * h2.x + c.y * h2.y + c.z * h2.z + c.w * h2.w;
            a = __ldg(r1 + lane); c = __ldg(r1 + 32 + lane);
            float s1 = a.x * h1.x + a.y * h1.y + a.z * h1.z + a.w * h1.w
                     + c.x * h2.x + c.y * h2.y + c.z * h2.z + c.w * h2.w;
            a = __ldg(r2 + lane); c = __ldg(r2 + 32 + lane);
            float s2 = a.x * h1.x + a.y * h1.y + a.z * h1.z + a.w * h1.w
                     + c.x * h2.x + c.y * h2.y + c.z * h2.z + c.w * h2.w;
#pragma unroll
            for (int off = 16; off > 0; off >>= 1) {
                s0 += __shfl_xor_sync(0xffffffffu, s0, off);
                s1 += __shfl_xor_sync(0xffffffffu, s1, off);
                s2 += __shfl_xor_sync(0xffffffffu, s2, off);
            }
            if (lane == 0) {
                float r = sigf(__ldg(&git[j]) + s0 + __ldg(&bhh[j]));
                float z = sigf(__ldg(&git[256 + j]) + s1 + __ldg(&bhh[256 + j]));
                float nn2 = tanhf(__ldg(&git[512 + j]) + r * (s2 + __ldg(&bhh[512 + j])));
                float hn = (1.f - z) * nn2 + z * cur[j];
                nxt[j] = hn;
                g_Hr[(size_t)n * HRR + j] = hn;
            }
        }
        __syncthreads();
        float* tmp = cur; cur = nxt; nxt = tmp;
    }
}

// ---------------- fused recurrence kernel: 58 co-resident CTAs ----------------
__global__ __launch_bounds__(512) void k_recur(
    const float* r_whh, const float* r_bhh,
    const float* e1_whh, const float* e1_bhh,
    const float* e2_whh, const float* e2_bhh,
    const float* e3_whh, const float* e3_bhh)
{
    __shared__ float hsm[1152];
    int c = blockIdx.x;
    if (c < 32)      expert_recur<512, 32>(c,     e3_whh, e3_bhh, g_gi_e3, g_H3, g_p3, hsm, hsm + 576);
    else if (c < 40) expert_recur<256, 8>(c - 32, e2_whh, e2_bhh, g_gi_e2, g_H2, g_p2, hsm, hsm + 576);
    else if (c < 42) expert_recur<128, 2>(c - 40, e1_whh, e1_bhh, g_gi_e1, g_H1, g_p1, hsm, hsm + 576);
    else             router_recur(c - 42, r_whh, r_bhh, hsm, hsm + 576);
}

// ---------------- gates: logits -> softmax -> raw, eul, task sums ----------------
__global__ void k_gates(const float* __restrict__ rw, const float* __restrict__ rb,
                        const int* __restrict__ task, float* __restrict__ out_raw)
{
    int warp = (blockIdx.x * blockDim.x + threadIdx.x) >> 5;
    int lane = threadIdx.x & 31;
    if (warp >= NN) return;
    const float* h = g_Hr + (size_t)warp * HRR;
    float hr[8];
#pragma unroll
    for (int i = 0; i < 8; i++) hr[i] = fmaxf(h[i * 32 + lane], 0.f);
    float lg[4];
#pragma unroll
    for (int e = 0; e < 4; e++) {
        float s = 0.f;
#pragma unroll
        for (int i = 0; i < 8; i++) s += __ldg(&rw[e * HRR + i * 32 + lane]) * hr[i];
#pragma unroll
        for (int off = 16; off > 0; off >>= 1) s += __shfl_xor_sync(0xffffffffu, s, off);
        lg[e] = s;
    }
    if (lane == 0) {
#pragma unroll
        for (int e = 0; e < 4; e++) lg[e] += __ldg(&rb[e]);
        float mx = fmaxf(fmaxf(lg[0], lg[1]), fmaxf(lg[2], lg[3]));
        float ex[4], se = 0.f;
#pragma unroll
        for (int e = 0; e < 4; e++) { ex[e] = __expf(lg[e] - mx); se += ex[e]; }
        float inv = 1.f / se;
        float gg[4];
#pragma unroll
        for (int e = 0; e < 4; e++) {
            gg[e] = ex[e] * inv;
            out_raw[warp * 4 + e] = gg[e];
            g_gates[warp * 4 + e] = gg[e];
        }
        float eul = gg[1] * 128.f + gg[2] * 256.f + gg[3] * 512.f;
        int tk = task[warp];
        atomicAdd(&g_tsum[tk], eul);
        atomicAdd(&g_tcnt[tk], 1u);
    }
}

// ---------------- BN stats: per-column mean/var -> affine A,B ----------------
__global__ void k_bn(const float* g1, const float* b1, const float* g2, const float* b2,
                     const float* g3, const float* b3)
{
    int bid = blockIdx.x, tid = threadIdx.x;
    const float* Hb; int H, ei, c;
    if (bid == 0)      { Hb = g_H1; H = 128; ei = 0; c = tid; }
    else if (bid < 3)  { Hb = g_H2; H = 256; ei = 1; c = (bid - 1) * 128 + tid; }
    else               { Hb = g_H3; H = 512; ei = 2; c = (bid - 3) * 128 + tid; }
    float s = 0.f, s2 = 0.f;
#pragma unroll 8
    for (int n = 0; n < NN; n++) {
        float v = __ldg(&Hb[(size_t)n * H + c]);
        s += v; s2 += v * v;
    }
    float mu = s * (1.f / NN);
    float var = s2 * (1.f / NN) - mu * mu;
    const float* gg = (ei == 0) ? g1 : (ei == 1) ? g2 : g3;
    const float* bb = (ei == 0) ? b1 : (ei == 1) ? b2 : b3;
    float A = gg[c] * rsqrtf(var + BN_EPS);
    g_bnA[ei][c] = A;
    g_bnB[ei][c] = bb[c] - mu * A;
}

// ---------------- epilogue: out (+)= gate_i * (relu(bn(H_i)) @ ow^T + ob) ----------------
__global__ __launch_bounds__(256) void k_epi(
    const float* __restrict__ ow, const float* __restrict__ ob,
    const float* __restrict__ x, float* __restrict__ out, int ei, int H)
{
    const float* Hb = (ei == 1) ? g_H1 : (ei == 2) ? g_H2 : g_H3;
    const float* bA = g_bnA[ei - 1];
    const float* bBv = g_bnB[ei - 1];
    __shared__ float As[64][17];
    __shared__ float Ws[64][17];
    const int tid = threadIdx.x;
    const int tx = tid & 15, ty = tid >> 4;
    const int m0 = blockIdx.y * 64, n0 = blockIdx.x * 64;
    const int lr = tid >> 2, lc = (tid & 3) * 4;

    float acc[4][4];
#pragma unroll
    for (int i = 0; i < 4; i++)
#pragma unroll
        for (int j = 0; j < 4; j++) acc[i][j] = 0.f;

    for (int kb = 0; kb < H; kb += 16) {
        float4 av = *reinterpret_cast<const float4*>(&Hb[(size_t)(m0 + lr) * H + kb + lc]);
        float4 wv = *reinterpret_cast<const float4*>(&ow[(size_t)(n0 + lr) * H + kb + lc]);
        As[lr][lc + 0] = fmaxf(av.x * __ldg(&bA[kb + lc + 0]) + __ldg(&bBv[kb + lc + 0]), 0.f);
        As[lr][lc + 1] = fmaxf(av.y * __ldg(&bA[kb + lc + 1]) + __ldg(&bBv[kb + lc + 1]), 0.f);
        As[lr][lc + 2] = fmaxf(av.z * __ldg(&bA[kb + lc + 2]) + __ldg(&bBv[kb + lc + 2]), 0.f);
        As[lr][lc + 3] = fmaxf(av.w * __ldg(&bA[kb + lc + 3]) + __ldg(&bBv[kb + lc + 3]), 0.f);
        Ws[lr][lc + 0] = wv.x; Ws[lr][lc + 1] = wv.y; Ws[lr][lc + 2] = wv.z; Ws[lr][lc + 3] = wv.w;
        __syncthreads();
#pragma unroll
        for (int k = 0; k < 16; k++) {
            float a[4], b[4];
#pragma unroll
            for (int i = 0; i < 4; i++) a[i] = As[ty * 4 + i][k];
#pragma unroll
            for (int j = 0; j < 4; j++) b[j] = Ws[tx * 4 + j][k];
#pragma unroll
            for (int i = 0; i < 4; i++)
#pragma unroll
                for (int j = 0; j < 4; j++) acc[i][j] += a[i] * b[j];
        }
        __syncthreads();
    }
#pragma unroll
    for (int i = 0; i < 4; i++) {
        int m = m0 + ty * 4 + i;
        float gate = g_gates[m * 4 + ei];
        float g0 = g_gates[m * 4];
#pragma unroll
        for (int j = 0; j < 4; j++) {
            int n = n0 + tx * 4 + j;
            float v = (acc[i][j] + __ldg(&ob[n])) * gate;
            if (ei == 1) v += g0 * __ldg(&x[(size_t)m * DD + n]);
            else         v += out[(size_t)m * DD + n];
            out[(size_t)m * DD + n] = v;
        }
    }
}

// ---------------- task losses ----------------
__global__ void k_tl(float* o) {
    int i = threadIdx.x;
    if (i < 4) o[i] = g_tsum[i] / (float)g_tcnt[i];
}

// ---------------- launch ----------------
extern "C" void kernel_launch(void* const* d_in, const int* in_sizes, int n_in,
                              void* d_out, int out_size)
{
    const float* x      = (const float*)d_in[0];
    const int*   task   = (const int*)d_in[1];
    const float* r_wih  = (const float*)d_in[2];
    const float* r_whh  = (const float*)d_in[3];
    const float* r_bih  = (const float*)d_in[4];
    const float* r_bhh  = (const float*)d_in[5];
    const float* r_ow   = (const float*)d_in[6];
    const float* r_ob   = (const float*)d_in[7];
    const float* e1_wih = (const float*)d_in[8];
    const float* e1_whh = (const float*)d_in[9];
    const float* e1_bih = (const float*)d_in[10];
    const float* e1_bhh = (const float*)d_in[11];
    const float* e1_bng = (const float*)d_in[12];
    const float* e1_bnb = (const float*)d_in[13];
    const float* e1_ow  = (const float*)d_in[14];
    const float* e1_ob  = (const float*)d_in[15];
    const float* e2_wih = (const float*)d_in[16];
    const float* e2_whh = (const float*)d_in[17];
    const float* e2_bih = (const float*)d_in[18];
    const float* e2_bhh = (const float*)d_in[19];
    const float* e2_bng = (const float*)d_in[20];
    const float* e2_bnb = (const float*)d_in[21];
    const float* e2_ow  = (const float*)d_in[22];
    const float* e2_ob  = (const float*)d_in[23];
    const float* e3_wih = (const float*)d_in[24];
    const float* e3_whh = (const float*)d_in[25];
    const float* e3_bih = (const float*)d_in[26];
    const float* e3_bhh = (const float*)d_in[27];
    const float* e3_bng = (const float*)d_in[28];
    const float* e3_bnb = (const float*)d_in[29];
    const float* e3_ow  = (const float*)d_in[30];
    const float* e3_ob  = (const float*)d_in[31];

    float* out = (float*)d_out;
    float* raw = out + (size_t)NN * DD;
    float* tl  = raw + (size_t)NN * 4;

    k_zero<<<8, 256>>>();
    k_gemm_bias<<<dim3(12, 64), 256>>>(x, r_wih,  r_bih,  0, 768);
    k_gemm_bias<<<dim3(6, 64),  256>>>(x, e1_wih, e1_bih, 1, 384);
    k_gemm_bias<<<dim3(12, 64), 256>>>(x, e2_wih, e2_bih, 2, 768);
    k_gemm_bias<<<dim3(24, 64), 256>>>(x, e3_wih, e3_bih, 3, 1536);
    k_recur<<<58, 512>>>(r_whh, r_bhh, e1_whh, e1_bhh, e2_whh, e2_bhh, e3_whh, e3_bhh);
    k_gates<<<512, 256>>>(r_ow, r_ob, task, raw);
    k_bn<<<7, 128>>>(e1_bng, e1_bnb, e2_bng, e2_bnb, e3_bng, e3_bnb);
    k_epi<<<dim3(8, 64), 256>>>(e1_ow, e1_ob, x, out, 1, 128);
    k_epi<<<dim3(8, 64), 256>>>(e2_ow, e2_ob, x, out, 2, 256);
    k_epi<<<dim3(8, 64), 256>>>(e3_ow, e3_ob, x, out, 3, 512);
    k_tl<<<1, 32>>>(tl);
}

// round 8
// speedup vs baseline: 1.5464x; 1.0543x over previous
#include <cuda_runtime.h>
#include <math.h>

#define TT 256
#define BB 16
#define DD 512
#define NN 4096
#define HRR 256
#define BN_EPS 1e-5f

// ---------------- device scratch ----------------
__device__ float g_gi_r [NN * 768];
__device__ float g_gi_e1[NN * 384];
__device__ float g_gi_e2[NN * 768];
__device__ float g_gi_e3[NN * 1536];
__device__ float g_Hr[NN * HRR];
__device__ float g_H1[NN * 128];
__device__ float g_H2[NN * 256];
__device__ float g_H3[NN * 512];
// replicated tagged exchange: [consumer_cta][parity][j] = (tag<<32)|float_bits
__device__ unsigned long long g_p1[2  * 2 * 128];
__device__ unsigned long long g_p2[8  * 2 * 256];
__device__ unsigned long long g_p3[32 * 2 * 512];
__device__ float g_gates[NN * 4];
__device__ float g_bnA[3][512];
__device__ float g_bnB[3][512];
__device__ float g_tsum[4];
__device__ unsigned g_tcnt[4];

__device__ __forceinline__ float sigf(float x) { return 1.f / (1.f + __expf(-x)); }

__device__ __forceinline__ void st_pair(unsigned long long* p, float v, unsigned tag) {
    unsigned long long x = ((unsigned long long)tag << 32) | (unsigned long long)__float_as_uint(v);
    asm volatile("st.relaxed.gpu.global.b64 [%0], %1;" :: "l"(p), "l"(x) : "memory");
}
__device__ __forceinline__ unsigned long long ld_pair(const unsigned long long* p) {
    unsigned long long v;
    asm volatile("ld.relaxed.gpu.global.b64 %0, [%1];" : "=l"(v) : "l"(p) : "memory");
    return v;
}

// ---------------- zero pairs / accumulators ----------------
__global__ void k_zero() {
    int i = blockIdx.x * 256 + threadIdx.x;
    if (i < 32 * 2 * 512) g_p3[i] = 0ull;
    if (i < 8 * 2 * 256)  g_p2[i] = 0ull;
    if (i < 2 * 2 * 128)  g_p1[i] = 0ull;
    if (i < 4) { g_tsum[i] = 0.f; g_tcnt[i] = 0u; }
}

// ---------------- merged gi GEMM: all four projections in one launch ----------------
// segment s: C[4096 x Nn] = x[4096 x 512] @ W[Nn x 512]^T + bias
__global__ __launch_bounds__(256) void k_gemm_all(
    const float* __restrict__ A,
    const float* __restrict__ w0, const float* __restrict__ bz0,
    const float* __restrict__ w1, const float* __restrict__ bz1,
    const float* __restrict__ w2, const float* __restrict__ bz2,
    const float* __restrict__ w3, const float* __restrict__ bz3)
{
    int bid = blockIdx.x;
    const float* W; const float* bias; float* C; int Nn, nb;
    if (bid < 768)       { W = w0; bias = bz0; C = g_gi_r;  Nn = 768;  nb = 12; }
    else if (bid < 1152) { bid -= 768;  W = w1; bias = bz1; C = g_gi_e1; Nn = 384;  nb = 6; }
    else if (bid < 1920) { bid -= 1152; W = w2; bias = bz2; C = g_gi_e2; Nn = 768;  nb = 12; }
    else                 { bid -= 1920; W = w3; bias = bz3; C = g_gi_e3; Nn = 1536; nb = 24; }
    const int n0 = (bid % nb) * 64, m0 = (bid / nb) * 64;

    __shared__ float As[64][17];
    __shared__ float Ws[64][17];
    const int tid = threadIdx.x;
    const int tx = tid & 15, ty = tid >> 4;
    const int lr = tid >> 2, lc = (tid & 3) * 4;

    float acc[4][4];
#pragma unroll
    for (int i = 0; i < 4; i++)
#pragma unroll
        for (int j = 0; j < 4; j++) acc[i][j] = 0.f;

    for (int kb = 0; kb < 512; kb += 16) {
        float4 av = *reinterpret_cast<const float4*>(&A[(size_t)(m0 + lr) * 512 + kb + lc]);
        float4 wv = *reinterpret_cast<const float4*>(&W[(size_t)(n0 + lr) * 512 + kb + lc]);
        As[lr][lc + 0] = av.x; As[lr][lc + 1] = av.y; As[lr][lc + 2] = av.z; As[lr][lc + 3] = av.w;
        Ws[lr][lc + 0] = wv.x; Ws[lr][lc + 1] = wv.y; Ws[lr][lc + 2] = wv.z; Ws[lr][lc + 3] = wv.w;
        __syncthreads();
#pragma unroll
        for (int k = 0; k < 16; k++) {
            float a[4], b[4];
#pragma unroll
            for (int i = 0; i < 4; i++) a[i] = As[ty * 4 + i][k];
#pragma unroll
            for (int j = 0; j < 4; j++) b[j] = Ws[tx * 4 + j][k];
#pragma unroll
            for (int i = 0; i < 4; i++)
#pragma unroll
                for (int j = 0; j < 4; j++) acc[i][j] += a[i] * b[j];
        }
        __syncthreads();
    }
#pragma unroll
    for (int i = 0; i < 4; i++)
#pragma unroll
        for (int j = 0; j < 4; j++)
            C[(size_t)(m0 + ty * 4 + i) * Nn + n0 + tx * 4 + j] =
                acc[i][j] + __ldg(&bias[n0 + tx * 4 + j]);
}

// ---------------- expert recurrence: replicated tagged exchange ----------------
// pbuf layout: [NC][2][H]. Producer warp: butterfly leaves full sums in ALL lanes;
// lane L (< NC) computes gates redundantly and publishes to consumer-region L.
// Consumer CTA c polls ONLY region c (no cross-CTA hot lines).
template <int H, int NC>
__device__ void expert_recur(int cta,
                             const float* __restrict__ Whh, const float* __restrict__ bhh,
                             const float* __restrict__ gi, float* __restrict__ Hbuf,
                             unsigned long long* __restrict__ pbuf,
                             float* hs0, float* hs1)
{
    constexpr int JPC = H / NC;    // outputs (j) per CTA
    constexpr int JW  = JPC / 16;  // j per warp (16 warps)
    constexpr int KL  = H / 32;    // k elems per lane
    const int tid = threadIdx.x, w = tid >> 5, lane = tid & 31;
    const int jbase = cta * JPC + w * JW;
    const int own_lo = cta * JPC, own_hi = own_lo + JPC;

    float wreg[3][JW][KL];
    float bh[3][JW];
#pragma unroll
    for (int g = 0; g < 3; g++)
#pragma unroll
        for (int jj = 0; jj < JW; jj++) {
            int row = g * H + jbase + jj;
            bh[g][jj] = bhh[row];
#pragma unroll
            for (int kk = 0; kk < KL; kk++)
                wreg[g][jj][kk] = Whh[(size_t)row * H + kk * 32 + lane];
        }

    if (tid < H) { hs0[tid] = 0.f; hs1[tid] = 0.f; }
    __syncthreads();

    float* cur = hs0;
    float* nxt = hs1;

    // preload gi for t=0 (all lanes: warp-uniform broadcast loads)
    float gr[3][JW];
#pragma unroll
    for (int g = 0; g < 3; g++)
#pragma unroll
        for (int jj = 0; jj < JW; jj++) gr[g][jj] = __ldg(&gi[g * H + jbase + jj]);

    for (int t = 0; t < NN; t++) {
        float acc[3][JW];
#pragma unroll
        for (int g = 0; g < 3; g++)
#pragma unroll
            for (int jj = 0; jj < JW; jj++) acc[g][jj] = 0.f;

#pragma unroll
        for (int kk = 0; kk < KL; kk++) {
            float hv = cur[kk * 32 + lane];
#pragma unroll
            for (int g = 0; g < 3; g++)
#pragma unroll
                for (int jj = 0; jj < JW; jj++) acc[g][jj] += wreg[g][jj][kk] * hv;
        }
        // butterfly: ALL lanes end with the full sums
#pragma unroll
        for (int g = 0; g < 3; g++)
#pragma unroll
            for (int jj = 0; jj < JW; jj++)
#pragma unroll
                for (int off = 16; off > 0; off >>= 1)
                    acc[g][jj] += __shfl_xor_sync(0xffffffffu, acc[g][jj], off);

        const int par = t & 1;
        // gate math on every lane (redundant), publish per-lane to its region
        float hn[JW];
#pragma unroll
        for (int jj = 0; jj < JW; jj++) {
            int j = jbase + jj;
            float r = sigf(gr[0][jj] + acc[0][jj] + bh[0][jj]);
            float z = sigf(gr[1][jj] + acc[1][jj] + bh[1][jj]);
            float n = tanhf(gr[2][jj] + r * (acc[2][jj] + bh[2][jj]));
            hn[jj] = (1.f - z) * n + z * cur[j];
        }
        if (lane < NC) {
            unsigned long long* reg = pbuf + ((size_t)lane * 2 + par) * H;
#pragma unroll
            for (int jj = 0; jj < JW; jj++)
                st_pair(&reg[jbase + jj], hn[jj], (unsigned)(t + 1));
        }
        if (lane == 0) {
#pragma unroll
            for (int jj = 0; jj < JW; jj++) {
                nxt[jbase + jj] = hn[jj];
                Hbuf[(size_t)t * H + jbase + jj] = hn[jj];
            }
        }
        // prefetch gi for t+1 (hidden under the wait; warp-uniform)
        {
            int tn = (t + 1 < NN) ? t + 1 : t;
            const float* gin = gi + (size_t)tn * 3 * H;
#pragma unroll
            for (int g = 0; g < 3; g++)
#pragma unroll
                for (int jj = 0; jj < JW; jj++) gr[g][jj] = __ldg(&gin[g * H + jbase + jj]);
        }
        // consumers: poll ONLY this CTA's private region
        if (tid < H && (tid < own_lo || tid >= own_hi)) {
            const unsigned long long* reg = pbuf + ((size_t)cta * 2 + par) * H;
            unsigned long long v;
            do { v = ld_pair(&reg[tid]); } while ((unsigned)(v >> 32) != (unsigned)(t + 1));
            nxt[tid] = __uint_as_float((unsigned)v);
        }
        __syncthreads();
        float* tmp = cur; cur = nxt; nxt = tmp;
    }
}

// ---------------- router recurrence: one CTA per batch item, L2-streamed weights ----------------
__device__ void router_recur(int b, const float* __restrict__ Whh, const float* __restrict__ bhh,
                             float* cur, float* nxt)
{
    const int tid = threadIdx.x, w = tid >> 5, lane = tid & 31;
    const int j0 = w * 16;
    if (tid < HRR) { cur[tid] = 0.f; }
    __syncthreads();

    for (int t = 0; t < TT; t++) {
        const int n = t * BB + b;
        const float* git = g_gi_r + (size_t)n * 768;
        float4 h1 = *reinterpret_cast<const float4*>(cur + lane * 4);
        float4 h2 = *reinterpret_cast<const float4*>(cur + 128 + lane * 4);
#pragma unroll 2
        for (int jj = 0; jj < 16; jj++) {
            int j = j0 + jj;
            const float4* r0 = reinterpret_cast<const float4*>(Whh + (size_t)j * HRR);
            const float4* r1 = reinterpret_cast<const float4*>(Whh + (size_t)(j + 256) * HRR);
            const float4* r2 = reinterpret_cast<const float4*>(Whh + (size_t)(j + 512) * HRR);
            float4 a = __ldg(r0 + lane), c = __ldg(r0 + 32 + lane);
            float s0 = a.x * h1.x + a.y * h1.y + a.z * h1.z + a.w * h1.w
                     + c.x * h2.x + c.y * h2.y + c.z * h2.z + c.w * h2.w;
            a = __ldg(r1 + lane); c = __ldg(r1 + 32 + lane);
            float s1 = a.x * h1.x + a.y * h1.y + a.z * h1.z + a.w * h1.w
                     + c.x * h2.x + c.y * h2.y + c.z * h2.z + c.w * h2.w;
            a = __ldg(r2 + lane); c = __ldg(r2 + 32 + lane);
            float s2 = a.x * h1.x + a.y * h1.y + a.z * h1.z + a.w * h1.w
                     + c.x * h2.x + c.y * h2.y + c.z * h2.z + c.w * h2.w;
#pragma unroll
            for (int off = 16; off > 0; off >>= 1) {
                s0 += __shfl_xor_sync(0xffffffffu, s0, off);
                s1 += __shfl_xor_sync(0xffffffffu, s1, off);
                s2 += __shfl_xor_sync(0xffffffffu, s2, off);
            }
            if (lane == 0) {
                float r = sigf(__ldg(&git[j]) + s0 + __ldg(&bhh[j]));
                float z = sigf(__ldg(&git[256 + j]) + s1 + __ldg(&bhh[256 + j]));
                float nn2 = tanhf(__ldg(&git[512 + j]) + r * (s2 + __ldg(&bhh[512 + j])));
                float hn = (1.f - z) * nn2 + z * cur[j];
                nxt[j] = hn;
                g_Hr[(size_t)n * HRR + j] = hn;
            }
        }
        __syncthreads();
        float* tmp = cur; cur = nxt; nxt = tmp;
    }
}

// ---------------- fused recurrence kernel: 58 co-resident CTAs ----------------
__global__ __launch_bounds__(512) void k_recur(
    const float* r_whh, const float* r_bhh,
    const float* e1_whh, const float* e1_bhh,
    const float* e2_whh, const float* e2_bhh,
    const float* e3_whh, const float* e3_bhh)
{
    __shared__ float hsm[1152];
    int c = blockIdx.x;
    if (c < 32)      expert_recur<512, 32>(c,     e3_whh, e3_bhh, g_gi_e3, g_H3, g_p3, hsm, hsm + 576);
    else if (c < 40) expert_recur<256, 8>(c - 32, e2_whh, e2_bhh, g_gi_e2, g_H2, g_p2, hsm, hsm + 576);
    else if (c < 42) expert_recur<128, 2>(c - 40, e1_whh, e1_bhh, g_gi_e1, g_H1, g_p1, hsm, hsm + 576);
    else             router_recur(c - 42, r_whh, r_bhh, hsm, hsm + 576);
}

// ---------------- gates: logits -> softmax -> raw, eul, task sums ----------------
__global__ void k_gates(const float* __restrict__ rw, const float* __restrict__ rb,
                        const int* __restrict__ task, float* __restrict__ out_raw)
{
    int warp = (blockIdx.x * blockDim.x + threadIdx.x) >> 5;
    int lane = threadIdx.x & 31;
    if (warp >= NN) return;
    const float* h = g_Hr + (size_t)warp * HRR;
    float hr[8];
#pragma unroll
    for (int i = 0; i < 8; i++) hr[i] = fmaxf(h[i * 32 + lane], 0.f);
    float lg[4];
#pragma unroll
    for (int e = 0; e < 4; e++) {
        float s = 0.f;
#pragma unroll
        for (int i = 0; i < 8; i++) s += __ldg(&rw[e * HRR + i * 32 + lane]) * hr[i];
#pragma unroll
        for (int off = 16; off > 0; off >>= 1) s += __shfl_xor_sync(0xffffffffu, s, off);
        lg[e] = s;
    }
    if (lane == 0) {
#pragma unroll
        for (int e = 0; e < 4; e++) lg[e] += __ldg(&rb[e]);
        float mx = fmaxf(fmaxf(lg[0], lg[1]), fmaxf(lg[2], lg[3]));
        float ex[4], se = 0.f;
#pragma unroll
        for (int e = 0; e < 4; e++) { ex[e] = __expf(lg[e] - mx); se += ex[e]; }
        float inv = 1.f / se;
        float gg[4];
#pragma unroll
        for (int e = 0; e < 4; e++) {
            gg[e] = ex[e] * inv;
            out_raw[warp * 4 + e] = gg[e];
            g_gates[warp * 4 + e] = gg[e];
        }
        float eul = gg[1] * 128.f + gg[2] * 256.f + gg[3] * 512.f;
        int tk = task[warp];
        atomicAdd(&g_tsum[tk], eul);
        atomicAdd(&g_tcnt[tk], 1u);
    }
}

// ---------------- BN stats: per-column mean/var -> affine A,B ----------------
__global__ void k_bn(const float* g1, const float* b1, const float* g2, const float* b2,
                     const float* g3, const float* b3)
{
    int bid = blockIdx.x, tid = threadIdx.x;
    const float* Hb; int H, ei, c;
    if (bid == 0)      { Hb = g_H1; H = 128; ei = 0; c = tid; }
    else if (bid < 3)  { Hb = g_H2; H = 256; ei = 1; c = (bid - 1) * 128 + tid; }
    else               { Hb = g_H3; H = 512; ei = 2; c = (bid - 3) * 128 + tid; }
    float s = 0.f, s2 = 0.f;
#pragma unroll 8
    for (int n = 0; n < NN; n++) {
        float v = __ldg(&Hb[(size_t)n * H + c]);
        s += v; s2 += v * v;
    }
    float mu = s * (1.f / NN);
    float var = s2 * (1.f / NN) - mu * mu;
    const float* gg = (ei == 0) ? g1 : (ei == 1) ? g2 : g3;
    const float* bb = (ei == 0) ? b1 : (ei == 1) ? b2 : b3;
    float A = gg[c] * rsqrtf(var + BN_EPS);
    g_bnA[ei][c] = A;
    g_bnB[ei][c] = bb[c] - mu * A;
}

// ---------------- epilogue: out (+)= gate_i * (relu(bn(H_i)) @ ow^T + ob) ----------------
__global__ __launch_bounds__(256) void k_epi(
    const float* __restrict__ ow, const float* __restrict__ ob,
    const float* __restrict__ x, float* __restrict__ out, int ei, int H)
{
    const float* Hb = (ei == 1) ? g_H1 : (ei == 2) ? g_H2 : g_H3;
    const float* bA = g_bnA[ei - 1];
    const float* bBv = g_bnB[ei - 1];
    __shared__ float As[64][17];
    __shared__ float Ws[64][17];
    const int tid = threadIdx.x;
    const int tx = tid & 15, ty = tid >> 4;
    const int m0 = blockIdx.y * 64, n0 = blockIdx.x * 64;
    const int lr = tid >> 2, lc = (tid & 3) * 4;

    float acc[4][4];
#pragma unroll
    for (int i = 0; i < 4; i++)
#pragma unroll
        for (int j = 0; j < 4; j++) acc[i][j] = 0.f;

    for (int kb = 0; kb < H; kb += 16) {
        float4 av = *reinterpret_cast<const float4*>(&Hb[(size_t)(m0 + lr) * H + kb + lc]);
        float4 wv = *reinterpret_cast<const float4*>(&ow[(size_t)(n0 + lr) * H + kb + lc]);
        As[lr][lc + 0] = fmaxf(av.x * __ldg(&bA[kb + lc + 0]) + __ldg(&bBv[kb + lc + 0]), 0.f);
        As[lr][lc + 1] = fmaxf(av.y * __ldg(&bA[kb + lc + 1]) + __ldg(&bBv[kb + lc + 1]), 0.f);
        As[lr][lc + 2] = fmaxf(av.z * __ldg(&bA[kb + lc + 2]) + __ldg(&bBv[kb + lc + 2]), 0.f);
        As[lr][lc + 3] = fmaxf(av.w * __ldg(&bA[kb + lc + 3]) + __ldg(&bBv[kb + lc + 3]), 0.f);
        Ws[lr][lc + 0] = wv.x; Ws[lr][lc + 1] = wv.y; Ws[lr][lc + 2] = wv.z; Ws[lr][lc + 3] = wv.w;
        __syncthreads();
#pragma unroll
        for (int k = 0; k < 16; k++) {
            float a[4], b[4];
#pragma unroll
            for (int i = 0; i < 4; i++) a[i] = As[ty * 4 + i][k];
#pragma unroll
            for (int j = 0; j < 4; j++) b[j] = Ws[tx * 4 + j][k];
#pragma unroll
            for (int i = 0; i < 4; i++)
#pragma unroll
                for (int j = 0; j < 4; j++) acc[i][j] += a[i] * b[j];
        }
        __syncthreads();
    }
#pragma unroll
    for (int i = 0; i < 4; i++) {
        int m = m0 + ty * 4 + i;
        float gate = g_gates[m * 4 + ei];
        float g0 = g_gates[m * 4];
#pragma unroll
        for (int j = 0; j < 4; j++) {
            int n = n0 + tx * 4 + j;
            float v = (acc[i][j] + __ldg(&ob[n])) * gate;
            if (ei == 1) v += g0 * __ldg(&x[(size_t)m * DD + n]);
            else         v += out[(size_t)m * DD + n];
            out[(size_t)m * DD + n] = v;
        }
    }
}

// ---------------- task losses ----------------
__global__ void k_tl(float* o) {
    int i = threadIdx.x;
    if (i < 4) o[i] = g_tsum[i] / (float)g_tcnt[i];
}

// ---------------- launch ----------------
extern "C" void kernel_launch(void* const* d_in, const int* in_sizes, int n_in,
                              void* d_out, int out_size)
{
    const float* x      = (const float*)d_in[0];
    const int*   task   = (const int*)d_in[1];
    const float* r_wih  = (const float*)d_in[2];
    const float* r_whh  = (const float*)d_in[3];
    const float* r_bih  = (const float*)d_in[4];
    const float* r_bhh  = (const float*)d_in[5];
    const float* r_ow   = (const float*)d_in[6];
    const float* r_ob   = (const float*)d_in[7];
    const float* e1_wih = (const float*)d_in[8];
    const float* e1_whh = (const float*)d_in[9];
    const float* e1_bih = (const float*)d_in[10];
    const float* e1_bhh = (const float*)d_in[11];
    const float* e1_bng = (const float*)d_in[12];
    const float* e1_bnb = (const float*)d_in[13];
    const float* e1_ow  = (const float*)d_in[14];
    const float* e1_ob  = (const float*)d_in[15];
    const float* e2_wih = (const float*)d_in[16];
    const float* e2_whh = (const float*)d_in[17];
    const float* e2_bih = (const float*)d_in[18];
    const float* e2_bhh = (const float*)d_in[19];
    const float* e2_bng = (const float*)d_in[20];
    const float* e2_bnb = (const float*)d_in[21];
    const float* e2_ow  = (const float*)d_in[22];
    const float* e2_ob  = (const float*)d_in[23];
    const float* e3_wih = (const float*)d_in[24];
    const float* e3_whh = (const float*)d_in[25];
    const float* e3_bih = (const float*)d_in[26];
    const float* e3_bhh = (const float*)d_in[27];
    const float* e3_bng = (const float*)d_in[28];
    const float* e3_bnb = (const float*)d_in[29];
    const float* e3_ow  = (const float*)d_in[30];
    const float* e3_ob  = (const float*)d_in[31];

    float* out = (float*)d_out;
    float* raw = out + (size_t)NN * DD;
    float* tl  = raw + (size_t)NN * 4;

    k_zero<<<128, 256>>>();
    k_gemm_all<<<3456, 256>>>(x, r_wih, r_bih, e1_wih, e1_bih, e2_wih, e2_bih, e3_wih, e3_bih);
    k_recur<<<58, 512>>>(r_whh, r_bhh, e1_whh, e1_bhh, e2_whh, e2_bhh, e3_whh, e3_bhh);
    k_gates<<<512, 256>>>(r_ow, r_ob, task, raw);
    k_bn<<<7, 128>>>(e1_bng, e1_bnb, e2_bng, e2_bnb, e3_bng, e3_bnb);
    k_epi<<<dim3(8, 64), 256>>>(e1_ow, e1_ob, x, out, 1, 128);
    k_epi<<<dim3(8, 64), 256>>>(e2_ow, e2_ob, x, out, 2, 256);
    k_epi<<<dim3(8, 64), 256>>>(e3_ow, e3_ob, x, out, 3, 512);
    k_tl<<<1, 32>>>(tl);
}

// round 9
// speedup vs baseline: 1.5804x; 1.0220x over previous
#include <cuda_runtime.h>
#include <math.h>

#define TT 256
#define BB 16
#define DD 512
#define NN 4096
#define HRR 256
#define BN_EPS 1e-5f

// ---------------- device scratch ----------------
__device__ float g_gi_r [NN * 768];
__device__ float g_gi_e1[NN * 384];
__device__ float g_gi_e2[NN * 768];
__device__ float g_gi_e3[NN * 1536];
__device__ float g_Hr[NN * HRR];
__device__ float g_H1[NN * 128];
__device__ float g_H2[NN * 256];
__device__ float g_H3[NN * 512];
// replicated tagged exchange: [consumer_cta][parity][j] = (tag<<32)|float_bits
__device__ unsigned long long g_p1[2  * 2 * 128];
__device__ unsigned long long g_p2[8  * 2 * 256];
__device__ unsigned long long g_p3[32 * 2 * 512];
__device__ float g_gates[NN * 4];
__device__ float g_bnA[3][512];
__device__ float g_bnB[3][512];
__device__ float g_tsum[4];
__device__ unsigned g_tcnt[4];

__device__ __forceinline__ float sigf(float x) { return 1.f / (1.f + __expf(-x)); }
__device__ __forceinline__ float tanhfast(float x) {
    float xc = fminf(fmaxf(x, -9.f), 9.f);
    float e = __expf(2.f * xc);
    return __fdividef(e - 1.f, e + 1.f);
}

__device__ __forceinline__ void st_pair_raw(unsigned long long* p, unsigned long long x) {
    asm volatile("st.relaxed.gpu.global.b64 [%0], %1;" :: "l"(p), "l"(x) : "memory");
}
__device__ __forceinline__ unsigned long long ld_pair(const unsigned long long* p) {
    unsigned long long v;
    asm volatile("ld.relaxed.gpu.global.b64 %0, [%1];" : "=l"(v) : "l"(p) : "memory");
    return v;
}

// ---------------- zero pairs / accumulators ----------------
__global__ void k_zero() {
    int i = blockIdx.x * 256 + threadIdx.x;
    if (i < 32 * 2 * 512) g_p3[i] = 0ull;
    if (i < 8 * 2 * 256)  g_p2[i] = 0ull;
    if (i < 2 * 2 * 128)  g_p1[i] = 0ull;
    if (i < 4) { g_tsum[i] = 0.f; g_tcnt[i] = 0u; }
}

// ---------------- merged gi GEMM: all four projections in one launch ----------------
__global__ __launch_bounds__(256) void k_gemm_all(
    const float* __restrict__ A,
    const float* __restrict__ w0, const float* __restrict__ bz0,
    const float* __restrict__ w1, const float* __restrict__ bz1,
    const float* __restrict__ w2, const float* __restrict__ bz2,
    const float* __restrict__ w3, const float* __restrict__ bz3)
{
    int bid = blockIdx.x;
    const float* W; const float* bias; float* C; int Nn, nb;
    if (bid < 768)       { W = w0; bias = bz0; C = g_gi_r;  Nn = 768;  nb = 12; }
    else if (bid < 1152) { bid -= 768;  W = w1; bias = bz1; C = g_gi_e1; Nn = 384;  nb = 6; }
    else if (bid < 1920) { bid -= 1152; W = w2; bias = bz2; C = g_gi_e2; Nn = 768;  nb = 12; }
    else                 { bid -= 1920; W = w3; bias = bz3; C = g_gi_e3; Nn = 1536; nb = 24; }
    const int n0 = (bid % nb) * 64, m0 = (bid / nb) * 64;

    __shared__ float As[64][17];
    __shared__ float Ws[64][17];
    const int tid = threadIdx.x;
    const int tx = tid & 15, ty = tid >> 4;
    const int lr = tid >> 2, lc = (tid & 3) * 4;

    float acc[4][4];
#pragma unroll
    for (int i = 0; i < 4; i++)
#pragma unroll
        for (int j = 0; j < 4; j++) acc[i][j] = 0.f;

    for (int kb = 0; kb < 512; kb += 16) {
        float4 av = *reinterpret_cast<const float4*>(&A[(size_t)(m0 + lr) * 512 + kb + lc]);
        float4 wv = *reinterpret_cast<const float4*>(&W[(size_t)(n0 + lr) * 512 + kb + lc]);
        As[lr][lc + 0] = av.x; As[lr][lc + 1] = av.y; As[lr][lc + 2] = av.z; As[lr][lc + 3] = av.w;
        Ws[lr][lc + 0] = wv.x; Ws[lr][lc + 1] = wv.y; Ws[lr][lc + 2] = wv.z; Ws[lr][lc + 3] = wv.w;
        __syncthreads();
#pragma unroll
        for (int k = 0; k < 16; k++) {
            float a[4], b[4];
#pragma unroll
            for (int i = 0; i < 4; i++) a[i] = As[ty * 4 + i][k];
#pragma unroll
            for (int j = 0; j < 4; j++) b[j] = Ws[tx * 4 + j][k];
#pragma unroll
            for (int i = 0; i < 4; i++)
#pragma unroll
                for (int j = 0; j < 4; j++) acc[i][j] += a[i] * b[j];
        }
        __syncthreads();
    }
#pragma unroll
    for (int i = 0; i < 4; i++)
#pragma unroll
        for (int j = 0; j < 4; j++)
            C[(size_t)(m0 + ty * 4 + i) * Nn + n0 + tx * 4 + j] =
                acc[i][j] + __ldg(&bias[n0 + tx * 4 + j]);
}

// ---------------- expert recurrence: coalesced single-warp publish ----------------
// pbuf layout: [NC][2][H]. After all warps deposit their outputs into smem nxt[],
// warp 0 publishes the CTA's JPC values to every region with COALESCED stores
// (lanes -> consecutive j). Consumer CTA c polls only region c.
template <int H, int NC>
__device__ void expert_recur(int cta,
                             const float* __restrict__ Whh, const float* __restrict__ bhh,
                             const float* __restrict__ gi, float* __restrict__ Hbuf,
                             unsigned long long* __restrict__ pbuf,
                             float* hs0, float* hs1)
{
    constexpr int JPC = H / NC;    // outputs (j) per CTA
    constexpr int JW  = JPC / 16;  // j per warp (16 warps)
    constexpr int KL  = H / 32;    // k elems per lane
    const int tid = threadIdx.x, w = tid >> 5, lane = tid & 31;
    const int jbase = cta * JPC + w * JW;
    const int own_lo = cta * JPC, own_hi = own_lo + JPC;

    float wreg[3][JW][KL];
    float bh[3][JW];
#pragma unroll
    for (int g = 0; g < 3; g++)
#pragma unroll
        for (int jj = 0; jj < JW; jj++) {
            int row = g * H + jbase + jj;
            bh[g][jj] = bhh[row];
#pragma unroll
            for (int kk = 0; kk < KL; kk++)
                wreg[g][jj][kk] = Whh[(size_t)row * H + kk * 32 + lane];
        }

    if (tid < H) { hs0[tid] = 0.f; hs1[tid] = 0.f; }
    __syncthreads();

    float* cur = hs0;
    float* nxt = hs1;

    // preload gi for t=0 (warp-uniform broadcast loads)
    float gr[3][JW];
#pragma unroll
    for (int g = 0; g < 3; g++)
#pragma unroll
        for (int jj = 0; jj < JW; jj++) gr[g][jj] = __ldg(&gi[g * H + jbase + jj]);

    for (int t = 0; t < NN; t++) {
        float acc[3][JW];
#pragma unroll
        for (int g = 0; g < 3; g++)
#pragma unroll
            for (int jj = 0; jj < JW; jj++) acc[g][jj] = 0.f;

#pragma unroll
        for (int kk = 0; kk < KL; kk++) {
            float hv = cur[kk * 32 + lane];
#pragma unroll
            for (int g = 0; g < 3; g++)
#pragma unroll
                for (int jj = 0; jj < JW; jj++) acc[g][jj] += wreg[g][jj][kk] * hv;
        }
#pragma unroll
        for (int g = 0; g < 3; g++)
#pragma unroll
            for (int jj = 0; jj < JW; jj++)
#pragma unroll
                for (int off = 16; off > 0; off >>= 1)
                    acc[g][jj] += __shfl_xor_sync(0xffffffffu, acc[g][jj], off);

        if (lane == 0) {
#pragma unroll
            for (int jj = 0; jj < JW; jj++) {
                int j = jbase + jj;
                float r = sigf(gr[0][jj] + acc[0][jj] + bh[0][jj]);
                float z = sigf(gr[1][jj] + acc[1][jj] + bh[1][jj]);
                float n = tanhfast(gr[2][jj] + r * (acc[2][jj] + bh[2][jj]));
                float hn = (1.f - z) * n + z * cur[j];
                nxt[j] = hn;
                Hbuf[(size_t)t * H + j] = hn;
            }
        }
        // prefetch gi for t+1 (hidden under the exchange; warp-uniform)
        {
            int tn = (t + 1 < NN) ? t + 1 : t;
            const float* gin = gi + (size_t)tn * 3 * H;
#pragma unroll
            for (int g = 0; g < 3; g++)
#pragma unroll
                for (int jj = 0; jj < JW; jj++) gr[g][jj] = __ldg(&gin[g * H + jbase + jj]);
        }
        __syncthreads();   // bar A: all own outputs staged in nxt[own_lo..own_hi)
        const int par = t & 1;
        if (w == 0) {
            // single-warp coalesced publish: lanes -> consecutive j, per region
#pragma unroll
            for (int idx = lane; idx < JPC; idx += 32) {
                float v = nxt[own_lo + idx];
                unsigned long long x =
                    ((unsigned long long)(unsigned)(t + 1) << 32) |
                    (unsigned long long)__float_as_uint(v);
#pragma unroll
                for (int r = 0; r < NC; r++)
                    st_pair_raw(&pbuf[((size_t)r * 2 + par) * H + own_lo + idx], x);
            }
        }
        // consumers: poll ONLY this CTA's private region
        if (tid < H && (tid < own_lo || tid >= own_hi)) {
            const unsigned long long* reg = pbuf + ((size_t)cta * 2 + par) * H;
            unsigned long long v;
            do { v = ld_pair(&reg[tid]); } while ((unsigned)(v >> 32) != (unsigned)(t + 1));
            nxt[tid] = __uint_as_float((unsigned)v);
        }
        __syncthreads();   // bar B
        float* tmp = cur; cur = nxt; nxt = tmp;
    }
}

// ---------------- router recurrence: one CTA per batch item, L2-streamed weights ----------------
__device__ void router_recur(int b, const float* __restrict__ Whh, const float* __restrict__ bhh,
                             float* cur, float* nxt)
{
    const int tid = threadIdx.x, w = tid >> 5, lane = tid & 31;
    const int j0 = w * 16;
    if (tid < HRR) { cur[tid] = 0.f; }
    __syncthreads();

    for (int t = 0; t < TT; t++) {
        const int n = t * BB + b;
        const float* git = g_gi_r + (size_t)n * 768;
        float4 h1 = *reinterpret_cast<const float4*>(cur + lane * 4);
        float4 h2 = *reinterpret_cast<const float4*>(cur + 128 + lane * 4);
#pragma unroll 2
        for (int jj = 0; jj < 16; jj++) {
            int j = j0 + jj;
            const float4* r0 = reinterpret_cast<const float4*>(Whh + (size_t)j * HRR);
            const float4* r1 = reinterpret_cast<const float4*>(Whh + (size_t)(j + 256) * HRR);
            const float4* r2 = reinterpret_cast<const float4*>(Whh + (size_t)(j + 512) * HRR);
            float4 a = __ldg(r0 + lane), c = __ldg(r0 + 32 + lane);
            float s0 = a.x * h1.x + a.y * h1.y + a.z * h1.z + a.w * h1.w
                     + c.x * h2.x + c.y * h2.y + c.z * h2.z + c.w * h2.w;
            a = __ldg(r1 + lane); c = __ldg(r1 + 32 + lane);
            float s1 = a.x * h1.x + a.y * h1.y + a.z * h1.z + a.w * h1.w
                     + c.x * h2.x + c.y * h2.y + c.z * h2.z + c.w * h2.w;
            a = __ldg(r2 + lane); c = __ldg(r2 + 32 + lane);
            float s2 = a.x * h1.x + a.y * h1.y + a.z * h1.z + a.w * h1.w
                     + c.x * h2.x + c.y * h2.y + c.z * h2.z + c.w * h2.w;
#pragma unroll
            for (int off = 16; off > 0; off >>= 1) {
                s0 += __shfl_xor_sync(0xffffffffu, s0, off);
                s1 += __shfl_xor_sync(0xffffffffu, s1, off);
                s2 += __shfl_xor_sync(0xffffffffu, s2, off);
            }
            if (lane == 0) {
                float r = sigf(__ldg(&git[j]) + s0 + __ldg(&bhh[j]));
                float z = sigf(__ldg(&git[256 + j]) + s1 + __ldg(&bhh[256 + j]));
                float nn2 = tanhfast(__ldg(&git[512 + j]) + r * (s2 + __ldg(&bhh[512 + j])));
                float hn = (1.f - z) * nn2 + z * cur[j];
                nxt[j] = hn;
                g_Hr[(size_t)n * HRR + j] = hn;
            }
        }
        __syncthreads();
        float* tmp = cur; cur = nxt; nxt = tmp;
    }
}

// ---------------- fused recurrence kernel: 58 co-resident CTAs ----------------
__global__ __launch_bounds__(512) void k_recur(
    const float* r_whh, const float* r_bhh,
    const float* e1_whh, const float* e1_bhh,
    const float* e2_whh, const float* e2_bhh,
    const float* e3_whh, const float* e3_bhh)
{
    __shared__ float hsm[1152];
    int c = blockIdx.x;
    if (c < 32)      expert_recur<512, 32>(c,     e3_whh, e3_bhh, g_gi_e3, g_H3, g_p3, hsm, hsm + 576);
    else if (c < 40) expert_recur<256, 8>(c - 32, e2_whh, e2_bhh, g_gi_e2, g_H2, g_p2, hsm, hsm + 576);
    else if (c < 42) expert_recur<128, 2>(c - 40, e1_whh, e1_bhh, g_gi_e1, g_H1, g_p1, hsm, hsm + 576);
    else             router_recur(c - 42, r_whh, r_bhh, hsm, hsm + 576);
}

// ---------------- gates: logits -> softmax -> raw, eul, task sums ----------------
__global__ void k_gates(const float* __restrict__ rw, const float* __restrict__ rb,
                        const int* __restrict__ task, float* __restrict__ out_raw)
{
    int warp = (blockIdx.x * blockDim.x + threadIdx.x) >> 5;
    int lane = threadIdx.x & 31;
    if (warp >= NN) return;
    const float* h = g_Hr + (size_t)warp * HRR;
    float hr[8];
#pragma unroll
    for (int i = 0; i < 8; i++) hr[i] = fmaxf(h[i * 32 + lane], 0.f);
    float lg[4];
#pragma unroll
    for (int e = 0; e < 4; e++) {
        float s = 0.f;
#pragma unroll
        for (int i = 0; i < 8; i++) s += __ldg(&rw[e * HRR + i * 32 + lane]) * hr[i];
#pragma unroll
        for (int off = 16; off > 0; off >>= 1) s += __shfl_xor_sync(0xffffffffu, s, off);
        lg[e] = s;
    }
    if (lane == 0) {
#pragma unroll
        for (int e = 0; e < 4; e++) lg[e] += __ldg(&rb[e]);
        float mx = fmaxf(fmaxf(lg[0], lg[1]), fmaxf(lg[2], lg[3]));
        float ex[4], se = 0.f;
#pragma unroll
        for (int e = 0; e < 4; e++) { ex[e] = __expf(lg[e] - mx); se += ex[e]; }
        float inv = 1.f / se;
        float gg[4];
#pragma unroll
        for (int e = 0; e < 4; e++) {
            gg[e] = ex[e] * inv;
            out_raw[warp * 4 + e] = gg[e];
            g_gates[warp * 4 + e] = gg[e];
        }
        float eul = gg[1] * 128.f + gg[2] * 256.f + gg[3] * 512.f;
        int tk = task[warp];
        atomicAdd(&g_tsum[tk], eul);
        atomicAdd(&g_tcnt[tk], 1u);
    }
}

// ---------------- BN stats: per-column mean/var -> affine A,B ----------------
__global__ void k_bn(const float* g1, const float* b1, const float* g2, const float* b2,
                     const float* g3, const float* b3)
{
    int bid = blockIdx.x, tid = threadIdx.x;
    const float* Hb; int H, ei, c;
    if (bid == 0)      { Hb = g_H1; H = 128; ei = 0; c = tid; }
    else if (bid < 3)  { Hb = g_H2; H = 256; ei = 1; c = (bid - 1) * 128 + tid; }
    else               { Hb = g_H3; H = 512; ei = 2; c = (bid - 3) * 128 + tid; }
    float s = 0.f, s2 = 0.f;
#pragma unroll 8
    for (int n = 0; n < NN; n++) {
        float v = __ldg(&Hb[(size_t)n * H + c]);
        s += v; s2 += v * v;
    }
    float mu = s * (1.f / NN);
    float var = s2 * (1.f / NN) - mu * mu;
    const float* gg = (ei == 0) ? g1 : (ei == 1) ? g2 : g3;
    const float* bb = (ei == 0) ? b1 : (ei == 1) ? b2 : b3;
    float A = gg[c] * rsqrtf(var + BN_EPS);
    g_bnA[ei][c] = A;
    g_bnB[ei][c] = bb[c] - mu * A;
}

// ---------------- epilogue: out (+)= gate_i * (relu(bn(H_i)) @ ow^T + ob) ----------------
__global__ __launch_bounds__(256) void k_epi(
    const float* __restrict__ ow, const float* __restrict__ ob,
    const float* __restrict__ x, float* __restrict__ out, int ei, int H)
{
    const float* Hb = (ei == 1) ? g_H1 : (ei == 2) ? g_H2 : g_H3;
    const float* bA = g_bnA[ei - 1];
    const float* bBv = g_bnB[ei - 1];
    __shared__ float As[64][17];
    __shared__ float Ws[64][17];
    const int tid = threadIdx.x;
    const int tx = tid & 15, ty = tid >> 4;
    const int m0 = blockIdx.y * 64, n0 = blockIdx.x * 64;
    const int lr = tid >> 2, lc = (tid & 3) * 4;

    float acc[4][4];
#pragma unroll
    for (int i = 0; i < 4; i++)
#pragma unroll
        for (int j = 0; j < 4; j++) acc[i][j] = 0.f;

    for (int kb = 0; kb < H; kb += 16) {
        float4 av = *reinterpret_cast<const float4*>(&Hb[(size_t)(m0 + lr) * H + kb + lc]);
        float4 wv = *reinterpret_cast<const float4*>(&ow[(size_t)(n0 + lr) * H + kb + lc]);
        As[lr][lc + 0] = fmaxf(av.x * __ldg(&bA[kb + lc + 0]) + __ldg(&bBv[kb + lc + 0]), 0.f);
        As[lr][lc + 1] = fmaxf(av.y * __ldg(&bA[kb + lc + 1]) + __ldg(&bBv[kb + lc + 1]), 0.f);
        As[lr][lc + 2] = fmaxf(av.z * __ldg(&bA[kb + lc + 2]) + __ldg(&bBv[kb + lc + 2]), 0.f);
        As[lr][lc + 3] = fmaxf(av.w * __ldg(&bA[kb + lc + 3]) + __ldg(&bBv[kb + lc + 3]), 0.f);
        Ws[lr][lc + 0] = wv.x; Ws[lr][lc + 1] = wv.y; Ws[lr][lc + 2] = wv.z; Ws[lr][lc + 3] = wv.w;
        __syncthreads();
#pragma unroll
        for (int k = 0; k < 16; k++) {
            float a[4], b[4];
#pragma unroll
            for (int i = 0; i < 4; i++) a[i] = As[ty * 4 + i][k];
#pragma unroll
            for (int j = 0; j < 4; j++) b[j] = Ws[tx * 4 + j][k];
#pragma unroll
            for (int i = 0; i < 4; i++)
#pragma unroll
                for (int j = 0; j < 4; j++) acc[i][j] += a[i] * b[j];
        }
        __syncthreads();
    }
#pragma unroll
    for (int i = 0; i < 4; i++) {
        int m = m0 + ty * 4 + i;
        float gate = g_gates[m * 4 + ei];
        float g0 = g_gates[m * 4];
#pragma unroll
        for (int j = 0; j < 4; j++) {
            int n = n0 + tx * 4 + j;
            float v = (acc[i][j] + __ldg(&ob[n])) * gate;
            if (ei == 1) v += g0 * __ldg(&x[(size_t)m * DD + n]);
            else         v += out[(size_t)m * DD + n];
            out[(size_t)m * DD + n] = v;
        }
    }
}

// ---------------- task losses ----------------
__global__ void k_tl(float* o) {
    int i = threadIdx.x;
    if (i < 4) o[i] = g_tsum[i] / (float)g_tcnt[i];
}

// ---------------- launch ----------------
extern "C" void kernel_launch(void* const* d_in, const int* in_sizes, int n_in,
                              void* d_out, int out_size)
{
    const float* x      = (const float*)d_in[0];
    const int*   task   = (const int*)d_in[1];
    const float* r_wih  = (const float*)d_in[2];
    const float* r_whh  = (const float*)d_in[3];
    const float* r_bih  = (const float*)d_in[4];
    const float* r_bhh  = (const float*)d_in[5];
    const float* r_ow   = (const float*)d_in[6];
    const float* r_ob   = (const float*)d_in[7];
    const float* e1_wih = (const float*)d_in[8];
    const float* e1_whh = (const float*)d_in[9];
    const float* e1_bih = (const float*)d_in[10];
    const float* e1_bhh = (const float*)d_in[11];
    const float* e1_bng = (const float*)d_in[12];
    const float* e1_bnb = (const float*)d_in[13];
    const float* e1_ow  = (const float*)d_in[14];
    const float* e1_ob  = (const float*)d_in[15];
    const float* e2_wih = (const float*)d_in[16];
    const float* e2_whh = (const float*)d_in[17];
    const float* e2_bih = (const float*)d_in[18];
    const float* e2_bhh = (const float*)d_in[19];
    const float* e2_bng = (const float*)d_in[20];
    const float* e2_bnb = (const float*)d_in[21];
    const float* e2_ow  = (const float*)d_in[22];
    const float* e2_ob  = (const float*)d_in[23];
    const float* e3_wih = (const float*)d_in[24];
    const float* e3_whh = (const float*)d_in[25];
    const float* e3_bih = (const float*)d_in[26];
    const float* e3_bhh = (const float*)d_in[27];
    const float* e3_bng = (const float*)d_in[28];
    const float* e3_bnb = (const float*)d_in[29];
    const float* e3_ow  = (const float*)d_in[30];
    const float* e3_ob  = (const float*)d_in[31];

    float* out = (float*)d_out;
    float* raw = out + (size_t)NN * DD;
    float* tl  = raw + (size_t)NN * 4;

    k_zero<<<128, 256>>>();
    k_gemm_all<<<3456, 256>>>(x, r_wih, r_bih, e1_wih, e1_bih, e2_wih, e2_bih, e3_wih, e3_bih);
    k_recur<<<58, 512>>>(r_whh, r_bhh, e1_whh, e1_bhh, e2_whh, e2_bhh, e3_whh, e3_bhh);
    k_gates<<<512, 256>>>(r_ow, r_ob, task, raw);
    k_bn<<<7, 128>>>(e1_bng, e1_bnb, e2_bng, e2_bnb, e3_bng, e3_bnb);
    k_epi<<<dim3(8, 64), 256>>>(e1_ow, e1_ob, x, out, 1, 128);
    k_epi<<<dim3(8, 64), 256>>>(e2_ow, e2_ob, x, out, 2, 256);
    k_epi<<<dim3(8, 64), 256>>>(e3_ow, e3_ob, x, out, 3, 512);
    k_tl<<<1, 32>>>(tl);
}

// round 11
// speedup vs baseline: 1.7253x; 1.0917x over previous
#include <cuda_runtime.h>
#include <stdint.h>
#include <math.h>

#define TT 256
#define BB 16
#define DD 512
#define NN 4096
#define HRR 256
#define BN_EPS 1e-5f

// ---------------- device scratch ----------------
__device__ float g_gi_r [NN * 768];
__device__ float g_gi_e1[NN * 384];
__device__ float g_gi_e2[NN * 768];
__device__ float g_gi_e3[NN * 1536];
__device__ float g_Hr[NN * HRR];
__device__ float g_H1[NN * 128];
__device__ float g_H2[NN * 256];
__device__ float g_H3[NN * 512];
__device__ float g_gates[NN * 4];
__device__ float g_bnA[3][512];
__device__ float g_bnB[3][512];
__device__ float g_tsum[4];
__device__ unsigned g_tcnt[4];

__device__ __forceinline__ float sigf(float x) { return 1.f / (1.f + __expf(-x)); }
__device__ __forceinline__ float tanhfast(float x) {
    float xc = fminf(fmaxf(x, -9.f), 9.f);
    float e = __expf(2.f * xc);
    return __fdividef(e - 1.f, e + 1.f);
}

// DSMEM publish: map local smem byte-addr into peer CTA rank, store 8B {tag,val}
__device__ __forceinline__ void st_pair_cluster(uint32_t laddr, int rank, unsigned long long x) {
    uint32_t ra;
    asm volatile("mapa.shared::cluster.u32 %0, %1, %2;" : "=r"(ra) : "r"(laddr), "r"(rank));
    asm volatile("st.shared::cluster.b64 [%0], %1;" :: "r"(ra), "l"(x) : "memory");
}
__device__ __forceinline__ unsigned long long ld_pair_sh(uint32_t laddr) {
    unsigned long long v;
    asm volatile("ld.volatile.shared.b64 %0, [%1];" : "=l"(v) : "r"(laddr));
    return v;
}
#define CLUSTER_SYNC() do { \
    asm volatile("barrier.cluster.arrive.aligned;" ::: "memory"); \
    asm volatile("barrier.cluster.wait.aligned;" ::: "memory"); } while (0)

// ---------------- zero accumulators ----------------
__global__ void k_zero() {
    int i = threadIdx.x;
    if (i < 4) { g_tsum[i] = 0.f; g_tcnt[i] = 0u; }
}

// ---------------- merged gi GEMM (r/z hidden biases folded in) ----------------
// C[4096 x Nn] = x @ W^T + bih  (+ bhh on rows < 2H: the r,z gates)
__global__ __launch_bounds__(256) void k_gemm_all(
    const float* __restrict__ A,
    const float* __restrict__ w0, const float* __restrict__ bz0, const float* __restrict__ hh0,
    const float* __restrict__ w1, const float* __restrict__ bz1, const float* __restrict__ hh1,
    const float* __restrict__ w2, const float* __restrict__ bz2, const float* __restrict__ hh2,
    const float* __restrict__ w3, const float* __restrict__ bz3, const float* __restrict__ hh3)
{
    int bid = blockIdx.x;
    const float* W; const float* bias; const float* bhh; float* C; int Nn, nb, twoH;
    if (bid < 768)       { W = w0; bias = bz0; bhh = hh0; C = g_gi_r;  Nn = 768;  nb = 12; twoH = 512; }
    else if (bid < 1152) { bid -= 768;  W = w1; bias = bz1; bhh = hh1; C = g_gi_e1; Nn = 384;  nb = 6;  twoH = 256; }
    else if (bid < 1920) { bid -= 1152; W = w2; bias = bz2; bhh = hh2; C = g_gi_e2; Nn = 768;  nb = 12; twoH = 512; }
    else                 { bid -= 1920; W = w3; bias = bz3; bhh = hh3; C = g_gi_e3; Nn = 1536; nb = 24; twoH = 1024; }
    const int n0 = (bid % nb) * 64, m0 = (bid / nb) * 64;

    __shared__ float As[64][17];
    __shared__ float Ws[64][17];
    const int tid = threadIdx.x;
    const int tx = tid & 15, ty = tid >> 4;
    const int lr = tid >> 2, lc = (tid & 3) * 4;

    float acc[4][4];
#pragma unroll
    for (int i = 0; i < 4; i++)
#pragma unroll
        for (int j = 0; j < 4; j++) acc[i][j] = 0.f;

    for (int kb = 0; kb < 512; kb += 16) {
        float4 av = *reinterpret_cast<const float4*>(&A[(size_t)(m0 + lr) * 512 + kb + lc]);
        float4 wv = *reinterpret_cast<const float4*>(&W[(size_t)(n0 + lr) * 512 + kb + lc]);
        As[lr][lc + 0] = av.x; As[lr][lc + 1] = av.y; As[lr][lc + 2] = av.z; As[lr][lc + 3] = av.w;
        Ws[lr][lc + 0] = wv.x; Ws[lr][lc + 1] = wv.y; Ws[lr][lc + 2] = wv.z; Ws[lr][lc + 3] = wv.w;
        __syncthreads();
#pragma unroll
        for (int k = 0; k < 16; k++) {
            float a[4], b[4];
#pragma unroll
            for (int i = 0; i < 4; i++) a[i] = As[ty * 4 + i][k];
#pragma unroll
            for (int j = 0; j < 4; j++) b[j] = Ws[tx * 4 + j][k];
#pragma unroll
            for (int i = 0; i < 4; i++)
#pragma unroll
                for (int j = 0; j < 4; j++) acc[i][j] += a[i] * b[j];
        }
        __syncthreads();
    }
#pragma unroll
    for (int i = 0; i < 4; i++)
#pragma unroll
        for (int j = 0; j < 4; j++) {
            int nidx = n0 + tx * 4 + j;
            float b = __ldg(&bias[nidx]);
            if (nidx < twoH) b += __ldg(&bhh[nidx]);
            C[(size_t)(m0 + ty * 4 + i) * Nn + nidx] = acc[i][j] + b;
        }
}

// ---------------- expert recurrence: DSMEM tagged exchange within one cluster ----------------
template <int H, int NC>
__device__ void expert_recur(int cta, int base_rank,
                             const float* __restrict__ Whh, const float* __restrict__ bhh,
                             const float* __restrict__ gi, float* __restrict__ Hbuf,
                             uint32_t pairs_addr, float* hs0, float* hs1)
{
    constexpr int JPC = H / NC;    // outputs per CTA
    constexpr int JW  = JPC / 16;  // outputs per warp
    constexpr int KL  = H / 32;    // k elems per lane
    const int tid = threadIdx.x, w = tid >> 5, lane = tid & 31;
    const int jbase = cta * JPC + w * JW;
    const int own_lo = cta * JPC;

    float wreg[3][JW][KL];
    float bhn[JW];
#pragma unroll
    for (int g = 0; g < 3; g++)
#pragma unroll
        for (int jj = 0; jj < JW; jj++) {
            int row = g * H + jbase + jj;
#pragma unroll
            for (int kk = 0; kk < KL; kk++)
                wreg[g][jj][kk] = Whh[(size_t)row * H + kk * 32 + lane];
        }
#pragma unroll
    for (int jj = 0; jj < JW; jj++)
        bhn[jj] = bhh[2 * H + jbase + jj];   // only n-gate bias stays (r,z folded into gi)

    float* cur = hs0;
    float* nxt = hs1;

    // preload gi for t=0 (warp-uniform broadcast loads)
    float gr[3][JW];
#pragma unroll
    for (int g = 0; g < 3; g++)
#pragma unroll
        for (int jj = 0; jj < JW; jj++) gr[g][jj] = __ldg(&gi[g * H + jbase + jj]);

    for (int t = 0; t < NN; t++) {
        float acc[3][JW];
#pragma unroll
        for (int g = 0; g < 3; g++)
#pragma unroll
            for (int jj = 0; jj < JW; jj++) acc[g][jj] = 0.f;

#pragma unroll
        for (int kk = 0; kk < KL; kk++) {
            float hv = cur[kk * 32 + lane];
#pragma unroll
            for (int g = 0; g < 3; g++)
#pragma unroll
                for (int jj = 0; jj < JW; jj++) acc[g][jj] += wreg[g][jj][kk] * hv;
        }
#pragma unroll
        for (int g = 0; g < 3; g++)
#pragma unroll
            for (int jj = 0; jj < JW; jj++)
#pragma unroll
                for (int off = 16; off > 0; off >>= 1)
                    acc[g][jj] += __shfl_xor_sync(0xffffffffu, acc[g][jj], off);

        if (lane == 0) {
#pragma unroll
            for (int jj = 0; jj < JW; jj++) {
                int j = jbase + jj;
                float r = sigf(gr[0][jj] + acc[0][jj]);
                float z = sigf(gr[1][jj] + acc[1][jj]);
                float n = tanhfast(gr[2][jj] + r * (acc[2][jj] + bhn[jj]));
                float hn = (1.f - z) * n + z * cur[j];
                nxt[j] = hn;
                Hbuf[(size_t)t * H + j] = hn;
            }
        }
        // prefetch gi for t+1 (hidden under the exchange; warp-uniform)
        {
            int tn = (t + 1 < NN) ? t + 1 : t;
            const float* gin = gi + (size_t)tn * 3 * H;
#pragma unroll
            for (int g = 0; g < 3; g++)
#pragma unroll
                for (int jj = 0; jj < JW; jj++) gr[g][jj] = __ldg(&gin[g * H + jbase + jj]);
        }
        __syncthreads();   // bar A: own outputs staged in nxt[own_lo..own_lo+JPC)
        const int par = t & 1;
        if (w == 0) {
            // warp0 publishes this CTA's slice into EVERY cluster peer's pair ring (incl. self)
#pragma unroll
            for (int idx = lane; idx < JPC; idx += 32) {
                float v = nxt[own_lo + idx];
                unsigned long long x =
                    ((unsigned long long)(unsigned)(t + 1) << 32) |
                    (unsigned long long)__float_as_uint(v);
                uint32_t la = pairs_addr + (uint32_t)((par * H + own_lo + idx) * 8);
#pragma unroll
                for (int r = 0; r < NC; r++)
                    st_pair_cluster(la, base_rank + r, x);
            }
        }
        // all threads spin on LOCAL smem tags (value+tag in one 8B word)
        if (tid < H) {
            uint32_t la = pairs_addr + (uint32_t)((par * H + tid) * 8);
            unsigned long long v;
            do { v = ld_pair_sh(la); } while ((unsigned)(v >> 32) != (unsigned)(t + 1));
            nxt[tid] = __uint_as_float((unsigned)v);
        }
        __syncthreads();   // bar B
        float* tmp = cur; cur = nxt; nxt = tmp;
    }
}

// ---------------- router recurrence (r/z biases folded into gi) ----------------
__device__ void router_recur(int b, const float* __restrict__ Whh, const float* __restrict__ bhh,
                             float* cur, float* nxt)
{
    const int tid = threadIdx.x, w = tid >> 5, lane = tid & 31;
    const int j0 = w * 16;
    __syncthreads();

    for (int t = 0; t < TT; t++) {
        const int n = t * BB + b;
        const float* git = g_gi_r + (size_t)n * 768;
        float4 h1 = *reinterpret_cast<const float4*>(cur + lane * 4);
        float4 h2 = *reinterpret_cast<const float4*>(cur + 128 + lane * 4);
#pragma unroll 2
        for (int jj = 0; jj < 16; jj++) {
            int j = j0 + jj;
            const float4* r0 = reinterpret_cast<const float4*>(Whh + (size_t)j * HRR);
            const float4* r1 = reinterpret_cast<const float4*>(Whh + (size_t)(j + 256) * HRR);
            const float4* r2 = reinterpret_cast<const float4*>(Whh + (size_t)(j + 512) * HRR);
            float4 a = __ldg(r0 + lane), c = __ldg(r0 + 32 + lane);
            float s0 = a.x * h1.x + a.y * h1.y + a.z * h1.z + a.w * h1.w
                     + c.x * h2.x + c.y * h2.y + c.z * h2.z + c.w * h2.w;
            a = __ldg(r1 + lane); c = __ldg(r1 + 32 + lane);
            float s1 = a.x * h1.x + a.y * h1.y + a.z * h1.z + a.w * h1.w
                     + c.x * h2.x + c.y * h2.y + c.z * h2.z + c.w * h2.w;
            a = __ldg(r2 + lane); c = __ldg(r2 + 32 + lane);
            float s2 = a.x * h1.x + a.y * h1.y + a.z * h1.z + a.w * h1.w
                     + c.x * h2.x + c.y * h2.y + c.z * h2.z + c.w * h2.w;
#pragma unroll
            for (int off = 16; off > 0; off >>= 1) {
                s0 += __shfl_xor_sync(0xffffffffu, s0, off);
                s1 += __shfl_xor_sync(0xffffffffu, s1, off);
                s2 += __shfl_xor_sync(0xffffffffu, s2, off);
            }
            if (lane == 0) {
                float r = sigf(__ldg(&git[j]) + s0);
                float z = sigf(__ldg(&git[256 + j]) + s1);
                float nn2 = tanhfast(__ldg(&git[512 + j]) + r * (s2 + __ldg(&bhh[512 + j])));
                float hn = (1.f - z) * nn2 + z * cur[j];
                nxt[j] = hn;
                g_Hr[(size_t)n * HRR + j] = hn;
            }
        }
        __syncthreads();
        float* tmp = cur; cur = nxt; nxt = tmp;
    }
}

// ---------------- fused recurrence kernel: 3 clusters of 16 CTAs ----------------
// cluster 0: e3 (16 CTAs). cluster 1: e2 (ranks 0-7), e1 (8-9), router b=0..5 (10-15).
// cluster 2: router b=6..15 (ranks 0-9), ranks 10-15 idle until final sync.
__global__ __launch_bounds__(512) void k_recur(
    const float* r_whh, const float* r_bhh,
    const float* e1_whh, const float* e1_bhh,
    const float* e2_whh, const float* e2_bhh,
    const float* e3_whh, const float* e3_bhh)
{
    __shared__ unsigned long long pairs[1024];   // [parity][H] value+tag rings
    __shared__ float hsm[1152];
    const int tid = threadIdx.x;
    for (int i = tid; i < 1024; i += 512) pairs[i] = 0ull;
    for (int i = tid; i < 1152; i += 512) hsm[i] = 0.f;
    __syncthreads();
    uint32_t paddr = (uint32_t)__cvta_generic_to_shared(pairs);
    const int cid = blockIdx.x >> 4;
    const int rank = blockIdx.x & 15;

    if (cid < 2) CLUSTER_SYNC();   // pair rings zeroed cluster-wide before any peer store

    if (cid == 0) {
        expert_recur<512, 16>(rank, 0, e3_whh, e3_bhh, g_gi_e3, g_H3, paddr, hsm, hsm + 576);
    } else if (cid == 1) {
        if (rank < 8)       expert_recur<256, 8>(rank, 0, e2_whh, e2_bhh, g_gi_e2, g_H2, paddr, hsm, hsm + 576);
        else if (rank < 10) expert_recur<128, 2>(rank - 8, 8, e1_whh, e1_bhh, g_gi_e1, g_H1, paddr, hsm, hsm + 576);
        else                router_recur(rank - 10, r_whh, r_bhh, hsm, hsm + 576);
    } else {
        if (rank < 10)      router_recur(6 + rank, r_whh, r_bhh, hsm, hsm + 576);
    }

    if (cid < 2) CLUSTER_SYNC();   // no CTA exits while peers may still store into it
}

// ---------------- gates: logits -> softmax -> raw, eul, task sums ----------------
__global__ void k_gates(const float* __restrict__ rw, const float* __restrict__ rb,
                        const int* __restrict__ task, float* __restrict__ out_raw)
{
    int warp = (blockIdx.x * blockDim.x + threadIdx.x) >> 5;
    int lane = threadIdx.x & 31;
    if (warp >= NN) return;
    const float* h = g_Hr + (size_t)warp * HRR;
    float hr[8];
#pragma unroll
    for (int i = 0; i < 8; i++) hr[i] = fmaxf(h[i * 32 + lane], 0.f);
    float lg[4];
#pragma unroll
    for (int e = 0; e < 4; e++) {
        float s = 0.f;
#pragma unroll
        for (int i = 0; i < 8; i++) s += __ldg(&rw[e * HRR + i * 32 + lane]) * hr[i];
#pragma unroll
        for (int off = 16; off > 0; off >>= 1) s += __shfl_xor_sync(0xffffffffu, s, off);
        lg[e] = s;
    }
    if (lane == 0) {
#pragma unroll
        for (int e = 0; e < 4; e++) lg[e] += __ldg(&rb[e]);
        float mx = fmaxf(fmaxf(lg[0], lg[1]), fmaxf(lg[2], lg[3]));
        float ex[4], se = 0.f;
#pragma unroll
        for (int e = 0; e < 4; e++) { ex[e] = __expf(lg[e] - mx); se += ex[e]; }
        float inv = 1.f / se;
        float gg[4];
#pragma unroll
        for (int e = 0; e < 4; e++) {
            gg[e] = ex[e] * inv;
            out_raw[warp * 4 + e] = gg[e];
            g_gates[warp * 4 + e] = gg[e];
        }
        float eul = gg[1] * 128.f + gg[2] * 256.f + gg[3] * 512.f;
        int tk = task[warp];
        atomicAdd(&g_tsum[tk], eul);
        atomicAdd(&g_tcnt[tk], 1u);
    }
}

// ---------------- BN stats ----------------
__global__ void k_bn(const float* g1, const float* b1, const float* g2, const float* b2,
                     const float* g3, const float* b3)
{
    int bid = blockIdx.x, tid = threadIdx.x;
    const float* Hb; int H, ei, c;
    if (bid == 0)      { Hb = g_H1; H = 128; ei = 0; c = tid; }
    else if (bid < 3)  { Hb = g_H2; H = 256; ei = 1; c = (bid - 1) * 128 + tid; }
    else               { Hb = g_H3; H = 512; ei = 2; c = (bid - 3) * 128 + tid; }
    float s = 0.f, s2 = 0.f;
#pragma unroll 8
    for (int n = 0; n < NN; n++) {
        float v = __ldg(&Hb[(size_t)n * H + c]);
        s += v; s2 += v * v;
    }
    float mu = s * (1.f / NN);
    float var = s2 * (1.f / NN) - mu * mu;
    const float* gg = (ei == 0) ? g1 : (ei == 1) ? g2 : g3;
    const float* bb = (ei == 0) ? b1 : (ei == 1) ? b2 : b3;
    float A = gg[c] * rsqrtf(var + BN_EPS);
    g_bnA[ei][c] = A;
    g_bnB[ei][c] = bb[c] - mu * A;
}

// ---------------- epilogue ----------------
__global__ __launch_bounds__(256) void k_epi(
    const float* __restrict__ ow, const float* __restrict__ ob,
    const float* __restrict__ x, float* __restrict__ out, int ei, int H)
{
    const float* Hb = (ei == 1) ? g_H1 : (ei == 2) ? g_H2 : g_H3;
    const float* bA = g_bnA[ei - 1];
    const float* bBv = g_bnB[ei - 1];
    __shared__ float As[64][17];
    __shared__ float Ws[64][17];
    const int tid = threadIdx.x;
    const int tx = tid & 15, ty = tid >> 4;
    const int m0 = blockIdx.y * 64, n0 = blockIdx.x * 64;
    const int lr = tid >> 2, lc = (tid & 3) * 4;

    float acc[4][4];
#pragma unroll
    for (int i = 0; i < 4; i++)
#pragma unroll
        for (int j = 0; j < 4; j++) acc[i][j] = 0.f;

    for (int kb = 0; kb < H; kb += 16) {
        float4 av = *reinterpret_cast<const float4*>(&Hb[(size_t)(m0 + lr) * H + kb + lc]);
        float4 wv = *reinterpret_cast<const float4*>(&ow[(size_t)(n0 + lr) * H + kb + lc]);
        As[lr][lc + 0] = fmaxf(av.x * __ldg(&bA[kb + lc + 0]) + __ldg(&bBv[kb + lc + 0]), 0.f);
        As[lr][lc + 1] = fmaxf(av.y * __ldg(&bA[kb + lc + 1]) + __ldg(&bBv[kb + lc + 1]), 0.f);
        As[lr][lc + 2] = fmaxf(av.z * __ldg(&bA[kb + lc + 2]) + __ldg(&bBv[kb + lc + 2]), 0.f);
        As[lr][lc + 3] = fmaxf(av.w * __ldg(&bA[kb + lc + 3]) + __ldg(&bBv[kb + lc + 3]), 0.f);
        Ws[lr][lc + 0] = wv.x; Ws[lr][lc + 1] = wv.y; Ws[lr][lc + 2] = wv.z; Ws[lr][lc + 3] = wv.w;
        __syncthreads();
#pragma unroll
        for (int k = 0; k < 16; k++) {
            float a[4], b[4];
#pragma unroll
            for (int i = 0; i < 4; i++) a[i] = As[ty * 4 + i][k];
#pragma unroll
            for (int j = 0; j < 4; j++) b[j] = Ws[tx * 4 + j][k];
#pragma unroll
            for (int i = 0; i < 4; i++)
#pragma unroll
                for (int j = 0; j < 4; j++) acc[i][j] += a[i] * b[j];
        }
        __syncthreads();
    }
#pragma unroll
    for (int i = 0; i < 4; i++) {
        int m = m0 + ty * 4 + i;
        float gate = g_gates[m * 4 + ei];
        float g0 = g_gates[m * 4];
#pragma unroll
        for (int j = 0; j < 4; j++) {
            int n = n0 + tx * 4 + j;
            float v = (acc[i][j] + __ldg(&ob[n])) * gate;
            if (ei == 1) v += g0 * __ldg(&x[(size_t)m * DD + n]);
            else         v += out[(size_t)m * DD + n];
            out[(size_t)m * DD + n] = v;
        }
    }
}

// ---------------- task losses ----------------
__global__ void k_tl(float* o) {
    int i = threadIdx.x;
    if (i < 4) o[i] = g_tsum[i] / (float)g_tcnt[i];
}

// ---------------- launch ----------------
extern "C" void kernel_launch(void* const* d_in, const int* in_sizes, int n_in,
                              void* d_out, int out_size)
{
    const float* x      = (const float*)d_in[0];
    const int*   task   = (const int*)d_in[1];
    const float* r_wih  = (const float*)d_in[2];
    const float* r_whh  = (const float*)d_in[3];
    const float* r_bih  = (const float*)d_in[4];
    const float* r_bhh  = (const float*)d_in[5];
    const float* r_ow   = (const float*)d_in[6];
    const float* r_ob   = (const float*)d_in[7];
    const float* e1_wih = (const float*)d_in[8];
    const float* e1_whh = (const float*)d_in[9];
    const float* e1_bih = (const float*)d_in[10];
    const float* e1_bhh = (const float*)d_in[11];
    const float* e1_bng = (const float*)d_in[12];
    const float* e1_bnb = (const float*)d_in[13];
    const float* e1_ow  = (const float*)d_in[14];
    const float* e1_ob  = (const float*)d_in[15];
    const float* e2_wih = (const float*)d_in[16];
    const float* e2_whh = (const float*)d_in[17];
    const float* e2_bih = (const float*)d_in[18];
    const float* e2_bhh = (const float*)d_in[19];
    const float* e2_bng = (const float*)d_in[20];
    const float* e2_bnb = (const float*)d_in[21];
    const float* e2_ow  = (const float*)d_in[22];
    const float* e2_ob  = (const float*)d_in[23];
    const float* e3_wih = (const float*)d_in[24];
    const float* e3_whh = (const float*)d_in[25];
    const float* e3_bih = (const float*)d_in[26];
    const float* e3_bhh = (const float*)d_in[27];
    const float* e3_bng = (const float*)d_in[28];
    const float* e3_bnb = (const float*)d_in[29];
    const float* e3_ow  = (const float*)d_in[30];
    const float* e3_ob  = (const float*)d_in[31];

    float* out = (float*)d_out;
    float* raw = out + (size_t)NN * DD;
    float* tl  = raw + (size_t)NN * 4;

    k_zero<<<1, 32>>>();
    k_gemm_all<<<3456, 256>>>(x,
        r_wih, r_bih, r_bhh,
        e1_wih, e1_bih, e1_bhh,
        e2_wih, e2_bih, e2_bhh,
        e3_wih, e3_bih, e3_bhh);

    // k_recur: grid 48 = 3 clusters of 16 (non-portable size), 512 threads
    cudaFuncSetAttribute(k_recur, cudaFuncAttributeNonPortableClusterSizeAllowed, 1);
    cudaLaunchConfig_t cfg = {};
    cfg.gridDim = dim3(48, 1, 1);
    cfg.blockDim = dim3(512, 1, 1);
    cfg.dynamicSmemBytes = 0;
    cfg.stream = 0;
    cudaLaunchAttribute lattr[1];
    lattr[0].id = cudaLaunchAttributeClusterDimension;
    lattr[0].val.clusterDim.x = 16;
    lattr[0].val.clusterDim.y = 1;
    lattr[0].val.clusterDim.z = 1;
    cfg.attrs = lattr;
    cfg.numAttrs = 1;
    cudaLaunchKernelEx(&cfg, k_recur,
                       r_whh, r_bhh, e1_whh, e1_bhh, e2_whh, e2_bhh, e3_whh, e3_bhh);

    k_gates<<<512, 256>>>(r_ow, r_ob, task, raw);
    k_bn<<<7, 128>>>(e1_bng, e1_bnb, e2_bng, e2_bnb, e3_bng, e3_bnb);
    k_epi<<<dim3(8, 64), 256>>>(e1_ow, e1_ob, x, out, 1, 128);
    k_epi<<<dim3(8, 64), 256>>>(e2_ow, e2_ob, x, out, 2, 256);
    k_epi<<<dim3(8, 64), 256>>>(e3_ow, e3_ob, x, out, 3, 512);
    k_tl<<<1, 32>>>(tl);
}

// round 12
// speedup vs baseline: 2.3466x; 1.3602x over previous
#include <cuda_runtime.h>
#include <stdint.h>
#include <math.h>

#define TT 256
#define BB 16
#define DD 512
#define NN 4096
#define HRR 256
#define BN_EPS 1e-5f

// ---------------- device scratch ----------------
__device__ float g_gi_r [NN * 768];
__device__ float g_gi_e1[NN * 384];
__device__ float g_gi_e2[NN * 768];
__device__ float g_gi_e3[NN * 1536];
__device__ float g_Hr[NN * HRR];
__device__ float g_H1[NN * 128];
__device__ float g_H2[NN * 256];
__device__ float g_H3[NN * 512];
__device__ float g_gates[NN * 4];
__device__ float g_bnA[3][512];
__device__ float g_bnB[3][512];
__device__ float g_tsum[4];
__device__ unsigned g_tcnt[4];

__device__ __forceinline__ float sigf(float x) { return 1.f / (1.f + __expf(-x)); }
__device__ __forceinline__ float tanhfast(float x) {
    float xc = fminf(fmaxf(x, -9.f), 9.f);
    float e = __expf(2.f * xc);
    return __fdividef(e - 1.f, e + 1.f);
}
__device__ __forceinline__ unsigned long long fma2(unsigned long long a, unsigned long long b,
                                                   unsigned long long c) {
    unsigned long long d;
    asm("fma.rn.f32x2 %0, %1, %2, %3;" : "=l"(d) : "l"(a), "l"(b), "l"(c));
    return d;
}
__device__ __forceinline__ int padi(int k) { return k + ((k >> 5) << 1); }  // bank-pad

// DSMEM publish: map local smem byte-addr into peer CTA rank, store 8B {tag,val}
__device__ __forceinline__ void st_pair_cluster(uint32_t laddr, int rank, unsigned long long x) {
    uint32_t ra;
    asm volatile("mapa.shared::cluster.u32 %0, %1, %2;" : "=r"(ra) : "r"(laddr), "r"(rank));
    asm volatile("st.shared::cluster.b64 [%0], %1;" :: "r"(ra), "l"(x) : "memory");
}
__device__ __forceinline__ unsigned long long ld_pair_sh(uint32_t laddr) {
    unsigned long long v;
    asm volatile("ld.volatile.shared.b64 %0, [%1];" : "=l"(v) : "r"(laddr));
    return v;
}
#define CLUSTER_SYNC() do { \
    asm volatile("barrier.cluster.arrive.aligned;" ::: "memory"); \
    asm volatile("barrier.cluster.wait.aligned;" ::: "memory"); } while (0)

// ---------------- zero accumulators ----------------
__global__ void k_zero() {
    int i = threadIdx.x;
    if (i < 4) { g_tsum[i] = 0.f; g_tcnt[i] = 0u; }
}

// ---------------- merged gi GEMM (r/z hidden biases folded in) ----------------
__global__ __launch_bounds__(256) void k_gemm_all(
    const float* __restrict__ A,
    const float* __restrict__ w0, const float* __restrict__ bz0, const float* __restrict__ hh0,
    const float* __restrict__ w1, const float* __restrict__ bz1, const float* __restrict__ hh1,
    const float* __restrict__ w2, const float* __restrict__ bz2, const float* __restrict__ hh2,
    const float* __restrict__ w3, const float* __restrict__ bz3, const float* __restrict__ hh3)
{
    int bid = blockIdx.x;
    const float* W; const float* bias; const float* bhh; float* C; int Nn, nb, twoH;
    if (bid < 768)       { W = w0; bias = bz0; bhh = hh0; C = g_gi_r;  Nn = 768;  nb = 12; twoH = 512; }
    else if (bid < 1152) { bid -= 768;  W = w1; bias = bz1; bhh = hh1; C = g_gi_e1; Nn = 384;  nb = 6;  twoH = 256; }
    else if (bid < 1920) { bid -= 1152; W = w2; bias = bz2; bhh = hh2; C = g_gi_e2; Nn = 768;  nb = 12; twoH = 512; }
    else                 { bid -= 1920; W = w3; bias = bz3; bhh = hh3; C = g_gi_e3; Nn = 1536; nb = 24; twoH = 1024; }
    const int n0 = (bid % nb) * 64, m0 = (bid / nb) * 64;

    __shared__ float As[64][17];
    __shared__ float Ws[64][17];
    const int tid = threadIdx.x;
    const int tx = tid & 15, ty = tid >> 4;
    const int lr = tid >> 2, lc = (tid & 3) * 4;

    float acc[4][4];
#pragma unroll
    for (int i = 0; i < 4; i++)
#pragma unroll
        for (int j = 0; j < 4; j++) acc[i][j] = 0.f;

    for (int kb = 0; kb < 512; kb += 16) {
        float4 av = *reinterpret_cast<const float4*>(&A[(size_t)(m0 + lr) * 512 + kb + lc]);
        float4 wv = *reinterpret_cast<const float4*>(&W[(size_t)(n0 + lr) * 512 + kb + lc]);
        As[lr][lc + 0] = av.x; As[lr][lc + 1] = av.y; As[lr][lc + 2] = av.z; As[lr][lc + 3] = av.w;
        Ws[lr][lc + 0] = wv.x; Ws[lr][lc + 1] = wv.y; Ws[lr][lc + 2] = wv.z; Ws[lr][lc + 3] = wv.w;
        __syncthreads();
#pragma unroll
        for (int k = 0; k < 16; k++) {
            float a[4], b[4];
#pragma unroll
            for (int i = 0; i < 4; i++) a[i] = As[ty * 4 + i][k];
#pragma unroll
            for (int j = 0; j < 4; j++) b[j] = Ws[tx * 4 + j][k];
#pragma unroll
            for (int i = 0; i < 4; i++)
#pragma unroll
                for (int j = 0; j < 4; j++) acc[i][j] += a[i] * b[j];
        }
        __syncthreads();
    }
#pragma unroll
    for (int i = 0; i < 4; i++)
#pragma unroll
        for (int j = 0; j < 4; j++) {
            int nidx = n0 + tx * 4 + j;
            float b = __ldg(&bias[nidx]);
            if (nidx < twoH) b += __ldg(&bhh[nidx]);
            C[(size_t)(m0 + ty * 4 + i) * Nn + nidx] = acc[i][j] + b;
        }
}

// ---------------- expert recurrence: f32x2 matvec + lane-group publish, 1 bar/step ----------------
// JW outputs per warp, LPJ=32/JW lanes per output. Each lane: blocked KB=H/LPJ k-range
// as KP=KB/2 f32x2 pairs; butterfly within the LPJ-lane group leaves sums in all lanes;
// lane linj<NC publishes its group's j directly to rank base+linj (one DSMEM store/warp).
template <int H, int NC, int JW>
__device__ void expert_recur(int cta, int base_rank,
                             const float* __restrict__ Whh, const float* __restrict__ bhh,
                             const float* __restrict__ gi, float* __restrict__ Hbuf,
                             uint32_t pairs_addr, float* hs0, float* hs1)
{
    constexpr int JPC = H / NC;
    constexpr int LPJ = 32 / JW;
    constexpr int KB  = H / LPJ;   // scalars per lane (blocked)
    constexpr int KP  = KB / 2;    // f32x2 pairs per lane
    const int tid = threadIdx.x, w = tid >> 5, lane = tid & 31;
    const int jj   = lane / LPJ;
    const int linj = lane % LPJ;
    const int j    = cta * JPC + w * JW + jj;
    const int k0   = linj * KB;
    const int pb   = padi(k0);     // padded smem base for this lane's h block

    unsigned long long wp[3][KP];
#pragma unroll
    for (int g = 0; g < 3; g++)
#pragma unroll
        for (int p = 0; p < KP; p++)
            wp[g][p] = *reinterpret_cast<const unsigned long long*>(
                &Whh[(size_t)(g * H + j) * H + k0 + 2 * p]);
    const float bhn = bhh[2 * H + j];

    float* cur = hs0;
    float* nxt = hs1;

    // preload gi for t=0 (per-lane j; group-broadcast addresses)
    float gr0 = __ldg(&gi[j]), gr1 = __ldg(&gi[H + j]), gr2 = __ldg(&gi[2 * H + j]);

    for (int t = 0; t < NN; t++) {
        unsigned long long acc[3] = {0ull, 0ull, 0ull};
        const float* hb = cur + pb;
#pragma unroll
        for (int p = 0; p < KP; p++) {
            unsigned long long hp = *reinterpret_cast<const unsigned long long*>(hb + 2 * p);
#pragma unroll
            for (int g = 0; g < 3; g++) acc[g] = fma2(wp[g][p], hp, acc[g]);
        }
        float s[3];
#pragma unroll
        for (int g = 0; g < 3; g++)
            s[g] = __uint_as_float((unsigned)acc[g]) + __uint_as_float((unsigned)(acc[g] >> 32));
#pragma unroll
        for (int off = LPJ / 2; off > 0; off >>= 1)
#pragma unroll
            for (int g = 0; g < 3; g++) s[g] += __shfl_xor_sync(0xffffffffu, s[g], off);

        // gates on every lane (group-redundant; enables one-instruction publish)
        float r = sigf(gr0 + s[0]);
        float z = sigf(gr1 + s[1]);
        float n = tanhfast(gr2 + r * (s[2] + bhn));
        float hn = (1.f - z) * n + z * cur[padi(j)];

        const int par = t & 1;
        if (linj < NC) {
            unsigned long long x =
                ((unsigned long long)(unsigned)(t + 1) << 32) |
                (unsigned long long)__float_as_uint(hn);
            uint32_t la = pairs_addr + (uint32_t)((par * H + j) * 8);
            st_pair_cluster(la, base_rank + linj, x);
        }
        if (linj == 0) Hbuf[(size_t)t * H + j] = hn;

        // prefetch gi for t+1 (overlaps the poll)
        {
            int tn = (t + 1 < NN) ? t + 1 : t;
            const float* gin = gi + (size_t)tn * 3 * H;
            gr0 = __ldg(&gin[j]); gr1 = __ldg(&gin[H + j]); gr2 = __ldg(&gin[2 * H + j]);
        }
        // everyone (incl. own slice) polls the LOCAL ring; confirming load IS the data
        if (tid < H) {
            uint32_t la = pairs_addr + (uint32_t)((par * H + tid) * 8);
            unsigned long long v;
            do { v = ld_pair_sh(la); } while ((unsigned)(v >> 32) != (unsigned)(t + 1));
            nxt[padi(tid)] = __uint_as_float((unsigned)v);
        }
        __syncthreads();   // single bar: nxt complete before next matvec
        float* tmp = cur; cur = nxt; nxt = tmp;
    }
}

// ---------------- router recurrence (r/z biases folded into gi) ----------------
__device__ void router_recur(int b, const float* __restrict__ Whh, const float* __restrict__ bhh,
                             float* cur, float* nxt)
{
    const int tid = threadIdx.x, w = tid >> 5, lane = tid & 31;
    const int j0 = w * 16;
    __syncthreads();

    for (int t = 0; t < TT; t++) {
        const int n = t * BB + b;
        const float* git = g_gi_r + (size_t)n * 768;
        float4 h1 = *reinterpret_cast<const float4*>(cur + lane * 4);
        float4 h2 = *reinterpret_cast<const float4*>(cur + 128 + lane * 4);
#pragma unroll 2
        for (int jj = 0; jj < 16; jj++) {
            int j = j0 + jj;
            const float4* r0 = reinterpret_cast<const float4*>(Whh + (size_t)j * HRR);
            const float4* r1 = reinterpret_cast<const float4*>(Whh + (size_t)(j + 256) * HRR);
            const float4* r2 = reinterpret_cast<const float4*>(Whh + (size_t)(j + 512) * HRR);
            float4 a = __ldg(r0 + lane), c = __ldg(r0 + 32 + lane);
            float s0 = a.x * h1.x + a.y * h1.y + a.z * h1.z + a.w * h1.w
                     + c.x * h2.x + c.y * h2.y + c.z * h2.z + c.w * h2.w;
            a = __ldg(r1 + lane); c = __ldg(r1 + 32 + lane);
            float s1 = a.x * h1.x + a.y * h1.y + a.z * h1.z + a.w * h1.w
                     + c.x * h2.x + c.y * h2.y + c.z * h2.z + c.w * h2.w;
            a = __ldg(r2 + lane); c = __ldg(r2 + 32 + lane);
            float s2 = a.x * h1.x + a.y * h1.y + a.z * h1.z + a.w * h1.w
                     + c.x * h2.x + c.y * h2.y + c.z * h2.z + c.w * h2.w;
#pragma unroll
            for (int off = 16; off > 0; off >>= 1) {
                s0 += __shfl_xor_sync(0xffffffffu, s0, off);
                s1 += __shfl_xor_sync(0xffffffffu, s1, off);
                s2 += __shfl_xor_sync(0xffffffffu, s2, off);
            }
            if (lane == 0) {
                float r = sigf(__ldg(&git[j]) + s0);
                float z = sigf(__ldg(&git[256 + j]) + s1);
                float nn2 = tanhfast(__ldg(&git[512 + j]) + r * (s2 + __ldg(&bhh[512 + j])));
                float hn = (1.f - z) * nn2 + z * cur[j];
                nxt[j] = hn;
                g_Hr[(size_t)n * HRR + j] = hn;
            }
        }
        __syncthreads();
        float* tmp = cur; cur = nxt; nxt = tmp;
    }
}

// ---------------- fused recurrence kernel: 3 clusters of 16 CTAs ----------------
__global__ __launch_bounds__(512) void k_recur(
    const float* r_whh, const float* r_bhh,
    const float* e1_whh, const float* e1_bhh,
    const float* e2_whh, const float* e2_bhh,
    const float* e3_whh, const float* e3_bhh)
{
    __shared__ unsigned long long pairs[1024];   // [parity][H] value+tag rings
    __shared__ float hsm[1152];                  // two padded h buffers (<=544 each)
    const int tid = threadIdx.x;
    for (int i = tid; i < 1024; i += 512) pairs[i] = 0ull;
    for (int i = tid; i < 1152; i += 512) hsm[i] = 0.f;
    __syncthreads();
    uint32_t paddr = (uint32_t)__cvta_generic_to_shared(pairs);
    const int cid = blockIdx.x >> 4;
    const int rank = blockIdx.x & 15;

    if (cid < 2) CLUSTER_SYNC();   // rings zeroed cluster-wide before any peer store

    if (cid == 0) {
        expert_recur<512, 16, 2>(rank, 0, e3_whh, e3_bhh, g_gi_e3, g_H3, paddr, hsm, hsm + 576);
    } else if (cid == 1) {
        if (rank < 8)       expert_recur<256, 8, 2>(rank, 0, e2_whh, e2_bhh, g_gi_e2, g_H2, paddr, hsm, hsm + 576);
        else if (rank < 10) expert_recur<128, 2, 4>(rank - 8, 8, e1_whh, e1_bhh, g_gi_e1, g_H1, paddr, hsm, hsm + 576);
        else                router_recur(rank - 10, r_whh, r_bhh, hsm, hsm + 576);
    } else {
        if (rank < 10)      router_recur(6 + rank, r_whh, r_bhh, hsm, hsm + 576);
    }

    if (cid < 2) CLUSTER_SYNC();   // no CTA exits while peers may still store into it
}

// ---------------- gates: logits -> softmax -> raw, eul, task sums ----------------
__global__ void k_gates(const float* __restrict__ rw, const float* __restrict__ rb,
                        const int* __restrict__ task, float* __restrict__ out_raw)
{
    int warp = (blockIdx.x * blockDim.x + threadIdx.x) >> 5;
    int lane = threadIdx.x & 31;
    if (warp >= NN) return;
    const float* h = g_Hr + (size_t)warp * HRR;
    float hr[8];
#pragma unroll
    for (int i = 0; i < 8; i++) hr[i] = fmaxf(h[i * 32 + lane], 0.f);
    float lg[4];
#pragma unroll
    for (int e = 0; e < 4; e++) {
        float s = 0.f;
#pragma unroll
        for (int i = 0; i < 8; i++) s += __ldg(&rw[e * HRR + i * 32 + lane]) * hr[i];
#pragma unroll
        for (int off = 16; off > 0; off >>= 1) s += __shfl_xor_sync(0xffffffffu, s, off);
        lg[e] = s;
    }
    if (lane == 0) {
#pragma unroll
        for (int e = 0; e < 4; e++) lg[e] += __ldg(&rb[e]);
        float mx = fmaxf(fmaxf(lg[0], lg[1]), fmaxf(lg[2], lg[3]));
        float ex[4], se = 0.f;
#pragma unroll
        for (int e = 0; e < 4; e++) { ex[e] = __expf(lg[e] - mx); se += ex[e]; }
        float inv = 1.f / se;
        float gg[4];
#pragma unroll
        for (int e = 0; e < 4; e++) {
            gg[e] = ex[e] * inv;
            out_raw[warp * 4 + e] = gg[e];
            g_gates[warp * 4 + e] = gg[e];
        }
        float eul = gg[1] * 128.f + gg[2] * 256.f + gg[3] * 512.f;
        int tk = task[warp];
        atomicAdd(&g_tsum[tk], eul);
        atomicAdd(&g_tcnt[tk], 1u);
    }
}

// ---------------- BN stats ----------------
__global__ void k_bn(const float* g1, const float* b1, const float* g2, const float* b2,
                     const float* g3, const float* b3)
{
    int bid = blockIdx.x, tid = threadIdx.x;
    const float* Hb; int H, ei, c;
    if (bid == 0)      { Hb = g_H1; H = 128; ei = 0; c = tid; }
    else if (bid < 3)  { Hb = g_H2; H = 256; ei = 1; c = (bid - 1) * 128 + tid; }
    else               { Hb = g_H3; H = 512; ei = 2; c = (bid - 3) * 128 + tid; }
    float s = 0.f, s2 = 0.f;
#pragma unroll 8
    for (int n = 0; n < NN; n++) {
        float v = __ldg(&Hb[(size_t)n * H + c]);
        s += v; s2 += v * v;
    }
    float mu = s * (1.f / NN);
    float var = s2 * (1.f / NN) - mu * mu;
    const float* gg = (ei == 0) ? g1 : (ei == 1) ? g2 : g3;
    const float* bb = (ei == 0) ? b1 : (ei == 1) ? b2 : b3;
    float A = gg[c] * rsqrtf(var + BN_EPS);
    g_bnA[ei][c] = A;
    g_bnB[ei][c] = bb[c] - mu * A;
}

// ---------------- epilogue ----------------
__global__ __launch_bounds__(256) void k_epi(
    const float* __restrict__ ow, const float* __restrict__ ob,
    const float* __restrict__ x, float* __restrict__ out, int ei, int H)
{
    const float* Hb = (ei == 1) ? g_H1 : (ei == 2) ? g_H2 : g_H3;
    const float* bA = g_bnA[ei - 1];
    const float* bBv = g_bnB[ei - 1];
    __shared__ float As[64][17];
    __shared__ float Ws[64][17];
    const int tid = threadIdx.x;
    const int tx = tid & 15, ty = tid >> 4;
    const int m0 = blockIdx.y * 64, n0 = blockIdx.x * 64;
    const int lr = tid >> 2, lc = (tid & 3) * 4;

    float acc[4][4];
#pragma unroll
    for (int i = 0; i < 4; i++)
#pragma unroll
        for (int j = 0; j < 4; j++) acc[i][j] = 0.f;

    for (int kb = 0; kb < H; kb += 16) {
        float4 av = *reinterpret_cast<const float4*>(&Hb[(size_t)(m0 + lr) * H + kb + lc]);
        float4 wv = *reinterpret_cast<const float4*>(&ow[(size_t)(n0 + lr) * H + kb + lc]);
        As[lr][lc + 0] = fmaxf(av.x * __ldg(&bA[kb + lc + 0]) + __ldg(&bBv[kb + lc + 0]), 0.f);
        As[lr][lc + 1] = fmaxf(av.y * __ldg(&bA[kb + lc + 1]) + __ldg(&bBv[kb + lc + 1]), 0.f);
        As[lr][lc + 2] = fmaxf(av.z * __ldg(&bA[kb + lc + 2]) + __ldg(&bBv[kb + lc + 2]), 0.f);
        As[lr][lc + 3] = fmaxf(av.w * __ldg(&bA[kb + lc + 3]) + __ldg(&bBv[kb + lc + 3]), 0.f);
        Ws[lr][lc + 0] = wv.x; Ws[lr][lc + 1] = wv.y; Ws[lr][lc + 2] = wv.z; Ws[lr][lc + 3] = wv.w;
        __syncthreads();
#pragma unroll
        for (int k = 0; k < 16; k++) {
            float a[4], b[4];
#pragma unroll
            for (int i = 0; i < 4; i++) a[i] = As[ty * 4 + i][k];
#pragma unroll
            for (int j = 0; j < 4; j++) b[j] = Ws[tx * 4 + j][k];
#pragma unroll
            for (int i = 0; i < 4; i++)
#pragma unroll
                for (int j = 0; j < 4; j++) acc[i][j] += a[i] * b[j];
        }
        __syncthreads();
    }
#pragma unroll
    for (int i = 0; i < 4; i++) {
        int m = m0 + ty * 4 + i;
        float gate = g_gates[m * 4 + ei];
        float g0 = g_gates[m * 4];
#pragma unroll
        for (int j = 0; j < 4; j++) {
            int n = n0 + tx * 4 + j;
            float v = (acc[i][j] + __ldg(&ob[n])) * gate;
            if (ei == 1) v += g0 * __ldg(&x[(size_t)m * DD + n]);
            else         v += out[(size_t)m * DD + n];
            out[(size_t)m * DD + n] = v;
        }
    }
}

// ---------------- task losses ----------------
__global__ void k_tl(float* o) {
    int i = threadIdx.x;
    if (i < 4) o[i] = g_tsum[i] / (float)g_tcnt[i];
}

// ---------------- launch ----------------
extern "C" void kernel_launch(void* const* d_in, const int* in_sizes, int n_in,
                              void* d_out, int out_size)
{
    const float* x      = (const float*)d_in[0];
    const int*   task   = (const int*)d_in[1];
    const float* r_wih  = (const float*)d_in[2];
    const float* r_whh  = (const float*)d_in[3];
    const float* r_bih  = (const float*)d_in[4];
    const float* r_bhh  = (const float*)d_in[5];
    const float* r_ow   = (const float*)d_in[6];
    const float* r_ob   = (const float*)d_in[7];
    const float* e1_wih = (const float*)d_in[8];
    const float* e1_whh = (const float*)d_in[9];
    const float* e1_bih = (const float*)d_in[10];
    const float* e1_bhh = (const float*)d_in[11];
    const float* e1_bng = (const float*)d_in[12];
    const float* e1_bnb = (const float*)d_in[13];
    const float* e1_ow  = (const float*)d_in[14];
    const float* e1_ob  = (const float*)d_in[15];
    const float* e2_wih = (const float*)d_in[16];
    const float* e2_whh = (const float*)d_in[17];
    const float* e2_bih = (const float*)d_in[18];
    const float* e2_bhh = (const float*)d_in[19];
    const float* e2_bng = (const float*)d_in[20];
    const float* e2_bnb = (const float*)d_in[21];
    const float* e2_ow  = (const float*)d_in[22];
    const float* e2_ob  = (const float*)d_in[23];
    const float* e3_wih = (const float*)d_in[24];
    const float* e3_whh = (const float*)d_in[25];
    const float* e3_bih = (const float*)d_in[26];
    const float* e3_bhh = (const float*)d_in[27];
    const float* e3_bng = (const float*)d_in[28];
    const float* e3_bnb = (const float*)d_in[29];
    const float* e3_ow  = (const float*)d_in[30];
    const float* e3_ob  = (const float*)d_in[31];

    float* out = (float*)d_out;
    float* raw = out + (size_t)NN * DD;
    float* tl  = raw + (size_t)NN * 4;

    k_zero<<<1, 32>>>();
    k_gemm_all<<<3456, 256>>>(x,
        r_wih, r_bih, r_bhh,
        e1_wih, e1_bih, e1_bhh,
        e2_wih, e2_bih, e2_bhh,
        e3_wih, e3_bih, e3_bhh);

    cudaFuncSetAttribute(k_recur, cudaFuncAttributeNonPortableClusterSizeAllowed, 1);
    cudaLaunchConfig_t cfg = {};
    cfg.gridDim = dim3(48, 1, 1);
    cfg.blockDim = dim3(512, 1, 1);
    cfg.dynamicSmemBytes = 0;
    cfg.stream = 0;
    cudaLaunchAttribute lattr[1];
    lattr[0].id = cudaLaunchAttributeClusterDimension;
    lattr[0].val.clusterDim.x = 16;
    lattr[0].val.clusterDim.y = 1;
    lattr[0].val.clusterDim.z = 1;
    cfg.attrs = lattr;
    cfg.numAttrs = 1;
    cudaLaunchKernelEx(&cfg, k_recur,
                       r_whh, r_bhh, e1_whh, e1_bhh, e2_whh, e2_bhh, e3_whh, e3_bhh);

    k_gates<<<512, 256>>>(r_ow, r_ob, task, raw);
    k_bn<<<7, 128>>>(e1_bng, e1_bnb, e2_bng, e2_bnb, e3_bng, e3_bnb);
    k_epi<<<dim3(8, 64), 256>>>(e1_ow, e1_ob, x, out, 1, 128);
    k_epi<<<dim3(8, 64), 256>>>(e2_ow, e2_ob, x, out, 2, 256);
    k_epi<<<dim3(8, 64), 256>>>(e3_ow, e3_ob, x, out, 3, 512);
    k_tl<<<1, 32>>>(tl);
}

// round 13
// speedup vs baseline: 2.7547x; 1.1739x over previous
#include <cuda_runtime.h>
#include <stdint.h>
#include <math.h>

#define TT 256
#define BB 16
#define DD 512
#define NN 4096
#define HRR 256
#define BN_EPS 1e-5f

// ---------------- device scratch ----------------
__device__ float g_gi_r [NN * 768];
__device__ float g_gi_e1[NN * 384];
__device__ float g_gi_e2[NN * 768];
__device__ float g_gi_e3[NN * 1536];
__device__ float g_Hr[NN * HRR];
__device__ float g_H1[NN * 128];
__device__ float g_H2[NN * 256];
__device__ float g_H3[NN * 512];
__device__ float g_gates[NN * 4];
__device__ unsigned g_girdy[4 * 64];      // per-(expert, token-block) readiness
__device__ float g_bnPS [8][896];
__device__ float g_bnPS2[8][896];
__device__ float g_bnA[3][512];
__device__ float g_bnB[3][512];
__device__ float g_tsum[4];
__device__ unsigned g_tcnt[4];

__device__ __forceinline__ float sigf(float x) { return 1.f / (1.f + __expf(-x)); }
__device__ __forceinline__ float tanhfast(float x) {
    float xc = fminf(fmaxf(x, -9.f), 9.f);
    float e = __expf(2.f * xc);
    return __fdividef(e - 1.f, e + 1.f);
}
__device__ __forceinline__ unsigned long long fma2(unsigned long long a, unsigned long long b,
                                                   unsigned long long c) {
    unsigned long long d;
    asm("fma.rn.f32x2 %0, %1, %2, %3;" : "=l"(d) : "l"(a), "l"(b), "l"(c));
    return d;
}
__device__ __forceinline__ int padi(int k) { return k + ((k >> 5) << 1); }  // bank-pad

__device__ __forceinline__ void st_pair_cluster(uint32_t laddr, int rank, unsigned long long x) {
    uint32_t ra;
    asm volatile("mapa.shared::cluster.u32 %0, %1, %2;" : "=r"(ra) : "r"(laddr), "r"(rank));
    asm volatile("st.shared::cluster.b64 [%0], %1;" :: "r"(ra), "l"(x) : "memory");
}
__device__ __forceinline__ unsigned long long ld_pair_sh(uint32_t laddr) {
    unsigned long long v;
    asm volatile("ld.volatile.shared.b64 %0, [%1];" : "=l"(v) : "r"(laddr));
    return v;
}
__device__ __forceinline__ unsigned ld_acq(const unsigned* p) {
    unsigned v;
    asm volatile("ld.acquire.gpu.global.u32 %0, [%1];" : "=r"(v) : "l"(p) : "memory");
    return v;
}
__device__ __forceinline__ void red_rel(unsigned* p) {
    asm volatile("red.release.gpu.global.add.u32 [%0], 1;" :: "l"(p) : "memory");
}
#define CLUSTER_SYNC() do { \
    asm volatile("barrier.cluster.arrive.aligned;" ::: "memory"); \
    asm volatile("barrier.cluster.wait.aligned;" ::: "memory"); } while (0)

// ---------------- zero ----------------
__global__ void k_zero() {
    int i = threadIdx.x;
    if (i < 256) g_girdy[i] = 0u;
    if (i < 4) { g_tsum[i] = 0.f; g_tcnt[i] = 0u; }
}

// ---------------- expert recurrence (as round 11 + gi readiness gating) ----------------
template <int H, int NC, int JW>
__device__ void expert_recur(int cta, int base_rank,
                             const float* __restrict__ Whh, const float* __restrict__ bhh,
                             const float* gi, float* __restrict__ Hbuf,
                             const unsigned* rdy, int nbk,
                             uint32_t pairs_addr, float* hs0, float* hs1)
{
    constexpr int JPC = H / NC;
    constexpr int LPJ = 32 / JW;
    constexpr int KB  = H / LPJ;
    constexpr int KP  = KB / 2;
    const int tid = threadIdx.x, w = tid >> 5, lane = tid & 31;
    const int jj   = lane / LPJ;
    const int linj = lane % LPJ;
    const int j    = cta * JPC + w * JW + jj;
    const int k0   = linj * KB;
    const int pb   = padi(k0);

    unsigned long long wp[3][KP];
#pragma unroll
    for (int g = 0; g < 3; g++)
#pragma unroll
        for (int p = 0; p < KP; p++)
            wp[g][p] = *reinterpret_cast<const unsigned long long*>(
                &Whh[(size_t)(g * H + j) * H + k0 + 2 * p]);
    const float bhn = bhh[2 * H + j];

    float* cur = hs0;
    float* nxt = hs1;

    // wait for gi token-block 0, then preload (plain loads: gi written concurrently)
    while (ld_acq(&rdy[0]) < (unsigned)nbk) {}
    int rdyw = 1;
    float gr0 = gi[j], gr1 = gi[H + j], gr2 = gi[2 * H + j];

    for (int t = 0; t < NN; t++) {
        unsigned long long acc[3] = {0ull, 0ull, 0ull};
        const float* hb = cur + pb;
#pragma unroll
        for (int p = 0; p < KP; p++) {
            unsigned long long hp = *reinterpret_cast<const unsigned long long*>(hb + 2 * p);
#pragma unroll
            for (int g = 0; g < 3; g++) acc[g] = fma2(wp[g][p], hp, acc[g]);
        }
        float s[3];
#pragma unroll
        for (int g = 0; g < 3; g++)
            s[g] = __uint_as_float((unsigned)acc[g]) + __uint_as_float((unsigned)(acc[g] >> 32));
#pragma unroll
        for (int off = LPJ / 2; off > 0; off >>= 1)
#pragma unroll
            for (int g = 0; g < 3; g++) s[g] += __shfl_xor_sync(0xffffffffu, s[g], off);

        float r = sigf(gr0 + s[0]);
        float z = sigf(gr1 + s[1]);
        float n = tanhfast(gr2 + r * (s[2] + bhn));
        float hn = (1.f - z) * n + z * cur[padi(j)];

        const int par = t & 1;
        if (linj < NC) {
            unsigned long long x =
                ((unsigned long long)(unsigned)(t + 1) << 32) |
                (unsigned long long)__float_as_uint(hn);
            uint32_t la = pairs_addr + (uint32_t)((par * H + j) * 8);
            st_pair_cluster(la, base_rank + linj, x);
        }
        if (linj == 0) Hbuf[(size_t)t * H + j] = hn;

        // gated gi prefetch for t+1
        {
            int tn = (t + 1 < NN) ? t + 1 : t;
            int blk = tn >> 6;
            if (blk >= rdyw) {
                while (ld_acq(&rdy[blk]) < (unsigned)nbk) {}
                rdyw = blk + 1;
            }
            const float* gin = gi + (size_t)tn * 3 * H;
            gr0 = gin[j]; gr1 = gin[H + j]; gr2 = gin[2 * H + j];
        }
        if (tid < H) {
            uint32_t la = pairs_addr + (uint32_t)((par * H + tid) * 8);
            unsigned long long v;
            do { v = ld_pair_sh(la); } while ((unsigned)(v >> 32) != (unsigned)(t + 1));
            nxt[padi(tid)] = __uint_as_float((unsigned)v);
        }
        __syncthreads();
        float* tmp = cur; cur = nxt; nxt = tmp;
    }
}

// ---------------- router recurrence (+ readiness gating) ----------------
__device__ void router_recur(int b, const float* __restrict__ Whh, const float* __restrict__ bhh,
                             const unsigned* rdy, int nbk, float* cur, float* nxt)
{
    const int tid = threadIdx.x, w = tid >> 5, lane = tid & 31;
    const int j0 = w * 16;
    __syncthreads();
    int rdyw = 0;

    for (int t = 0; t < TT; t++) {
        const int n = t * BB + b;
        int blk = n >> 6;
        if (blk >= rdyw) {
            while (ld_acq(&rdy[blk]) < (unsigned)nbk) {}
            rdyw = blk + 1;
        }
        const float* git = g_gi_r + (size_t)n * 768;
        float4 h1 = *reinterpret_cast<const float4*>(cur + lane * 4);
        float4 h2 = *reinterpret_cast<const float4*>(cur + 128 + lane * 4);
#pragma unroll 2
        for (int jj = 0; jj < 16; jj++) {
            int j = j0 + jj;
            const float4* r0 = reinterpret_cast<const float4*>(Whh + (size_t)j * HRR);
            const float4* r1 = reinterpret_cast<const float4*>(Whh + (size_t)(j + 256) * HRR);
            const float4* r2 = reinterpret_cast<const float4*>(Whh + (size_t)(j + 512) * HRR);
            float4 a = __ldg(r0 + lane), c = __ldg(r0 + 32 + lane);
            float s0 = a.x * h1.x + a.y * h1.y + a.z * h1.z + a.w * h1.w
                     + c.x * h2.x + c.y * h2.y + c.z * h2.z + c.w * h2.w;
            a = __ldg(r1 + lane); c = __ldg(r1 + 32 + lane);
            float s1 = a.x * h1.x + a.y * h1.y + a.z * h1.z + a.w * h1.w
                     + c.x * h2.x + c.y * h2.y + c.z * h2.z + c.w * h2.w;
            a = __ldg(r2 + lane); c = __ldg(r2 + 32 + lane);
            float s2 = a.x * h1.x + a.y * h1.y + a.z * h1.z + a.w * h1.w
                     + c.x * h2.x + c.y * h2.y + c.z * h2.z + c.w * h2.w;
#pragma unroll
            for (int off = 16; off > 0; off >>= 1) {
                s0 += __shfl_xor_sync(0xffffffffu, s0, off);
                s1 += __shfl_xor_sync(0xffffffffu, s1, off);
                s2 += __shfl_xor_sync(0xffffffffu, s2, off);
            }
            if (lane == 0) {
                float r = sigf(git[j] + s0);
                float z = sigf(git[256 + j] + s1);
                float nn2 = tanhfast(git[512 + j] + r * (s2 + __ldg(&bhh[512 + j])));
                float hn = (1.f - z) * nn2 + z * cur[j];
                nxt[j] = hn;
                g_Hr[(size_t)n * HRR + j] = hn;
            }
        }
        __syncthreads();
        float* tmp = cur; cur = nxt; nxt = tmp;
    }
}

// ---------------- fused fat kernel: 48 recurrence CTAs + 3456 GEMM CTAs ----------------
// bid<48: 3 clusters of 16 (e3 | e2+e1+6 routers | 10 routers)
// bid>=48: gi GEMM, m-block-major ordering (all experts' token-block mb first),
//          releases g_girdy[e*64+mb] when its (mb, nblk) tile is done.
__global__ __launch_bounds__(512) void k_fat(
    const float* __restrict__ x,
    const float* __restrict__ r_wih,  const float* __restrict__ r_bih,
    const float* __restrict__ e1_wih, const float* __restrict__ e1_bih,
    const float* __restrict__ e2_wih, const float* __restrict__ e2_bih,
    const float* __restrict__ e3_wih, const float* __restrict__ e3_bih,
    const float* __restrict__ r_whh,  const float* __restrict__ r_bhh,
    const float* __restrict__ e1_whh, const float* __restrict__ e1_bhh,
    const float* __restrict__ e2_whh, const float* __restrict__ e2_bhh,
    const float* __restrict__ e3_whh, const float* __restrict__ e3_bhh)
{
    __shared__ unsigned long long pairs[1024];
    __shared__ float hsm[1152];
    __shared__ float As[64][17];
    __shared__ float Ws[64][17];
    const int bid = blockIdx.x;
    const int tid = threadIdx.x;

    if (bid >= 48) {
        // ---------------- GEMM path (512 threads, 64x64 tile) ----------------
        int gid = bid - 48;
        int mb = gid / 54;
        int r  = gid % 54;
        const float* W; const float* bias; const float* bhh; float* C;
        int Nn, nblk, e, twoH;
        if (r < 12)      { e = 0; nblk = r;      W = r_wih;  bias = r_bih;  bhh = r_bhh;  C = g_gi_r;  Nn = 768;  twoH = 512; }
        else if (r < 18) { e = 1; nblk = r - 12; W = e1_wih; bias = e1_bih; bhh = e1_bhh; C = g_gi_e1; Nn = 384;  twoH = 256; }
        else if (r < 30) { e = 2; nblk = r - 18; W = e2_wih; bias = e2_bih; bhh = e2_bhh; C = g_gi_e2; Nn = 768;  twoH = 512; }
        else             { e = 3; nblk = r - 30; W = e3_wih; bias = e3_bih; bhh = e3_bhh; C = g_gi_e3; Nn = 1536; twoH = 1024; }
        const int m0 = mb * 64, n0 = nblk * 64;
        const int tx = tid & 15, ty = tid >> 4;       // 4 cols x 2 rows per thread
        const int lr = tid >> 3, lc = (tid & 7) * 2;  // loads

        float acc[2][4];
#pragma unroll
        for (int i = 0; i < 2; i++)
#pragma unroll
            for (int jq = 0; jq < 4; jq++) acc[i][jq] = 0.f;

        for (int kb = 0; kb < 512; kb += 16) {
            float2 av = *reinterpret_cast<const float2*>(&x[(size_t)(m0 + lr) * 512 + kb + lc]);
            float2 wv = *reinterpret_cast<const float2*>(&W[(size_t)(n0 + lr) * 512 + kb + lc]);
            As[lr][lc] = av.x; As[lr][lc + 1] = av.y;
            Ws[lr][lc] = wv.x; Ws[lr][lc + 1] = wv.y;
            __syncthreads();
#pragma unroll
            for (int k = 0; k < 16; k++) {
                float a0 = As[ty * 2][k], a1 = As[ty * 2 + 1][k];
                float b0 = Ws[tx * 4][k], b1 = Ws[tx * 4 + 1][k];
                float b2 = Ws[tx * 4 + 2][k], b3 = Ws[tx * 4 + 3][k];
                acc[0][0] += a0 * b0; acc[0][1] += a0 * b1; acc[0][2] += a0 * b2; acc[0][3] += a0 * b3;
                acc[1][0] += a1 * b0; acc[1][1] += a1 * b1; acc[1][2] += a1 * b2; acc[1][3] += a1 * b3;
            }
            __syncthreads();
        }
#pragma unroll
        for (int i = 0; i < 2; i++)
#pragma unroll
            for (int jq = 0; jq < 4; jq++) {
                int nidx = n0 + tx * 4 + jq;
                float b = __ldg(&bias[nidx]);
                if (nidx < twoH) b += __ldg(&bhh[nidx]);   // fold r,z hidden biases
                C[(size_t)(m0 + ty * 2 + i) * Nn + nidx] = acc[i][jq] + b;
            }
        __syncthreads();
        if (tid == 0) red_rel(&g_girdy[e * 64 + mb]);
        return;
    }

    // ---------------- recurrence path ----------------
    for (int i = tid; i < 1024; i += 512) pairs[i] = 0ull;
    for (int i = tid; i < 1152; i += 512) hsm[i] = 0.f;
    __syncthreads();
    uint32_t paddr = (uint32_t)__cvta_generic_to_shared(pairs);
    const int cid = bid >> 4;
    const int rank = bid & 15;

    if (cid < 2) CLUSTER_SYNC();

    if (cid == 0) {
        expert_recur<512, 16, 2>(rank, 0, e3_whh, e3_bhh, g_gi_e3, g_H3,
                                 g_girdy + 3 * 64, 24, paddr, hsm, hsm + 576);
    } else if (cid == 1) {
        if (rank < 8)       expert_recur<256, 8, 2>(rank, 0, e2_whh, e2_bhh, g_gi_e2, g_H2,
                                                    g_girdy + 2 * 64, 12, paddr, hsm, hsm + 576);
        else if (rank < 10) expert_recur<128, 2, 4>(rank - 8, 8, e1_whh, e1_bhh, g_gi_e1, g_H1,
                                                    g_girdy + 1 * 64, 6, paddr, hsm, hsm + 576);
        else                router_recur(rank - 10, r_whh, r_bhh, g_girdy, 12, hsm, hsm + 576);
    } else {
        if (rank < 10)      router_recur(6 + rank, r_whh, r_bhh, g_girdy, 12, hsm, hsm + 576);
    }

    if (cid < 2) CLUSTER_SYNC();
}

// ---------------- gates ----------------
__global__ void k_gates(const float* __restrict__ rw, const float* __restrict__ rb,
                        const int* __restrict__ task, float* __restrict__ out_raw)
{
    int warp = (blockIdx.x * blockDim.x + threadIdx.x) >> 5;
    int lane = threadIdx.x & 31;
    if (warp >= NN) return;
    const float* h = g_Hr + (size_t)warp * HRR;
    float hr[8];
#pragma unroll
    for (int i = 0; i < 8; i++) hr[i] = fmaxf(h[i * 32 + lane], 0.f);
    float lg[4];
#pragma unroll
    for (int e = 0; e < 4; e++) {
        float s = 0.f;
#pragma unroll
        for (int i = 0; i < 8; i++) s += __ldg(&rw[e * HRR + i * 32 + lane]) * hr[i];
#pragma unroll
        for (int off = 16; off > 0; off >>= 1) s += __shfl_xor_sync(0xffffffffu, s, off);
        lg[e] = s;
    }
    if (lane == 0) {
#pragma unroll
        for (int e = 0; e < 4; e++) lg[e] += __ldg(&rb[e]);
        float mx = fmaxf(fmaxf(lg[0], lg[1]), fmaxf(lg[2], lg[3]));
        float ex[4], se = 0.f;
#pragma unroll
        for (int e = 0; e < 4; e++) { ex[e] = __expf(lg[e] - mx); se += ex[e]; }
        float inv = 1.f / se;
        float gg[4];
#pragma unroll
        for (int e = 0; e < 4; e++) {
            gg[e] = ex[e] * inv;
            out_raw[warp * 4 + e] = gg[e];
            g_gates[warp * 4 + e] = gg[e];
        }
        float eul = gg[1] * 128.f + gg[2] * 256.f + gg[3] * 512.f;
        int tk = task[warp];
        atomicAdd(&g_tsum[tk], eul);
        atomicAdd(&g_tcnt[tk], 1u);
    }
}

// ---------------- BN stats: deterministic two-pass (no atomics) ----------------
__global__ void k_bnp() {
    int bx = blockIdx.x, rc = blockIdx.y, tid = threadIdx.x;
    const float* Hb; int H, c;
    if (bx == 0)      { Hb = g_H1; H = 128; c = tid; }
    else if (bx < 3)  { Hb = g_H2; H = 256; c = (bx - 1) * 128 + tid; }
    else              { Hb = g_H3; H = 512; c = (bx - 3) * 128 + tid; }
    float s = 0.f, s2 = 0.f;
    int n0 = rc * (NN / 8);
#pragma unroll 8
    for (int n = n0; n < n0 + NN / 8; n++) {
        float v = __ldg(&Hb[(size_t)n * H + c]);
        s += v; s2 += v * v;
    }
    g_bnPS [rc][bx * 128 + tid] = s;
    g_bnPS2[rc][bx * 128 + tid] = s2;
}

__global__ void k_bnf(const float* g1, const float* b1, const float* g2, const float* b2,
                      const float* g3, const float* b3)
{
    int bx = blockIdx.x, tid = threadIdx.x;
    int ei, c;
    if (bx == 0)      { ei = 0; c = tid; }
    else if (bx < 3)  { ei = 1; c = (bx - 1) * 128 + tid; }
    else              { ei = 2; c = (bx - 3) * 128 + tid; }
    float s = 0.f, s2 = 0.f;
#pragma unroll
    for (int rc = 0; rc < 8; rc++) { s += g_bnPS[rc][bx * 128 + tid]; s2 += g_bnPS2[rc][bx * 128 + tid]; }
    float mu = s * (1.f / NN);
    float var = s2 * (1.f / NN) - mu * mu;
    const float* gg = (ei == 0) ? g1 : (ei == 1) ? g2 : g3;
    const float* bb = (ei == 0) ? b1 : (ei == 1) ? b2 : b3;
    float A = gg[c] * rsqrtf(var + BN_EPS);
    g_bnA[ei][c] = A;
    g_bnB[ei][c] = bb[c] - mu * A;
}

// ---------------- epilogue ----------------
__global__ __launch_bounds__(256) void k_epi(
    const float* __restrict__ ow, const float* __restrict__ ob,
    const float* __restrict__ x, float* __restrict__ out, int ei, int H)
{
    const float* Hb = (ei == 1) ? g_H1 : (ei == 2) ? g_H2 : g_H3;
    const float* bA = g_bnA[ei - 1];
    const float* bBv = g_bnB[ei - 1];
    __shared__ float As[64][17];
    __shared__ float Ws[64][17];
    const int tid = threadIdx.x;
    const int tx = tid & 15, ty = tid >> 4;
    const int m0 = blockIdx.y * 64, n0 = blockIdx.x * 64;
    const int lr = tid >> 2, lc = (tid & 3) * 4;

    float acc[4][4];
#pragma unroll
    for (int i = 0; i < 4; i++)
#pragma unroll
        for (int j = 0; j < 4; j++) acc[i][j] = 0.f;

    for (int kb = 0; kb < H; kb += 16) {
        float4 av = *reinterpret_cast<const float4*>(&Hb[(size_t)(m0 + lr) * H + kb + lc]);
        float4 wv = *reinterpret_cast<const float4*>(&ow[(size_t)(n0 + lr) * H + kb + lc]);
        As[lr][lc + 0] = fmaxf(av.x * __ldg(&bA[kb + lc + 0]) + __ldg(&bBv[kb + lc + 0]), 0.f);
        As[lr][lc + 1] = fmaxf(av.y * __ldg(&bA[kb + lc + 1]) + __ldg(&bBv[kb + lc + 1]), 0.f);
        As[lr][lc + 2] = fmaxf(av.z * __ldg(&bA[kb + lc + 2]) + __ldg(&bBv[kb + lc + 2]), 0.f);
        As[lr][lc + 3] = fmaxf(av.w * __ldg(&bA[kb + lc + 3]) + __ldg(&bBv[kb + lc + 3]), 0.f);
        Ws[lr][lc + 0] = wv.x; Ws[lr][lc + 1] = wv.y; Ws[lr][lc + 2] = wv.z; Ws[lr][lc + 3] = wv.w;
        __syncthreads();
#pragma unroll
        for (int k = 0; k < 16; k++) {
            float a[4], b[4];
#pragma unroll
            for (int i = 0; i < 4; i++) a[i] = As[ty * 4 + i][k];
#pragma unroll
            for (int j = 0; j < 4; j++) b[j] = Ws[tx * 4 + j][k];
#pragma unroll
            for (int i = 0; i < 4; i++)
#pragma unroll
                for (int j = 0; j < 4; j++) acc[i][j] += a[i] * b[j];
        }
        __syncthreads();
    }
#pragma unroll
    for (int i = 0; i < 4; i++) {
        int m = m0 + ty * 4 + i;
        float gate = g_gates[m * 4 + ei];
        float g0 = g_gates[m * 4];
#pragma unroll
        for (int j = 0; j < 4; j++) {
            int n = n0 + tx * 4 + j;
            float v = (acc[i][j] + __ldg(&ob[n])) * gate;
            if (ei == 1) v += g0 * __ldg(&x[(size_t)m * DD + n]);
            else         v += out[(size_t)m * DD + n];
            out[(size_t)m * DD + n] = v;
        }
    }
}

// ---------------- task losses ----------------
__global__ void k_tl(float* o) {
    int i = threadIdx.x;
    if (i < 4) o[i] = g_tsum[i] / (float)g_tcnt[i];
}

// ---------------- launch ----------------
extern "C" void kernel_launch(void* const* d_in, const int* in_sizes, int n_in,
                              void* d_out, int out_size)
{
    const float* x      = (const float*)d_in[0];
    const int*   task   = (const int*)d_in[1];
    const float* r_wih  = (const float*)d_in[2];
    const float* r_whh  = (const float*)d_in[3];
    const float* r_bih  = (const float*)d_in[4];
    const float* r_bhh  = (const float*)d_in[5];
    const float* r_ow   = (const float*)d_in[6];
    const float* r_ob   = (const float*)d_in[7];
    const float* e1_wih = (const float*)d_in[8];
    const float* e1_whh = (const float*)d_in[9];
    const float* e1_bih = (const float*)d_in[10];
    const float* e1_bhh = (const float*)d_in[11];
    const float* e1_bng = (const float*)d_in[12];
    const float* e1_bnb = (const float*)d_in[13];
    const float* e1_ow  = (const float*)d_in[14];
    const float* e1_ob  = (const float*)d_in[15];
    const float* e2_wih = (const float*)d_in[16];
    const float* e2_whh = (const float*)d_in[17];
    const float* e2_bih = (const float*)d_in[18];
    const float* e2_bhh = (const float*)d_in[19];
    const float* e2_bng = (const float*)d_in[20];
    const float* e2_bnb = (const float*)d_in[21];
    const float* e2_ow  = (const float*)d_in[22];
    const float* e2_ob  = (const float*)d_in[23];
    const float* e3_wih = (const float*)d_in[24];
    const float* e3_whh = (const float*)d_in[25];
    const float* e3_bih = (const float*)d_in[26];
    const float* e3_bhh = (const float*)d_in[27];
    const float* e3_bng = (const float*)d_in[28];
    const float* e3_bnb = (const float*)d_in[29];
    const float* e3_ow  = (const float*)d_in[30];
    const float* e3_ob  = (const float*)d_in[31];

    float* out = (float*)d_out;
    float* raw = out + (size_t)NN * DD;
    float* tl  = raw + (size_t)NN * 4;

    k_zero<<<1, 256>>>();

    cudaFuncSetAttribute(k_fat, cudaFuncAttributeNonPortableClusterSizeAllowed, 1);
    cudaLaunchConfig_t cfg = {};
    cfg.gridDim = dim3(3504, 1, 1);   // 48 recurrence + 3456 GEMM
    cfg.blockDim = dim3(512, 1, 1);
    cfg.dynamicSmemBytes = 0;
    cfg.stream = 0;
    cudaLaunchAttribute lattr[1];
    lattr[0].id = cudaLaunchAttributeClusterDimension;
    lattr[0].val.clusterDim.x = 16;
    lattr[0].val.clusterDim.y = 1;
    lattr[0].val.clusterDim.z = 1;
    cfg.attrs = lattr;
    cfg.numAttrs = 1;
    cudaLaunchKernelEx(&cfg, k_fat,
                       x, r_wih, r_bih, e1_wih, e1_bih, e2_wih, e2_bih, e3_wih, e3_bih,
                       r_whh, r_bhh, e1_whh, e1_bhh, e2_whh, e2_bhh, e3_whh, e3_bhh);

    k_gates<<<512, 256>>>(r_ow, r_ob, task, raw);
    k_bnp<<<dim3(7, 8), 128>>>();
    k_bnf<<<7, 128>>>(e1_bng, e1_bnb, e2_bng, e2_bnb, e3_bng, e3_bnb);
    k_epi<<<dim3(8, 64), 256>>>(e1_ow, e1_ob, x, out, 1, 128);
    k_epi<<<dim3(8, 64), 256>>>(e2_ow, e2_ob, x, out, 2, 256);
    k_epi<<<dim3(8, 64), 256>>>(e3_ow, e3_ob, x, out, 3, 512);
    k_tl<<<1, 32>>>(tl);
}